// round 2
// baseline (speedup 1.0000x reference)
#include <cuda_runtime.h>
#include <cstdint>

#define LSEQ 1024
#define DM   1024
#define BATCH 8
#define NH   16
#define DK   64
#define BHN  (BATCH*NH)     // 128
#define NREL 33
#define DI   4096
#define ROWS (BATCH*LSEQ)   // 8192

// ---------------- scratch (static device arrays; no allocation) ----------------
__device__ float g_Q[ROWS*DM];
__device__ float g_K[ROWS*DM];
__device__ float g_V[ROWS*DM];
__device__ float g_S[(size_t)BHN*LSEQ*LSEQ];      // 512 MB scores/probs
__device__ float g_Srel[(size_t)BHN*LSEQ*NREL];   // Qh . rel_k[r]
__device__ float g_Wb[(size_t)BHN*LSEQ*NREL];     // bucket-summed attention
__device__ float g_attn[ROWS*DM];
__device__ float g_tmp[ROWS*DM];
__device__ float g_ln1[ROWS*DM];
__device__ float g_h1[(size_t)ROWS*DI];
__device__ float g_t2[ROWS*DM];

// ---------------- reductions ----------------
__device__ __forceinline__ float block_sum(float v, float* red) {
    int lane = threadIdx.x & 31, w = threadIdx.x >> 5;
#pragma unroll
    for (int o = 16; o; o >>= 1) v += __shfl_xor_sync(0xffffffffu, v, o);
    if (lane == 0) red[w] = v;
    __syncthreads();
    if (w == 0) {
        float t = (lane < 8) ? red[lane] : 0.f;
#pragma unroll
        for (int o = 4; o; o >>= 1) t += __shfl_xor_sync(0xffffffffu, t, o);
        if (lane == 0) red[0] = t;
    }
    __syncthreads();
    float r = red[0];
    __syncthreads();
    return r;
}

__device__ __forceinline__ float block_max(float v, float* red) {
    int lane = threadIdx.x & 31, w = threadIdx.x >> 5;
#pragma unroll
    for (int o = 16; o; o >>= 1) v = fmaxf(v, __shfl_xor_sync(0xffffffffu, v, o));
    if (lane == 0) red[w] = v;
    __syncthreads();
    if (w == 0) {
        float t = (lane < 8) ? red[lane] : -3.4e38f;
#pragma unroll
        for (int o = 4; o; o >>= 1) t = fmaxf(t, __shfl_xor_sync(0xffffffffu, t, o));
        if (lane == 0) red[0] = t;
    }
    __syncthreads();
    float r = red[0];
    __syncthreads();
    return r;
}

// ---------------- tf32 helpers ----------------
__device__ __forceinline__ uint32_t f2tf32(float x) {
    uint32_t u;
    asm("cvt.rna.tf32.f32 %0, %1;" : "=r"(u) : "f"(x));
    return u;
}

__device__ __forceinline__ void mma_tf32(float* c,
    uint32_t a0, uint32_t a1, uint32_t a2, uint32_t a3,
    uint32_t b0, uint32_t b1) {
    asm volatile(
        "mma.sync.aligned.m16n8k8.row.col.f32.tf32.tf32.f32 "
        "{%0,%1,%2,%3}, {%4,%5,%6,%7}, {%8,%9}, {%0,%1,%2,%3};"
        : "+f"(c[0]), "+f"(c[1]), "+f"(c[2]), "+f"(c[3])
        : "r"(a0), "r"(a1), "r"(a2), "r"(a3), "r"(b0), "r"(b1));
}

// ---------------- TF32x3 GEMM: C[M,N] = A[M,K] @ W[K,N] + bias (opt relu) ----------------
// BM=128, BN=128, BK=16, 256 threads = 8 warps (4x2), warp tile 32x64.
// Fragment-friendly permuted smem layout: k' = 4*(k%4) + k/4 within each BK=16,
// so one aligned LDS.128 per fragment row covers both k8-subtiles.
// Precision: 3xTF32 split (hi/lo), residual ~2^-22.
#define ASTRIDE 20
__global__ __launch_bounds__(256, 2) void gemm_tf32(
    const float* __restrict__ A, const float* __restrict__ W,
    const float* __restrict__ bias, float* __restrict__ C,
    int M, int N, int K, int relu)
{
    __shared__ uint32_t As[2][128 * ASTRIDE];   // [hi/lo][m*20 + k']
    __shared__ uint32_t Bs[2][128 * ASTRIDE];   // [hi/lo][n*20 + k']

    const int tid = threadIdx.x;
    const int wid = tid >> 5, lane = tid & 31;
    const int g = lane >> 2, tig = lane & 3;
    const int wm = wid >> 1, wn = wid & 1;
    const int bm = blockIdx.y * 128, bn = blockIdx.x * 128;

    float c[2][8][4];
#pragma unroll
    for (int mt = 0; mt < 2; mt++)
#pragma unroll
        for (int nt = 0; nt < 8; nt++)
#pragma unroll
            for (int r = 0; r < 4; r++) c[mt][nt][r] = 0.f;

    for (int k0 = 0; k0 < K; k0 += 16) {
        // --- load A tile 128x16 (512 float4 / 512 thread-iters) ---
#pragma unroll
        for (int i = 0; i < 2; i++) {
            int f = tid + i * 256;
            int r = f >> 2, cc = f & 3;
            float4 v = *(const float4*)(A + (size_t)(bm + r) * K + k0 + cc * 4);
            float xs[4] = {v.x, v.y, v.z, v.w};
#pragma unroll
            for (int j = 0; j < 4; j++) {
                uint32_t h = f2tf32(xs[j]);
                uint32_t l = f2tf32(xs[j] - __uint_as_float(h));
                As[0][r * ASTRIDE + 4 * j + cc] = h;
                As[1][r * ASTRIDE + 4 * j + cc] = l;
            }
        }
        // --- load B tile 16x128, store transposed [n][k'] ---
#pragma unroll
        for (int i = 0; i < 2; i++) {
            int f = tid + i * 256;
            int kr = f >> 5, nc = f & 31;
            float4 v = *(const float4*)(W + (size_t)(k0 + kr) * N + bn + nc * 4);
            int kp = 4 * (kr & 3) + (kr >> 2);
            float xs[4] = {v.x, v.y, v.z, v.w};
#pragma unroll
            for (int j = 0; j < 4; j++) {
                uint32_t h = f2tf32(xs[j]);
                uint32_t l = f2tf32(xs[j] - __uint_as_float(h));
                Bs[0][(nc * 4 + j) * ASTRIDE + kp] = h;
                Bs[1][(nc * 4 + j) * ASTRIDE + kp] = l;
            }
        }
        __syncthreads();

        // --- A fragments (both 16-row halves, hi+lo), one LDS.128 each ---
        uint4 ah[2][2], al[2][2];
#pragma unroll
        for (int mt = 0; mt < 2; mt++) {
            int mrow = wm * 32 + mt * 16 + g;
            ah[mt][0] = *(const uint4*)&As[0][mrow * ASTRIDE + 4 * tig];
            ah[mt][1] = *(const uint4*)&As[0][(mrow + 8) * ASTRIDE + 4 * tig];
            al[mt][0] = *(const uint4*)&As[1][mrow * ASTRIDE + 4 * tig];
            al[mt][1] = *(const uint4*)&As[1][(mrow + 8) * ASTRIDE + 4 * tig];
        }
#pragma unroll
        for (int nt = 0; nt < 8; nt++) {
            int nrow = wn * 64 + nt * 8 + g;
            uint4 bh = *(const uint4*)&Bs[0][nrow * ASTRIDE + 4 * tig];
            uint4 bl = *(const uint4*)&Bs[1][nrow * ASTRIDE + 4 * tig];
#pragma unroll
            for (int mt = 0; mt < 2; mt++) {
                float* cc4 = c[mt][nt];
                // k-subtile 0 (k = 0..7 of this BK): regs .x/.y
                mma_tf32(cc4, ah[mt][0].x, ah[mt][1].x, ah[mt][0].y, ah[mt][1].y, bh.x, bh.y);
                mma_tf32(cc4, al[mt][0].x, al[mt][1].x, al[mt][0].y, al[mt][1].y, bh.x, bh.y);
                mma_tf32(cc4, ah[mt][0].x, ah[mt][1].x, ah[mt][0].y, ah[mt][1].y, bl.x, bl.y);
                // k-subtile 1 (k = 8..15): regs .z/.w
                mma_tf32(cc4, ah[mt][0].z, ah[mt][1].z, ah[mt][0].w, ah[mt][1].w, bh.z, bh.w);
                mma_tf32(cc4, al[mt][0].z, al[mt][1].z, al[mt][0].w, al[mt][1].w, bh.z, bh.w);
                mma_tf32(cc4, ah[mt][0].z, ah[mt][1].z, ah[mt][0].w, ah[mt][1].w, bl.z, bl.w);
            }
        }
        __syncthreads();
    }

    // --- epilogue: bias (+relu), float2 stores ---
#pragma unroll
    for (int mt = 0; mt < 2; mt++) {
        int row = bm + wm * 32 + mt * 16 + g;
#pragma unroll
        for (int nt = 0; nt < 8; nt++) {
            int col = bn + wn * 64 + nt * 8 + tig * 2;
            float b0 = bias[col], b1 = bias[col + 1];
            float v0 = c[mt][nt][0] + b0, v1 = c[mt][nt][1] + b1;
            float v2 = c[mt][nt][2] + b0, v3 = c[mt][nt][3] + b1;
            if (relu) {
                v0 = fmaxf(v0, 0.f); v1 = fmaxf(v1, 0.f);
                v2 = fmaxf(v2, 0.f); v3 = fmaxf(v3, 0.f);
            }
            *(float2*)(C + (size_t)row * N + col) = make_float2(v0, v1);
            *(float2*)(C + (size_t)(row + 8) * N + col) = make_float2(v2, v3);
        }
    }
}

// ---------------- S_rel[b,h,q,r] = Qh[b,q,h,:] . rel_k[r,:] ----------------
// rk padded to stride 65 -> adjacent lanes (different r) hit distinct banks.
__global__ void srel_kernel(const float* __restrict__ rel_k) {
    int blk = blockIdx.x;               // b*L + q
    int b = blk >> 10, q = blk & 1023;
    __shared__ float qrow[DM];
    __shared__ float rk[NREL * 65];
    int tid = threadIdx.x;
    *(float4*)(qrow + tid * 4) = *(const float4*)(g_Q + (size_t)blk * DM + tid * 4);
    for (int o = tid; o < NREL * DK; o += 256) {
        int r = o >> 6, d = o & 63;
        rk[r * 65 + d] = rel_k[o];
    }
    __syncthreads();
    for (int o = tid; o < NH * NREL; o += 256) {
        int h = o / NREL, r = o % NREL;
        float acc = 0.f;
#pragma unroll
        for (int d = 0; d < DK; d++) acc += qrow[h * DK + d] * rk[r * 65 + d];
        g_Srel[(((size_t)(b * NH + h)) * LSEQ + q) * NREL + r] = acc;
    }
}

// ---------------- scores: S = (Qh Kh^T + Srel-lookup) / 8 ----------------
__global__ void attn_scores() {
    int bh = blockIdx.z, b = bh >> 4, h = bh & 15;
    int bq = blockIdx.y * 64, bk = blockIdx.x * 64;
    __shared__ __align__(16) float Qs[64][68];   // [d][q]
    __shared__ __align__(16) float Ks[64][68];   // [d][k]
    int tid = threadIdx.x, tx = tid & 15, ty = tid >> 4;
    const float* Qb = g_Q + ((size_t)(b * LSEQ) + bq) * DM + h * DK;
    const float* Kb = g_K + ((size_t)(b * LSEQ) + bk) * DM + h * DK;
#pragma unroll
    for (int i = 0; i < 4; i++) {
        int f = tid + i * 256;              // 1024 float4
        int r = f >> 4, c4 = f & 15;
        float4 vq = *(const float4*)(Qb + (size_t)r * DM + c4 * 4);
        Qs[c4 * 4 + 0][r] = vq.x; Qs[c4 * 4 + 1][r] = vq.y;
        Qs[c4 * 4 + 2][r] = vq.z; Qs[c4 * 4 + 3][r] = vq.w;
        float4 vk = *(const float4*)(Kb + (size_t)r * DM + c4 * 4);
        Ks[c4 * 4 + 0][r] = vk.x; Ks[c4 * 4 + 1][r] = vk.y;
        Ks[c4 * 4 + 2][r] = vk.z; Ks[c4 * 4 + 3][r] = vk.w;
    }
    __syncthreads();
    float acc[4][4] = {};
#pragma unroll 16
    for (int kk = 0; kk < 64; kk++) {
        float a[4], bb[4];
#pragma unroll
        for (int i = 0; i < 4; i++) a[i] = Qs[kk][ty * 4 + i];
#pragma unroll
        for (int j = 0; j < 4; j++) bb[j] = Ks[kk][tx * 4 + j];
#pragma unroll
        for (int i = 0; i < 4; i++)
#pragma unroll
            for (int j = 0; j < 4; j++) acc[i][j] += a[i] * bb[j];
    }
    const float* srel = g_Srel + (size_t)bh * LSEQ * NREL;
#pragma unroll
    for (int i = 0; i < 4; i++) {
        int q = bq + ty * 4 + i;
#pragma unroll
        for (int j = 0; j < 4; j++) {
            int k = bk + tx * 4 + j;
            int d = k - q; d = max(-16, min(16, d));
            float val = (acc[i][j] + srel[(size_t)q * NREL + (d + 16)]) * 0.125f;
            g_S[((size_t)bh * LSEQ + q) * LSEQ + k] = val;
        }
    }
}

// ---------------- softmax rows (in place) + relative-position buckets ----------------
__global__ void softmax_bucket() {
    int row = blockIdx.x;               // bh*L + q
    int q = row & (LSEQ - 1);
    float* Sr = g_S + (size_t)row * LSEQ;
    int tid = threadIdx.x;
    __shared__ float sp[LSEQ];
    __shared__ float red[32];
    float4 v = *(float4*)(Sr + tid * 4);
    float m = fmaxf(fmaxf(v.x, v.y), fmaxf(v.z, v.w));
    m = block_max(m, red);
    float e0 = __expf(v.x - m), e1 = __expf(v.y - m);
    float e2 = __expf(v.z - m), e3 = __expf(v.w - m);
    float s = block_sum(e0 + e1 + e2 + e3, red);
    float inv = 1.f / s;
    float p0 = e0 * inv, p1 = e1 * inv, p2 = e2 * inv, p3 = e3 * inv;
    int k0 = tid * 4;
    sp[k0] = p0; sp[k0 + 1] = p1; sp[k0 + 2] = p2; sp[k0 + 3] = p3;
    *(float4*)(Sr + k0) = make_float4(p0, p1, p2, p3);
    float lo = 0.f, hi = 0.f;
    float pv[4] = {p0, p1, p2, p3};
#pragma unroll
    for (int u = 0; u < 4; u++) {
        int k = k0 + u;
        if (k <= q - 16) lo += pv[u];
        if (k >= q + 16) hi += pv[u];
    }
    lo = block_sum(lo, red);            // also serves as barrier for sp
    hi = block_sum(hi, red);
    float* Wr = g_Wb + (size_t)row * NREL;
    if (tid == 0) { Wr[0] = lo; Wr[32] = hi; }
    if (tid < 31) {
        int r = tid + 1;
        int k = q + r - 16;
        Wr[r] = (k >= 0 && k < LSEQ) ? sp[k] : 0.f;
    }
}

// ---------------- attn output: P @ Vh + Wb @ rel_v, written as [B,L,H*DV] ----------------
__global__ void attn_av(const float* __restrict__ rel_v) {
    int bh = blockIdx.z, b = bh >> 4, h = bh & 15;
    int bq = blockIdx.y * 64;
    __shared__ __align__(16) float Pt[64][68];   // [k][q]
    __shared__ __align__(16) float Vs[64][68];   // [k][d]
    int tid = threadIdx.x, tx = tid & 15, ty = tid >> 4;
    float acc[4][4] = {};
    for (int k0 = 0; k0 < LSEQ; k0 += 64) {
#pragma unroll
        for (int i = 0; i < 4; i++) {
            int f = tid + i * 256;
            int r = f >> 4, c4 = f & 15;
            float4 p = *(const float4*)(g_S + ((size_t)bh * LSEQ + bq + r) * LSEQ + k0 + c4 * 4);
            Pt[c4 * 4 + 0][r] = p.x; Pt[c4 * 4 + 1][r] = p.y;
            Pt[c4 * 4 + 2][r] = p.z; Pt[c4 * 4 + 3][r] = p.w;
            float4 vv = *(const float4*)(g_V + ((size_t)(b * LSEQ) + k0 + r) * DM + h * DK + c4 * 4);
            *(float4*)&Vs[r][c4 * 4] = vv;
        }
        __syncthreads();
#pragma unroll 16
        for (int kk = 0; kk < 64; kk++) {
            float a[4], bb[4];
#pragma unroll
            for (int i = 0; i < 4; i++) a[i] = Pt[kk][ty * 4 + i];
#pragma unroll
            for (int j = 0; j < 4; j++) bb[j] = Vs[kk][tx * 4 + j];
#pragma unroll
            for (int i = 0; i < 4; i++)
#pragma unroll
                for (int j = 0; j < 4; j++) acc[i][j] += a[i] * bb[j];
        }
        __syncthreads();
    }
    // rank-33 relative-V update; reuse smem
    float* Wl = &Pt[0][0];   // 64*33
    float* rv = &Vs[0][0];   // 33*64
    for (int o = tid; o < 64 * NREL; o += 256) {
        int m = o / NREL, r = o % NREL;
        Wl[o] = g_Wb[((size_t)bh * LSEQ + bq + m) * NREL + r];
    }
    for (int o = tid; o < NREL * DK; o += 256) rv[o] = rel_v[o];
    __syncthreads();
#pragma unroll 1
    for (int r = 0; r < NREL; r++) {
        float bb[4];
#pragma unroll
        for (int j = 0; j < 4; j++) bb[j] = rv[r * DK + tx * 4 + j];
#pragma unroll
        for (int i = 0; i < 4; i++) {
            float w = Wl[(ty * 4 + i) * NREL + r];
#pragma unroll
            for (int j = 0; j < 4; j++) acc[i][j] += w * bb[j];
        }
    }
#pragma unroll
    for (int i = 0; i < 4; i++) {
        int qi = bq + ty * 4 + i;
#pragma unroll
        for (int j = 0; j < 4; j++) {
            int d = tx * 4 + j;
            g_attn[((size_t)(b * LSEQ) + qi) * DM + h * DK + d] = acc[i][j];
        }
    }
}

// ---------------- layernorm: O = LN(X (+Res)) * g + b ----------------
__global__ void layernorm_k(const float* __restrict__ X, const float* __restrict__ Res,
                            const float* __restrict__ gam, const float* __restrict__ bet,
                            float* __restrict__ O) {
    int row = blockIdx.x, tid = threadIdx.x;
    __shared__ float red[32];
    float4 v = *(const float4*)(X + (size_t)row * DM + tid * 4);
    if (Res) {
        float4 rr = *(const float4*)(Res + (size_t)row * DM + tid * 4);
        v.x += rr.x; v.y += rr.y; v.z += rr.z; v.w += rr.w;
    }
    float s = block_sum(v.x + v.y + v.z + v.w, red);
    float s2 = block_sum(v.x * v.x + v.y * v.y + v.z * v.z + v.w * v.w, red);
    float mu = s * (1.f / DM);
    float var = s2 * (1.f / DM) - mu * mu;
    float rstd = rsqrtf(var + 1e-6f);
    float4 g4 = *(const float4*)(gam + tid * 4);
    float4 b4 = *(const float4*)(bet + tid * 4);
    float4 o;
    o.x = (v.x - mu) * rstd * g4.x + b4.x;
    o.y = (v.y - mu) * rstd * g4.y + b4.y;
    o.z = (v.z - mu) * rstd * g4.z + b4.z;
    o.w = (v.w - mu) * rstd * g4.w + b4.w;
    *(float4*)(O + (size_t)row * DM + tid * 4) = o;
}

// ---------------- launch ----------------
static void* sym_addr(const void* s) { void* p = nullptr; cudaGetSymbolAddress(&p, s); return p; }

extern "C" void kernel_launch(void* const* d_in, const int* in_sizes, int n_in,
                              void* d_out, int out_size) {
    const float* q    = (const float*)d_in[0];
    const float* k    = (const float*)d_in[1];
    const float* v    = (const float*)d_in[2];
    const float* wq   = (const float*)d_in[3];
    const float* bq   = (const float*)d_in[4];
    const float* wk   = (const float*)d_in[5];
    const float* bk   = (const float*)d_in[6];
    const float* wv   = (const float*)d_in[7];
    const float* bv   = (const float*)d_in[8];
    const float* wfc  = (const float*)d_in[9];
    const float* bfc  = (const float*)d_in[10];
    const float* w1   = (const float*)d_in[11];
    const float* b1   = (const float*)d_in[12];
    const float* w2   = (const float*)d_in[13];
    const float* b2   = (const float*)d_in[14];
    const float* ln_g = (const float*)d_in[15];
    const float* ln_b = (const float*)d_in[16];
    const float* relk = (const float*)d_in[17];
    const float* relv = (const float*)d_in[18];
    float* out = (float*)d_out;

    float* pQ    = (float*)sym_addr(g_Q);
    float* pK    = (float*)sym_addr(g_K);
    float* pV    = (float*)sym_addr(g_V);
    float* pAttn = (float*)sym_addr(g_attn);
    float* pTmp  = (float*)sym_addr(g_tmp);
    float* pLn1  = (float*)sym_addr(g_ln1);
    float* pH1   = (float*)sym_addr(g_h1);
    float* pT2   = (float*)sym_addr(g_t2);

    dim3 gD(DM / 128, ROWS / 128);    // N=1024 GEMMs: 8 x 64
    dim3 gI(DI / 128, ROWS / 128);    // N=4096 GEMM: 32 x 64

    gemm_tf32<<<gD, 256>>>(q, wq, bq, pQ, ROWS, DM, DM, 0);
    gemm_tf32<<<gD, 256>>>(k, wk, bk, pK, ROWS, DM, DM, 0);
    gemm_tf32<<<gD, 256>>>(v, wv, bv, pV, ROWS, DM, DM, 0);

    srel_kernel<<<ROWS, 256>>>(relk);

    dim3 gs(LSEQ / 64, LSEQ / 64, BHN);
    attn_scores<<<gs, 256>>>();

    softmax_bucket<<<BHN * LSEQ, 256>>>();

    dim3 gav(1, LSEQ / 64, BHN);
    attn_av<<<gav, 256>>>(relv);

    gemm_tf32<<<gD, 256>>>(pAttn, wfc, bfc, pTmp, ROWS, DM, DM, 0);
    layernorm_k<<<ROWS, 256>>>(pTmp, q, ln_g, ln_b, pLn1);

    gemm_tf32<<<gI, 256>>>(pLn1, w1, b1, pH1, ROWS, DI, DM, 1);
    gemm_tf32<<<gD, 256>>>(pH1, w2, b2, pT2, ROWS, DM, DI, 0);
    layernorm_k<<<ROWS, 256>>>(pT2, pLn1, ln_g, ln_b, out);
}

// round 4
// speedup vs baseline: 2.4774x; 2.4774x over previous
#include <cuda_runtime.h>
#include <cuda_bf16.h>
#include <cstdint>

#define LSEQ 1024
#define DM   1024
#define BATCH 8
#define NH   16
#define DK   64
#define BHN  (BATCH*NH)     // 128
#define NREL 33
#define DI   4096
#define ROWS (BATCH*LSEQ)   // 8192

// ---------------- scratch (static device arrays; no allocation) ----------------
__device__ float g_Q[ROWS*DM];
__device__ float g_K[ROWS*DM];
__device__ float g_V[ROWS*DM];
__device__ float g_S[(size_t)BHN*LSEQ*LSEQ];      // 512 MB scores/probs
__device__ float g_Srel[(size_t)BHN*LSEQ*NREL];
__device__ float g_Wb[(size_t)BHN*LSEQ*NREL];
__device__ float g_attn[ROWS*DM];
__device__ float g_tmp[ROWS*DM];
__device__ float g_ln1[ROWS*DM];
__device__ float g_h1[(size_t)ROWS*DI];
__device__ float g_t2[ROWS*DM];
// bf16 split buffers
__device__ __nv_bfloat16 g_Ahi[(size_t)ROWS*DI];
__device__ __nv_bfloat16 g_Alo[(size_t)ROWS*DI];
__device__ __nv_bfloat16 g_Whi[(size_t)DM*DI];
__device__ __nv_bfloat16 g_Wlo[(size_t)DM*DI];

// ---------------- helpers ----------------
__device__ __forceinline__ uint32_t smem_u32(const void* p) {
    uint32_t a;
    asm("{ .reg .u64 t; cvta.to.shared.u64 t, %1; cvt.u32.u64 %0, t; }" : "=r"(a) : "l"(p));
    return a;
}

__device__ __forceinline__ void cp_async16(uint32_t saddr, const void* gaddr) {
    asm volatile("cp.async.cg.shared.global [%0], [%1], 16;" :: "r"(saddr), "l"(gaddr));
}
__device__ __forceinline__ void cp_async_wait_all() {
    asm volatile("cp.async.commit_group;\ncp.async.wait_group 0;" ::: "memory");
}

__device__ __forceinline__ void ldmx4(uint32_t* r, uint32_t addr) {
    asm volatile("ldmatrix.sync.aligned.m8n8.x4.shared.b16 {%0,%1,%2,%3}, [%4];"
        : "=r"(r[0]), "=r"(r[1]), "=r"(r[2]), "=r"(r[3]) : "r"(addr));
}

__device__ __forceinline__ void mma_bf16(float* c, const uint32_t* a, uint32_t b0, uint32_t b1) {
    asm volatile(
        "mma.sync.aligned.m16n8k16.row.col.f32.bf16.bf16.f32 "
        "{%0,%1,%2,%3}, {%4,%5,%6,%7}, {%8,%9}, {%0,%1,%2,%3};"
        : "+f"(c[0]), "+f"(c[1]), "+f"(c[2]), "+f"(c[3])
        : "r"(a[0]), "r"(a[1]), "r"(a[2]), "r"(a[3]), "r"(b0), "r"(b1));
}

// ---------------- split conversion kernels ----------------
__global__ void conv_split(const float* __restrict__ X, __nv_bfloat16* __restrict__ hi,
                           __nv_bfloat16* __restrict__ lo) {
    int i = blockIdx.x * blockDim.x + threadIdx.x;       // per float4
    float4 v = ((const float4*)X)[i];
    __nv_bfloat16 h[4], l[4];
    float xs[4] = {v.x, v.y, v.z, v.w};
#pragma unroll
    for (int j = 0; j < 4; j++) {
        h[j] = __float2bfloat16(xs[j]);
        l[j] = __float2bfloat16(xs[j] - __bfloat162float(h[j]));
    }
    *(uint2*)(hi + (size_t)i * 4) = *(uint2*)h;
    *(uint2*)(lo + (size_t)i * 4) = *(uint2*)l;
}

// W[K,N] -> hiT/loT [N,K]
__global__ void conv_split_T(const float* __restrict__ W, __nv_bfloat16* __restrict__ hiT,
                             __nv_bfloat16* __restrict__ loT, int K, int N) {
    __shared__ float t[32][33];
    int n0 = blockIdx.x * 32, k0 = blockIdx.y * 32;
    int tx = threadIdx.x, ty = threadIdx.y;
    for (int i = ty; i < 32; i += 8)
        t[i][tx] = W[(size_t)(k0 + i) * N + n0 + tx];
    __syncthreads();
    for (int r = ty; r < 32; r += 8) {
        float x = t[tx][r];                 // = W[k0+tx][n0+r]
        __nv_bfloat16 h = __float2bfloat16(x);
        __nv_bfloat16 l = __float2bfloat16(x - __bfloat162float(h));
        size_t o = (size_t)(n0 + r) * K + k0 + tx;
        hiT[o] = h;
        loT[o] = l;
    }
}

// ---------------- bf16x3 mma.sync GEMM: C[M,N] = A @ W + bias (opt relu) ----------------
// A (hi/lo) [M,K] K-major bf16; B (hi/lo) [N,K] K-major bf16 (pre-transposed W).
// BM=128, BN=128, BK=32, 256 threads = 8 warps (2 m x 4 n), warp tile 64x32.
#define SPAD 40   // bf16 row stride in smem (80 bytes) -> conflict-free ldmatrix
__global__ __launch_bounds__(256, 2) void gemm_tc(
    const __nv_bfloat16* __restrict__ Ahi, const __nv_bfloat16* __restrict__ Alo,
    const __nv_bfloat16* __restrict__ Bhi, const __nv_bfloat16* __restrict__ Blo,
    const float* __restrict__ bias, float* __restrict__ C,
    int M, int N, int K, int relu)
{
    __shared__ __nv_bfloat16 sAh[128 * SPAD];
    __shared__ __nv_bfloat16 sAl[128 * SPAD];
    __shared__ __nv_bfloat16 sBh[128 * SPAD];
    __shared__ __nv_bfloat16 sBl[128 * SPAD];

    const int tid = threadIdx.x;
    const int wid = tid >> 5, lane = tid & 31;
    const int wm = wid >> 2, wn = wid & 3;   // 2 x 4 warps
    const int bm = blockIdx.y * 128, bn = blockIdx.x * 128;

    const uint32_t aAh = smem_u32(sAh), aAl = smem_u32(sAl);
    const uint32_t aBh = smem_u32(sBh), aBl = smem_u32(sBl);

    float c[4][4][4];
#pragma unroll
    for (int mt = 0; mt < 4; mt++)
#pragma unroll
        for (int nt = 0; nt < 4; nt++)
#pragma unroll
            for (int r = 0; r < 4; r++) c[mt][nt][r] = 0.f;

    // fragment smem addresses (per lane, constant across tiles)
    // A: m = wm*64 + mt*16 + (lane%8) + 8*((lane/8)&1); kk = 8*(lane/16)
    const int a_m_base = wm * 64 + (lane & 7) + 8 * ((lane >> 3) & 1);
    const int a_kk = 8 * (lane >> 4);
    // B: n = wn*32 + p*16 + (lane%8) + 8*(lane/16); kk = 8*((lane/8)&1)
    const int b_n_base = wn * 32 + (lane & 7) + 8 * (lane >> 4);
    const int b_kk = 8 * ((lane >> 3) & 1);

    const int ktiles = K >> 5;
    for (int t = 0; t < ktiles; t++) {
        const int kbase = t * 32;
        // --- cp.async tile loads: 512 16B segments per array, 2 per thread ---
#pragma unroll
        for (int i = 0; i < 2; i++) {
            int f = tid + i * 256;
            int row = f >> 2, seg = f & 3;
            uint32_t so = (uint32_t)(row * SPAD + seg * 8) * 2;
            size_t ga = (size_t)(bm + row) * K + kbase + seg * 8;
            size_t gb = (size_t)(bn + row) * K + kbase + seg * 8;
            cp_async16(aAh + so, Ahi + ga);
            cp_async16(aAl + so, Alo + ga);
            cp_async16(aBh + so, Bhi + gb);
            cp_async16(aBl + so, Blo + gb);
        }
        cp_async_wait_all();
        __syncthreads();

#pragma unroll
        for (int kh = 0; kh < 2; kh++) {
            const int k0 = kh * 16;
            // B fragments: 4 n8-tiles, hi+lo (2 ldmatrix.x4 each)
            uint32_t bh[8], bl[8];
#pragma unroll
            for (int p = 0; p < 2; p++) {
                uint32_t off = (uint32_t)((b_n_base + p * 16) * SPAD + k0 + b_kk) * 2;
                ldmx4(bh + p * 4, aBh + off);
                ldmx4(bl + p * 4, aBl + off);
            }
#pragma unroll
            for (int mt = 0; mt < 4; mt++) {
                uint32_t ah[4], al[4];
                uint32_t off = (uint32_t)((a_m_base + mt * 16) * SPAD + k0 + a_kk) * 2;
                ldmx4(ah, aAh + off);
                ldmx4(al, aAl + off);
#pragma unroll
                for (int nt = 0; nt < 4; nt++) {
                    mma_bf16(c[mt][nt], ah, bh[nt * 2], bh[nt * 2 + 1]);
                    mma_bf16(c[mt][nt], ah, bl[nt * 2], bl[nt * 2 + 1]);
                    mma_bf16(c[mt][nt], al, bh[nt * 2], bh[nt * 2 + 1]);
                }
            }
        }
        __syncthreads();
    }

    // --- epilogue: bias (+relu), float2 stores ---
    const int r0 = lane >> 2, c0 = (lane & 3) * 2;
#pragma unroll
    for (int mt = 0; mt < 4; mt++) {
        int row = bm + wm * 64 + mt * 16 + r0;
#pragma unroll
        for (int nt = 0; nt < 4; nt++) {
            int col = bn + wn * 32 + nt * 8 + c0;
            float b0v = bias[col], b1v = bias[col + 1];
            float v0 = c[mt][nt][0] + b0v, v1 = c[mt][nt][1] + b1v;
            float v2 = c[mt][nt][2] + b0v, v3 = c[mt][nt][3] + b1v;
            if (relu) {
                v0 = fmaxf(v0, 0.f); v1 = fmaxf(v1, 0.f);
                v2 = fmaxf(v2, 0.f); v3 = fmaxf(v3, 0.f);
            }
            *(float2*)(C + (size_t)row * N + col) = make_float2(v0, v1);
            *(float2*)(C + (size_t)(row + 8) * N + col) = make_float2(v2, v3);
        }
    }
}

// ---------------- reductions ----------------
__device__ __forceinline__ float block_sum(float v, float* red) {
    int lane = threadIdx.x & 31, w = threadIdx.x >> 5;
#pragma unroll
    for (int o = 16; o; o >>= 1) v += __shfl_xor_sync(0xffffffffu, v, o);
    if (lane == 0) red[w] = v;
    __syncthreads();
    if (w == 0) {
        float t = (lane < 8) ? red[lane] : 0.f;
#pragma unroll
        for (int o = 4; o; o >>= 1) t += __shfl_xor_sync(0xffffffffu, t, o);
        if (lane == 0) red[0] = t;
    }
    __syncthreads();
    float r = red[0];
    __syncthreads();
    return r;
}

__device__ __forceinline__ float block_max(float v, float* red) {
    int lane = threadIdx.x & 31, w = threadIdx.x >> 5;
#pragma unroll
    for (int o = 16; o; o >>= 1) v = fmaxf(v, __shfl_xor_sync(0xffffffffu, v, o));
    if (lane == 0) red[w] = v;
    __syncthreads();
    if (w == 0) {
        float t = (lane < 8) ? red[lane] : -3.4e38f;
#pragma unroll
        for (int o = 4; o; o >>= 1) t = fmaxf(t, __shfl_xor_sync(0xffffffffu, t, o));
        if (lane == 0) red[0] = t;
    }
    __syncthreads();
    float r = red[0];
    __syncthreads();
    return r;
}

// ---------------- S_rel[b,h,q,r] = Qh[b,q,h,:] . rel_k[r,:] ----------------
__global__ void srel_kernel(const float* __restrict__ rel_k) {
    int blk = blockIdx.x;               // b*L + q
    int b = blk >> 10, q = blk & 1023;
    __shared__ float qrow[DM];
    __shared__ float rk[NREL * 65];
    int tid = threadIdx.x;
    *(float4*)(qrow + tid * 4) = *(const float4*)(g_Q + (size_t)blk * DM + tid * 4);
    for (int o = tid; o < NREL * DK; o += 256) {
        int r = o >> 6, d = o & 63;
        rk[r * 65 + d] = rel_k[o];
    }
    __syncthreads();
    for (int o = tid; o < NH * NREL; o += 256) {
        int h = o / NREL, r = o % NREL;
        float acc = 0.f;
#pragma unroll
        for (int d = 0; d < DK; d++) acc += qrow[h * DK + d] * rk[r * 65 + d];
        g_Srel[(((size_t)(b * NH + h)) * LSEQ + q) * NREL + r] = acc;
    }
}

// ---------------- scores: S = (Qh Kh^T + Srel-lookup) / 8 ----------------
__global__ void attn_scores() {
    int bh = blockIdx.z, b = bh >> 4, h = bh & 15;
    int bq = blockIdx.y * 64, bk = blockIdx.x * 64;
    __shared__ __align__(16) float Qs[64][68];
    __shared__ __align__(16) float Ks[64][68];
    int tid = threadIdx.x, tx = tid & 15, ty = tid >> 4;
    const float* Qb = g_Q + ((size_t)(b * LSEQ) + bq) * DM + h * DK;
    const float* Kb = g_K + ((size_t)(b * LSEQ) + bk) * DM + h * DK;
#pragma unroll
    for (int i = 0; i < 4; i++) {
        int f = tid + i * 256;
        int r = f >> 4, c4 = f & 15;
        float4 vq = *(const float4*)(Qb + (size_t)r * DM + c4 * 4);
        Qs[c4 * 4 + 0][r] = vq.x; Qs[c4 * 4 + 1][r] = vq.y;
        Qs[c4 * 4 + 2][r] = vq.z; Qs[c4 * 4 + 3][r] = vq.w;
        float4 vk = *(const float4*)(Kb + (size_t)r * DM + c4 * 4);
        Ks[c4 * 4 + 0][r] = vk.x; Ks[c4 * 4 + 1][r] = vk.y;
        Ks[c4 * 4 + 2][r] = vk.z; Ks[c4 * 4 + 3][r] = vk.w;
    }
    __syncthreads();
    float acc[4][4] = {};
#pragma unroll 16
    for (int kk = 0; kk < 64; kk++) {
        float a[4], bb[4];
#pragma unroll
        for (int i = 0; i < 4; i++) a[i] = Qs[kk][ty * 4 + i];
#pragma unroll
        for (int j = 0; j < 4; j++) bb[j] = Ks[kk][tx * 4 + j];
#pragma unroll
        for (int i = 0; i < 4; i++)
#pragma unroll
            for (int j = 0; j < 4; j++) acc[i][j] += a[i] * bb[j];
    }
    const float* srel = g_Srel + (size_t)bh * LSEQ * NREL;
#pragma unroll
    for (int i = 0; i < 4; i++) {
        int q = bq + ty * 4 + i;
#pragma unroll
        for (int j = 0; j < 4; j++) {
            int k = bk + tx * 4 + j;
            int d = k - q; d = max(-16, min(16, d));
            float val = (acc[i][j] + srel[(size_t)q * NREL + (d + 16)]) * 0.125f;
            g_S[((size_t)bh * LSEQ + q) * LSEQ + k] = val;
        }
    }
}

// ---------------- softmax rows (in place) + relative-position buckets ----------------
__global__ void softmax_bucket() {
    int row = blockIdx.x;
    int q = row & (LSEQ - 1);
    float* Sr = g_S + (size_t)row * LSEQ;
    int tid = threadIdx.x;
    __shared__ float sp[LSEQ];
    __shared__ float red[32];
    float4 v = *(float4*)(Sr + tid * 4);
    float m = fmaxf(fmaxf(v.x, v.y), fmaxf(v.z, v.w));
    m = block_max(m, red);
    float e0 = __expf(v.x - m), e1 = __expf(v.y - m);
    float e2 = __expf(v.z - m), e3 = __expf(v.w - m);
    float s = block_sum(e0 + e1 + e2 + e3, red);
    float inv = 1.f / s;
    float p0 = e0 * inv, p1 = e1 * inv, p2 = e2 * inv, p3 = e3 * inv;
    int k0 = tid * 4;
    sp[k0] = p0; sp[k0 + 1] = p1; sp[k0 + 2] = p2; sp[k0 + 3] = p3;
    *(float4*)(Sr + k0) = make_float4(p0, p1, p2, p3);
    float lo = 0.f, hi = 0.f;
    float pv[4] = {p0, p1, p2, p3};
#pragma unroll
    for (int u = 0; u < 4; u++) {
        int k = k0 + u;
        if (k <= q - 16) lo += pv[u];
        if (k >= q + 16) hi += pv[u];
    }
    lo = block_sum(lo, red);
    hi = block_sum(hi, red);
    float* Wr = g_Wb + (size_t)row * NREL;
    if (tid == 0) { Wr[0] = lo; Wr[32] = hi; }
    if (tid < 31) {
        int r = tid + 1;
        int k = q + r - 16;
        Wr[r] = (k >= 0 && k < LSEQ) ? sp[k] : 0.f;
    }
}

// ---------------- attn output: P @ Vh + Wb @ rel_v ----------------
__global__ void attn_av(const float* __restrict__ rel_v) {
    int bh = blockIdx.z, b = bh >> 4, h = bh & 15;
    int bq = blockIdx.y * 64;
    __shared__ __align__(16) float Pt[64][68];
    __shared__ __align__(16) float Vs[64][68];
    int tid = threadIdx.x, tx = tid & 15, ty = tid >> 4;
    float acc[4][4] = {};
    for (int k0 = 0; k0 < LSEQ; k0 += 64) {
#pragma unroll
        for (int i = 0; i < 4; i++) {
            int f = tid + i * 256;
            int r = f >> 4, c4 = f & 15;
            float4 p = *(const float4*)(g_S + ((size_t)bh * LSEQ + bq + r) * LSEQ + k0 + c4 * 4);
            Pt[c4 * 4 + 0][r] = p.x; Pt[c4 * 4 + 1][r] = p.y;
            Pt[c4 * 4 + 2][r] = p.z; Pt[c4 * 4 + 3][r] = p.w;
            float4 vv = *(const float4*)(g_V + ((size_t)(b * LSEQ) + k0 + r) * DM + h * DK + c4 * 4);
            *(float4*)&Vs[r][c4 * 4] = vv;
        }
        __syncthreads();
#pragma unroll 16
        for (int kk = 0; kk < 64; kk++) {
            float a[4], bb[4];
#pragma unroll
            for (int i = 0; i < 4; i++) a[i] = Pt[kk][ty * 4 + i];
#pragma unroll
            for (int j = 0; j < 4; j++) bb[j] = Vs[kk][tx * 4 + j];
#pragma unroll
            for (int i = 0; i < 4; i++)
#pragma unroll
                for (int j = 0; j < 4; j++) acc[i][j] += a[i] * bb[j];
        }
        __syncthreads();
    }
    float* Wl = &Pt[0][0];
    float* rv = &Vs[0][0];
    for (int o = tid; o < 64 * NREL; o += 256) {
        int m = o / NREL, r = o % NREL;
        Wl[o] = g_Wb[((size_t)bh * LSEQ + bq + m) * NREL + r];
    }
    for (int o = tid; o < NREL * DK; o += 256) rv[o] = rel_v[o];
    __syncthreads();
#pragma unroll 1
    for (int r = 0; r < NREL; r++) {
        float bb[4];
#pragma unroll
        for (int j = 0; j < 4; j++) bb[j] = rv[r * DK + tx * 4 + j];
#pragma unroll
        for (int i = 0; i < 4; i++) {
            float w = Wl[(ty * 4 + i) * NREL + r];
#pragma unroll
            for (int j = 0; j < 4; j++) acc[i][j] += w * bb[j];
        }
    }
#pragma unroll
    for (int i = 0; i < 4; i++) {
        int qi = bq + ty * 4 + i;
#pragma unroll
        for (int j = 0; j < 4; j++) {
            int d = tx * 4 + j;
            g_attn[((size_t)(b * LSEQ) + qi) * DM + h * DK + d] = acc[i][j];
        }
    }
}

// ---------------- layernorm ----------------
__global__ void layernorm_k(const float* __restrict__ X, const float* __restrict__ Res,
                            const float* __restrict__ gam, const float* __restrict__ bet,
                            float* __restrict__ O) {
    int row = blockIdx.x, tid = threadIdx.x;
    __shared__ float red[32];
    float4 v = *(const float4*)(X + (size_t)row * DM + tid * 4);
    if (Res) {
        float4 rr = *(const float4*)(Res + (size_t)row * DM + tid * 4);
        v.x += rr.x; v.y += rr.y; v.z += rr.z; v.w += rr.w;
    }
    float s = block_sum(v.x + v.y + v.z + v.w, red);
    float s2 = block_sum(v.x * v.x + v.y * v.y + v.z * v.z + v.w * v.w, red);
    float mu = s * (1.f / DM);
    float var = s2 * (1.f / DM) - mu * mu;
    float rstd = rsqrtf(var + 1e-6f);
    float4 g4 = *(const float4*)(gam + tid * 4);
    float4 b4 = *(const float4*)(bet + tid * 4);
    float4 o;
    o.x = (v.x - mu) * rstd * g4.x + b4.x;
    o.y = (v.y - mu) * rstd * g4.y + b4.y;
    o.z = (v.z - mu) * rstd * g4.z + b4.z;
    o.w = (v.w - mu) * rstd * g4.w + b4.w;
    *(float4*)(O + (size_t)row * DM + tid * 4) = o;
}

// ---------------- launch ----------------
static void* sym_addr(const void* s) { void* p = nullptr; cudaGetSymbolAddress(&p, s); return p; }

extern "C" void kernel_launch(void* const* d_in, const int* in_sizes, int n_in,
                              void* d_out, int out_size) {
    const float* q    = (const float*)d_in[0];
    const float* k    = (const float*)d_in[1];
    const float* v    = (const float*)d_in[2];
    const float* wq   = (const float*)d_in[3];
    const float* bq   = (const float*)d_in[4];
    const float* wk   = (const float*)d_in[5];
    const float* bk   = (const float*)d_in[6];
    const float* wv   = (const float*)d_in[7];
    const float* bv   = (const float*)d_in[8];
    const float* wfc  = (const float*)d_in[9];
    const float* bfc  = (const float*)d_in[10];
    const float* w1   = (const float*)d_in[11];
    const float* b1   = (const float*)d_in[12];
    const float* w2   = (const float*)d_in[13];
    const float* b2   = (const float*)d_in[14];
    const float* ln_g = (const float*)d_in[15];
    const float* ln_b = (const float*)d_in[16];
    const float* relk = (const float*)d_in[17];
    const float* relv = (const float*)d_in[18];
    float* out = (float*)d_out;

    float* pQ    = (float*)sym_addr(g_Q);
    float* pK    = (float*)sym_addr(g_K);
    float* pV    = (float*)sym_addr(g_V);
    float* pAttn = (float*)sym_addr(g_attn);
    float* pTmp  = (float*)sym_addr(g_tmp);
    float* pLn1  = (float*)sym_addr(g_ln1);
    float* pH1   = (float*)sym_addr(g_h1);
    float* pT2   = (float*)sym_addr(g_t2);
    __nv_bfloat16* pAhi = (__nv_bfloat16*)sym_addr(g_Ahi);
    __nv_bfloat16* pAlo = (__nv_bfloat16*)sym_addr(g_Alo);
    __nv_bfloat16* pWhi = (__nv_bfloat16*)sym_addr(g_Whi);
    __nv_bfloat16* pWlo = (__nv_bfloat16*)sym_addr(g_Wlo);

    const int nD4 = ROWS * DM / 4 / 256;      // conv blocks for [8192,1024]
    const int nI4 = ROWS * DI / 4 / 256;      // conv blocks for [8192,4096]
    dim3 tBlk(32, 8);
    dim3 tGridD(DM / 32, DM / 32);            // [1024,1024] weights
    dim3 tGridW1(DI / 32, DM / 32);           // w1 [1024,4096]
    dim3 tGridW2(DM / 32, DI / 32);           // w2 [4096,1024]
    dim3 gD(DM / 128, ROWS / 128);
    dim3 gI(DI / 128, ROWS / 128);

    // QKV projections
    conv_split_T<<<tGridD, tBlk>>>(wq, pWhi, pWlo, DM, DM);
    conv_split<<<nD4, 256>>>(q, pAhi, pAlo);
    gemm_tc<<<gD, 256>>>(pAhi, pAlo, pWhi, pWlo, bq, pQ, ROWS, DM, DM, 0);

    conv_split_T<<<tGridD, tBlk>>>(wk, pWhi, pWlo, DM, DM);
    conv_split<<<nD4, 256>>>(k, pAhi, pAlo);
    gemm_tc<<<gD, 256>>>(pAhi, pAlo, pWhi, pWlo, bk, pK, ROWS, DM, DM, 0);

    conv_split_T<<<tGridD, tBlk>>>(wv, pWhi, pWlo, DM, DM);
    conv_split<<<nD4, 256>>>(v, pAhi, pAlo);
    gemm_tc<<<gD, 256>>>(pAhi, pAlo, pWhi, pWlo, bv, pV, ROWS, DM, DM, 0);

    // attention
    srel_kernel<<<ROWS, 256>>>(relk);
    dim3 gs(LSEQ / 64, LSEQ / 64, BHN);
    attn_scores<<<gs, 256>>>();
    softmax_bucket<<<BHN * LSEQ, 256>>>();
    dim3 gav(1, LSEQ / 64, BHN);
    attn_av<<<gav, 256>>>(relv);

    // out-proj + LN1
    conv_split_T<<<tGridD, tBlk>>>(wfc, pWhi, pWlo, DM, DM);
    conv_split<<<nD4, 256>>>(pAttn, pAhi, pAlo);
    gemm_tc<<<gD, 256>>>(pAhi, pAlo, pWhi, pWlo, bfc, pTmp, ROWS, DM, DM, 0);
    layernorm_k<<<ROWS, 256>>>(pTmp, q, ln_g, ln_b, pLn1);

    // FFN
    conv_split_T<<<tGridW1, tBlk>>>(w1, pWhi, pWlo, DM, DI);
    conv_split<<<nD4, 256>>>(pLn1, pAhi, pAlo);
    gemm_tc<<<gI, 256>>>(pAhi, pAlo, pWhi, pWlo, b1, pH1, ROWS, DI, DM, 1);

    conv_split_T<<<tGridW2, tBlk>>>(w2, pWhi, pWlo, DI, DM);
    conv_split<<<nI4, 256>>>(pH1, pAhi, pAlo);
    gemm_tc<<<gD, 256>>>(pAhi, pAlo, pWhi, pWlo, b2, pT2, ROWS, DM, DI, 0);
    layernorm_k<<<ROWS, 256>>>(pT2, pLn1, ln_g, ln_b, out);
}

// round 5
// speedup vs baseline: 3.1196x; 1.2592x over previous
#include <cuda_runtime.h>
#include <cuda_bf16.h>
#include <cstdint>

#define LSEQ 1024
#define DM   1024
#define BATCH 8
#define NH   16
#define DK   64
#define BHN  (BATCH*NH)     // 128
#define NREL 33
#define DI   4096
#define ROWS (BATCH*LSEQ)   // 8192

// ---------------- scratch (static device arrays; no allocation) ----------------
__device__ float g_Q[ROWS*DM];
__device__ float g_K[ROWS*DM];
__device__ float g_V[ROWS*DM];
__device__ float g_S[(size_t)BHN*LSEQ*LSEQ];      // 512 MB scores (fp32)
__device__ float g_Srel[(size_t)BHN*LSEQ*NREL];
__device__ float g_Wb[(size_t)BHN*LSEQ*NREL];
__device__ float g_attn[ROWS*DM];
__device__ float g_tmp[ROWS*DM];
__device__ float g_ln1[ROWS*DM];
__device__ float g_h1[(size_t)ROWS*DI];
__device__ float g_t2[ROWS*DM];
// bf16 split buffers (GEMM path)
__device__ __nv_bfloat16 g_Ahi[(size_t)ROWS*DI];
__device__ __nv_bfloat16 g_Alo[(size_t)ROWS*DI];
__device__ __nv_bfloat16 g_Whi[(size_t)DM*DI];
__device__ __nv_bfloat16 g_Wlo[(size_t)DM*DI];
// bf16 split buffers (attention path)
__device__ __nv_bfloat16 g_Qhi[ROWS*DM];
__device__ __nv_bfloat16 g_Qlo[ROWS*DM];
__device__ __nv_bfloat16 g_Khi[ROWS*DM];
__device__ __nv_bfloat16 g_Klo[ROWS*DM];
__device__ __nv_bfloat16 g_Vthi[(size_t)BHN*DK*LSEQ];   // [bh][d][k]
__device__ __nv_bfloat16 g_Vtlo[(size_t)BHN*DK*LSEQ];
__device__ __nv_bfloat16 g_Phi[(size_t)BHN*LSEQ*LSEQ];  // 256 MB
__device__ __nv_bfloat16 g_Plo[(size_t)BHN*LSEQ*LSEQ];  // 256 MB

// ---------------- helpers ----------------
__device__ __forceinline__ uint32_t smem_u32(const void* p) {
    uint32_t a;
    asm("{ .reg .u64 t; cvta.to.shared.u64 t, %1; cvt.u32.u64 %0, t; }" : "=r"(a) : "l"(p));
    return a;
}
__device__ __forceinline__ void cp_async16(uint32_t saddr, const void* gaddr) {
    asm volatile("cp.async.cg.shared.global [%0], [%1], 16;" :: "r"(saddr), "l"(gaddr));
}
__device__ __forceinline__ void cp_async_wait_all() {
    asm volatile("cp.async.commit_group;\ncp.async.wait_group 0;" ::: "memory");
}
__device__ __forceinline__ void ldmx4(uint32_t* r, uint32_t addr) {
    asm volatile("ldmatrix.sync.aligned.m8n8.x4.shared.b16 {%0,%1,%2,%3}, [%4];"
        : "=r"(r[0]), "=r"(r[1]), "=r"(r[2]), "=r"(r[3]) : "r"(addr));
}
__device__ __forceinline__ void mma_bf16(float* c, const uint32_t* a, uint32_t b0, uint32_t b1) {
    asm volatile(
        "mma.sync.aligned.m16n8k16.row.col.f32.bf16.bf16.f32 "
        "{%0,%1,%2,%3}, {%4,%5,%6,%7}, {%8,%9}, {%0,%1,%2,%3};"
        : "+f"(c[0]), "+f"(c[1]), "+f"(c[2]), "+f"(c[3])
        : "r"(a[0]), "r"(a[1]), "r"(a[2]), "r"(a[3]), "r"(b0), "r"(b1));
}

// ---------------- split conversion kernels ----------------
__global__ void conv_split(const float* __restrict__ X, __nv_bfloat16* __restrict__ hi,
                           __nv_bfloat16* __restrict__ lo) {
    int i = blockIdx.x * blockDim.x + threadIdx.x;       // per float4
    float4 v = ((const float4*)X)[i];
    __nv_bfloat16 h[4], l[4];
    float xs[4] = {v.x, v.y, v.z, v.w};
#pragma unroll
    for (int j = 0; j < 4; j++) {
        h[j] = __float2bfloat16(xs[j]);
        l[j] = __float2bfloat16(xs[j] - __bfloat162float(h[j]));
    }
    *(uint2*)(hi + (size_t)i * 4) = *(uint2*)h;
    *(uint2*)(lo + (size_t)i * 4) = *(uint2*)l;
}

// W[K,N] -> hiT/loT [N,K]
__global__ void conv_split_T(const float* __restrict__ W, __nv_bfloat16* __restrict__ hiT,
                             __nv_bfloat16* __restrict__ loT, int K, int N) {
    __shared__ float t[32][33];
    int n0 = blockIdx.x * 32, k0 = blockIdx.y * 32;
    int tx = threadIdx.x, ty = threadIdx.y;
    for (int i = ty; i < 32; i += 8)
        t[i][tx] = W[(size_t)(k0 + i) * N + n0 + tx];
    __syncthreads();
    for (int r = ty; r < 32; r += 8) {
        float x = t[tx][r];
        __nv_bfloat16 h = __float2bfloat16(x);
        __nv_bfloat16 l = __float2bfloat16(x - __bfloat162float(h));
        size_t o = (size_t)(n0 + r) * K + k0 + tx;
        hiT[o] = h;
        loT[o] = l;
    }
}

// V [b*L+k][h*64+d] -> Vt [bh][d][k] (hi/lo split)
__global__ void vt_split(const float* __restrict__ V, __nv_bfloat16* __restrict__ hiT,
                         __nv_bfloat16* __restrict__ loT) {
    __shared__ float t[32][33];
    int bh = blockIdx.z, b = bh >> 4, h = bh & 15;
    int k0 = blockIdx.x * 32, d0 = blockIdx.y * 32;
    int tx = threadIdx.x, ty = threadIdx.y;
    for (int i = ty; i < 32; i += 8)
        t[i][tx] = V[(size_t)(b * LSEQ + k0 + i) * DM + h * DK + d0 + tx];
    __syncthreads();
    for (int r = ty; r < 32; r += 8) {
        float x = t[tx][r];                      // = V[k0+tx][d0+r]
        __nv_bfloat16 hh = __float2bfloat16(x);
        __nv_bfloat16 ll = __float2bfloat16(x - __bfloat162float(hh));
        size_t o = ((size_t)bh * DK + d0 + r) * LSEQ + k0 + tx;
        hiT[o] = hh;
        loT[o] = ll;
    }
}

// ---------------- bf16x3 mma.sync GEMM (unchanged from R4) ----------------
#define SPAD 40
__global__ __launch_bounds__(256, 2) void gemm_tc(
    const __nv_bfloat16* __restrict__ Ahi, const __nv_bfloat16* __restrict__ Alo,
    const __nv_bfloat16* __restrict__ Bhi, const __nv_bfloat16* __restrict__ Blo,
    const float* __restrict__ bias, float* __restrict__ C,
    int M, int N, int K, int relu)
{
    __shared__ __nv_bfloat16 sAh[128 * SPAD];
    __shared__ __nv_bfloat16 sAl[128 * SPAD];
    __shared__ __nv_bfloat16 sBh[128 * SPAD];
    __shared__ __nv_bfloat16 sBl[128 * SPAD];

    const int tid = threadIdx.x;
    const int wid = tid >> 5, lane = tid & 31;
    const int wm = wid >> 2, wn = wid & 3;
    const int bm = blockIdx.y * 128, bn = blockIdx.x * 128;

    const uint32_t aAh = smem_u32(sAh), aAl = smem_u32(sAl);
    const uint32_t aBh = smem_u32(sBh), aBl = smem_u32(sBl);

    float c[4][4][4];
#pragma unroll
    for (int mt = 0; mt < 4; mt++)
#pragma unroll
        for (int nt = 0; nt < 4; nt++)
#pragma unroll
            for (int r = 0; r < 4; r++) c[mt][nt][r] = 0.f;

    const int a_m_base = wm * 64 + (lane & 7) + 8 * ((lane >> 3) & 1);
    const int a_kk = 8 * (lane >> 4);
    const int b_n_base = wn * 32 + (lane & 7) + 8 * (lane >> 4);
    const int b_kk = 8 * ((lane >> 3) & 1);

    const int ktiles = K >> 5;
    for (int t = 0; t < ktiles; t++) {
        const int kbase = t * 32;
#pragma unroll
        for (int i = 0; i < 2; i++) {
            int f = tid + i * 256;
            int row = f >> 2, seg = f & 3;
            uint32_t so = (uint32_t)(row * SPAD + seg * 8) * 2;
            size_t ga = (size_t)(bm + row) * K + kbase + seg * 8;
            size_t gb = (size_t)(bn + row) * K + kbase + seg * 8;
            cp_async16(aAh + so, Ahi + ga);
            cp_async16(aAl + so, Alo + ga);
            cp_async16(aBh + so, Bhi + gb);
            cp_async16(aBl + so, Blo + gb);
        }
        cp_async_wait_all();
        __syncthreads();

#pragma unroll
        for (int kh = 0; kh < 2; kh++) {
            const int k0 = kh * 16;
            uint32_t bh[8], bl[8];
#pragma unroll
            for (int p = 0; p < 2; p++) {
                uint32_t off = (uint32_t)((b_n_base + p * 16) * SPAD + k0 + b_kk) * 2;
                ldmx4(bh + p * 4, aBh + off);
                ldmx4(bl + p * 4, aBl + off);
            }
#pragma unroll
            for (int mt = 0; mt < 4; mt++) {
                uint32_t ah[4], al[4];
                uint32_t off = (uint32_t)((a_m_base + mt * 16) * SPAD + k0 + a_kk) * 2;
                ldmx4(ah, aAh + off);
                ldmx4(al, aAl + off);
#pragma unroll
                for (int nt = 0; nt < 4; nt++) {
                    mma_bf16(c[mt][nt], ah, bh[nt * 2], bh[nt * 2 + 1]);
                    mma_bf16(c[mt][nt], ah, bl[nt * 2], bl[nt * 2 + 1]);
                    mma_bf16(c[mt][nt], al, bh[nt * 2], bh[nt * 2 + 1]);
                }
            }
        }
        __syncthreads();
    }

    const int r0 = lane >> 2, c0 = (lane & 3) * 2;
#pragma unroll
    for (int mt = 0; mt < 4; mt++) {
        int row = bm + wm * 64 + mt * 16 + r0;
#pragma unroll
        for (int nt = 0; nt < 4; nt++) {
            int col = bn + wn * 32 + nt * 8 + c0;
            float b0v = bias[col], b1v = bias[col + 1];
            float v0 = c[mt][nt][0] + b0v, v1 = c[mt][nt][1] + b1v;
            float v2 = c[mt][nt][2] + b0v, v3 = c[mt][nt][3] + b1v;
            if (relu) {
                v0 = fmaxf(v0, 0.f); v1 = fmaxf(v1, 0.f);
                v2 = fmaxf(v2, 0.f); v3 = fmaxf(v3, 0.f);
            }
            *(float2*)(C + (size_t)row * N + col) = make_float2(v0, v1);
            *(float2*)(C + (size_t)(row + 8) * N + col) = make_float2(v2, v3);
        }
    }
}

// ---------------- attention scores via mma.sync: S = (Q K^T + srel)/8 ----------------
// 128x128 tile, K=64. dynamic smem: 4 x 128 x 72 bf16 = 73728 B
#define QPAD 72
__global__ __launch_bounds__(256, 2) void attn_scores_tc() {
    extern __shared__ __nv_bfloat16 dsm[];
    __nv_bfloat16* sQh = dsm;
    __nv_bfloat16* sQl = dsm + 128 * QPAD;
    __nv_bfloat16* sKh = dsm + 2 * 128 * QPAD;
    __nv_bfloat16* sKl = dsm + 3 * 128 * QPAD;

    const int tid = threadIdx.x;
    const int wid = tid >> 5, lane = tid & 31;
    const int wm = wid >> 2, wn = wid & 3;
    const int bh = blockIdx.z, b = bh >> 4, h = bh & 15;
    const int bq = blockIdx.y * 128, bk = blockIdx.x * 128;

    const uint32_t aQh = smem_u32(sQh), aQl = smem_u32(sQl);
    const uint32_t aKh = smem_u32(sKh), aKl = smem_u32(sKl);

    // load Q/K tiles: 128 rows x 8 segs of 16B per array
    const __nv_bfloat16* Qh = g_Qhi; const __nv_bfloat16* Ql = g_Qlo;
    const __nv_bfloat16* Kh = g_Khi; const __nv_bfloat16* Kl = g_Klo;
#pragma unroll
    for (int i = 0; i < 4; i++) {
        int f = tid + i * 256;               // 0..1023
        int row = f >> 3, seg = f & 7;
        uint32_t so = (uint32_t)(row * QPAD + seg * 8) * 2;
        size_t gq = (size_t)(b * LSEQ + bq + row) * DM + h * DK + seg * 8;
        size_t gk = (size_t)(b * LSEQ + bk + row) * DM + h * DK + seg * 8;
        cp_async16(aQh + so, Qh + gq);
        cp_async16(aQl + so, Ql + gq);
        cp_async16(aKh + so, Kh + gk);
        cp_async16(aKl + so, Kl + gk);
    }
    cp_async_wait_all();
    __syncthreads();

    float c[4][4][4];
#pragma unroll
    for (int mt = 0; mt < 4; mt++)
#pragma unroll
        for (int nt = 0; nt < 4; nt++)
#pragma unroll
            for (int r = 0; r < 4; r++) c[mt][nt][r] = 0.f;

    const int a_m_base = wm * 64 + (lane & 7) + 8 * ((lane >> 3) & 1);
    const int a_kk = 8 * (lane >> 4);
    const int b_n_base = wn * 32 + (lane & 7) + 8 * (lane >> 4);
    const int b_kk = 8 * ((lane >> 3) & 1);

#pragma unroll
    for (int kh = 0; kh < 4; kh++) {
        const int k0 = kh * 16;
        uint32_t bhf[8], blf[8];
#pragma unroll
        for (int p = 0; p < 2; p++) {
            uint32_t off = (uint32_t)((b_n_base + p * 16) * QPAD + k0 + b_kk) * 2;
            ldmx4(bhf + p * 4, aKh + off);
            ldmx4(blf + p * 4, aKl + off);
        }
#pragma unroll
        for (int mt = 0; mt < 4; mt++) {
            uint32_t ah[4], al[4];
            uint32_t off = (uint32_t)((a_m_base + mt * 16) * QPAD + k0 + a_kk) * 2;
            ldmx4(ah, aQh + off);
            ldmx4(al, aQl + off);
#pragma unroll
            for (int nt = 0; nt < 4; nt++) {
                mma_bf16(c[mt][nt], ah, bhf[nt * 2], bhf[nt * 2 + 1]);
                mma_bf16(c[mt][nt], ah, blf[nt * 2], blf[nt * 2 + 1]);
                mma_bf16(c[mt][nt], al, bhf[nt * 2], bhf[nt * 2 + 1]);
            }
        }
    }

    // epilogue: add srel lookup, scale by 1/8, store fp32
    const int r0 = lane >> 2, c0 = (lane & 3) * 2;
#pragma unroll
    for (int mt = 0; mt < 4; mt++) {
#pragma unroll
        for (int sub = 0; sub < 2; sub++) {
            int q = bq + wm * 64 + mt * 16 + r0 + sub * 8;
            const float* srel = g_Srel + ((size_t)bh * LSEQ + q) * NREL;
            float* Srow = g_S + ((size_t)bh * LSEQ + q) * LSEQ;
#pragma unroll
            for (int nt = 0; nt < 4; nt++) {
                int kk = bk + wn * 32 + nt * 8 + c0;
                int d0 = max(-16, min(16, kk - q));
                int d1 = max(-16, min(16, kk + 1 - q));
                float v0 = (c[mt][nt][sub * 2 + 0] + srel[d0 + 16]) * 0.125f;
                float v1 = (c[mt][nt][sub * 2 + 1] + srel[d1 + 16]) * 0.125f;
                *(float2*)(Srow + kk) = make_float2(v0, v1);
            }
        }
    }
}

// ---------------- attention AV via mma.sync: out = P @ V^T + Wb @ rel_v ----------------
// block: (bh, qtile 128). k loop 1024 in BK=32. N=64.
__global__ __launch_bounds__(256) void attn_av_tc(const float* __restrict__ rel_v) {
    __shared__ __align__(16) char smraw[30720];
    __nv_bfloat16* sPh = (__nv_bfloat16*)smraw;               // 128*40*2 = 10240 B
    __nv_bfloat16* sPl = (__nv_bfloat16*)(smraw + 10240);
    __nv_bfloat16* sVh = (__nv_bfloat16*)(smraw + 20480);     // 64*40*2 = 5120 B
    __nv_bfloat16* sVl = (__nv_bfloat16*)(smraw + 25600);

    const int tid = threadIdx.x;
    const int wid = tid >> 5, lane = tid & 31;
    const int wm = wid >> 1, wn = wid & 1;    // 4 x 2 warps, warp tile 32x32
    const int bh = blockIdx.z, b = bh >> 4, h = bh & 15;
    const int bq = blockIdx.y * 128;

    const uint32_t aPh = smem_u32(sPh), aPl = smem_u32(sPl);
    const uint32_t aVh = smem_u32(sVh), aVl = smem_u32(sVl);

    float c[2][4][4];
#pragma unroll
    for (int mt = 0; mt < 2; mt++)
#pragma unroll
        for (int nt = 0; nt < 4; nt++)
#pragma unroll
            for (int r = 0; r < 4; r++) c[mt][nt][r] = 0.f;

    const int a_m_base = wm * 32 + (lane & 7) + 8 * ((lane >> 3) & 1);
    const int a_kk = 8 * (lane >> 4);
    const int b_n_base = wn * 32 + (lane & 7) + 8 * (lane >> 4);
    const int b_kk = 8 * ((lane >> 3) & 1);

    const size_t prow0 = ((size_t)bh * LSEQ + bq) * LSEQ;
    const size_t vrow0 = (size_t)bh * DK * LSEQ;

    for (int t = 0; t < LSEQ / 32; t++) {
        const int kbase = t * 32;
        // P: 128 rows x 4 segs (x2 hi/lo); V: 64 rows x 4 segs (x2)
#pragma unroll
        for (int i = 0; i < 2; i++) {
            int f = tid + i * 256;
            int row = f >> 2, seg = f & 3;
            uint32_t so = (uint32_t)(row * SPAD + seg * 8) * 2;
            size_t gp = prow0 + (size_t)row * LSEQ + kbase + seg * 8;
            cp_async16(aPh + so, g_Phi + gp);
            cp_async16(aPl + so, g_Plo + gp);
        }
        {
            int row = tid >> 2, seg = tid & 3;
            uint32_t so = (uint32_t)(row * SPAD + seg * 8) * 2;
            size_t gv = vrow0 + (size_t)row * LSEQ + kbase + seg * 8;
            cp_async16(aVh + so, g_Vthi + gv);
            cp_async16(aVl + so, g_Vtlo + gv);
        }
        cp_async_wait_all();
        __syncthreads();

#pragma unroll
        for (int kh = 0; kh < 2; kh++) {
            const int k0 = kh * 16;
            uint32_t bhf[8], blf[8];
#pragma unroll
            for (int p = 0; p < 2; p++) {
                uint32_t off = (uint32_t)((b_n_base + p * 16) * SPAD + k0 + b_kk) * 2;
                ldmx4(bhf + p * 4, aVh + off);
                ldmx4(blf + p * 4, aVl + off);
            }
#pragma unroll
            for (int mt = 0; mt < 2; mt++) {
                uint32_t ah[4], al[4];
                uint32_t off = (uint32_t)((a_m_base + mt * 16) * SPAD + k0 + a_kk) * 2;
                ldmx4(ah, aPh + off);
                ldmx4(al, aPl + off);
#pragma unroll
                for (int nt = 0; nt < 4; nt++) {
                    mma_bf16(c[mt][nt], ah, bhf[nt * 2], bhf[nt * 2 + 1]);
                    mma_bf16(c[mt][nt], ah, blf[nt * 2], blf[nt * 2 + 1]);
                    mma_bf16(c[mt][nt], al, bhf[nt * 2], bhf[nt * 2 + 1]);
                }
            }
        }
        __syncthreads();
    }

    // ---- rank-33 update: reuse smem for Wl [128][33] and rv [33][64] (fp32) ----
    float* Wl = (float*)smraw;                    // 128*33*4 = 16896 B
    float* rv = (float*)(smraw + 16896);          // 33*64*4 = 8448 B
    for (int o = tid; o < 128 * NREL; o += 256) {
        int m = o / NREL, r = o % NREL;
        Wl[o] = g_Wb[((size_t)bh * LSEQ + bq + m) * NREL + r];
    }
    for (int o = tid; o < NREL * DK; o += 256) rv[o] = rel_v[o];
    __syncthreads();

    const int r0 = lane >> 2, c0 = (lane & 3) * 2;
#pragma unroll 1
    for (int r = 0; r < NREL; r++) {
        float bb[8];
#pragma unroll
        for (int nt = 0; nt < 4; nt++) {
            int d = wn * 32 + nt * 8 + c0;
            bb[nt * 2] = rv[r * DK + d];
            bb[nt * 2 + 1] = rv[r * DK + d + 1];
        }
#pragma unroll
        for (int mt = 0; mt < 2; mt++) {
            float w0 = Wl[(wm * 32 + mt * 16 + r0) * NREL + r];
            float w1 = Wl[(wm * 32 + mt * 16 + r0 + 8) * NREL + r];
#pragma unroll
            for (int nt = 0; nt < 4; nt++) {
                c[mt][nt][0] += w0 * bb[nt * 2];
                c[mt][nt][1] += w0 * bb[nt * 2 + 1];
                c[mt][nt][2] += w1 * bb[nt * 2];
                c[mt][nt][3] += w1 * bb[nt * 2 + 1];
            }
        }
    }

#pragma unroll
    for (int mt = 0; mt < 2; mt++) {
#pragma unroll
        for (int sub = 0; sub < 2; sub++) {
            int q = bq + wm * 32 + mt * 16 + r0 + sub * 8;
            float* orow = g_attn + (size_t)(b * LSEQ + q) * DM + h * DK;
#pragma unroll
            for (int nt = 0; nt < 4; nt++) {
                int d = wn * 32 + nt * 8 + c0;
                *(float2*)(orow + d) =
                    make_float2(c[mt][nt][sub * 2], c[mt][nt][sub * 2 + 1]);
            }
        }
    }
}

// ---------------- reductions ----------------
__device__ __forceinline__ float block_sum(float v, float* red) {
    int lane = threadIdx.x & 31, w = threadIdx.x >> 5;
#pragma unroll
    for (int o = 16; o; o >>= 1) v += __shfl_xor_sync(0xffffffffu, v, o);
    if (lane == 0) red[w] = v;
    __syncthreads();
    if (w == 0) {
        float t = (lane < 8) ? red[lane] : 0.f;
#pragma unroll
        for (int o = 4; o; o >>= 1) t += __shfl_xor_sync(0xffffffffu, t, o);
        if (lane == 0) red[0] = t;
    }
    __syncthreads();
    float r = red[0];
    __syncthreads();
    return r;
}
__device__ __forceinline__ float block_max(float v, float* red) {
    int lane = threadIdx.x & 31, w = threadIdx.x >> 5;
#pragma unroll
    for (int o = 16; o; o >>= 1) v = fmaxf(v, __shfl_xor_sync(0xffffffffu, v, o));
    if (lane == 0) red[w] = v;
    __syncthreads();
    if (w == 0) {
        float t = (lane < 8) ? red[lane] : -3.4e38f;
#pragma unroll
        for (int o = 4; o; o >>= 1) t = fmaxf(t, __shfl_xor_sync(0xffffffffu, t, o));
        if (lane == 0) red[0] = t;
    }
    __syncthreads();
    float r = red[0];
    __syncthreads();
    return r;
}

// ---------------- S_rel[b,h,q,r] = Qh[b,q,h,:] . rel_k[r,:] ----------------
__global__ void srel_kernel(const float* __restrict__ rel_k) {
    int blk = blockIdx.x;
    int b = blk >> 10, q = blk & 1023;
    __shared__ float qrow[DM];
    __shared__ float rk[NREL * 65];
    int tid = threadIdx.x;
    *(float4*)(qrow + tid * 4) = *(const float4*)(g_Q + (size_t)blk * DM + tid * 4);
    for (int o = tid; o < NREL * DK; o += 256) {
        int r = o >> 6, d = o & 63;
        rk[r * 65 + d] = rel_k[o];
    }
    __syncthreads();
    for (int o = tid; o < NH * NREL; o += 256) {
        int h = o / NREL, r = o % NREL;
        float acc = 0.f;
#pragma unroll
        for (int d = 0; d < DK; d++) acc += qrow[h * DK + d] * rk[r * 65 + d];
        g_Srel[(((size_t)(b * NH + h)) * LSEQ + q) * NREL + r] = acc;
    }
}

// ---------------- softmax rows + bucket sums; emits P as bf16 hi/lo ----------------
__global__ void softmax_bucket() {
    int row = blockIdx.x;
    int q = row & (LSEQ - 1);
    float* Sr = g_S + (size_t)row * LSEQ;
    int tid = threadIdx.x;
    __shared__ float sp[LSEQ];
    __shared__ float red[32];
    float4 v = *(float4*)(Sr + tid * 4);
    float m = fmaxf(fmaxf(v.x, v.y), fmaxf(v.z, v.w));
    m = block_max(m, red);
    float e0 = __expf(v.x - m), e1 = __expf(v.y - m);
    float e2 = __expf(v.z - m), e3 = __expf(v.w - m);
    float s = block_sum(e0 + e1 + e2 + e3, red);
    float inv = 1.f / s;
    float pv[4] = {e0 * inv, e1 * inv, e2 * inv, e3 * inv};
    int k0 = tid * 4;
    sp[k0] = pv[0]; sp[k0 + 1] = pv[1]; sp[k0 + 2] = pv[2]; sp[k0 + 3] = pv[3];
    __nv_bfloat16 ph[4], pl[4];
#pragma unroll
    for (int u = 0; u < 4; u++) {
        ph[u] = __float2bfloat16(pv[u]);
        pl[u] = __float2bfloat16(pv[u] - __bfloat162float(ph[u]));
    }
    *(uint2*)(g_Phi + (size_t)row * LSEQ + k0) = *(uint2*)ph;
    *(uint2*)(g_Plo + (size_t)row * LSEQ + k0) = *(uint2*)pl;
    float lo = 0.f, hi = 0.f;
#pragma unroll
    for (int u = 0; u < 4; u++) {
        int k = k0 + u;
        if (k <= q - 16) lo += pv[u];
        if (k >= q + 16) hi += pv[u];
    }
    lo = block_sum(lo, red);
    hi = block_sum(hi, red);
    float* Wr = g_Wb + (size_t)row * NREL;
    if (tid == 0) { Wr[0] = lo; Wr[32] = hi; }
    if (tid < 31) {
        int r = tid + 1;
        int k = q + r - 16;
        Wr[r] = (k >= 0 && k < LSEQ) ? sp[k] : 0.f;
    }
}

// ---------------- layernorm ----------------
__global__ void layernorm_k(const float* __restrict__ X, const float* __restrict__ Res,
                            const float* __restrict__ gam, const float* __restrict__ bet,
                            float* __restrict__ O) {
    int row = blockIdx.x, tid = threadIdx.x;
    __shared__ float red[32];
    float4 v = *(const float4*)(X + (size_t)row * DM + tid * 4);
    if (Res) {
        float4 rr = *(const float4*)(Res + (size_t)row * DM + tid * 4);
        v.x += rr.x; v.y += rr.y; v.z += rr.z; v.w += rr.w;
    }
    float s = block_sum(v.x + v.y + v.z + v.w, red);
    float s2 = block_sum(v.x * v.x + v.y * v.y + v.z * v.z + v.w * v.w, red);
    float mu = s * (1.f / DM);
    float var = s2 * (1.f / DM) - mu * mu;
    float rstd = rsqrtf(var + 1e-6f);
    float4 g4 = *(const float4*)(gam + tid * 4);
    float4 b4 = *(const float4*)(bet + tid * 4);
    float4 o;
    o.x = (v.x - mu) * rstd * g4.x + b4.x;
    o.y = (v.y - mu) * rstd * g4.y + b4.y;
    o.z = (v.z - mu) * rstd * g4.z + b4.z;
    o.w = (v.w - mu) * rstd * g4.w + b4.w;
    *(float4*)(O + (size_t)row * DM + tid * 4) = o;
}

// ---------------- launch ----------------
static void* sym_addr(const void* s) { void* p = nullptr; cudaGetSymbolAddress(&p, s); return p; }

#define SCORES_SMEM (4 * 128 * QPAD * 2)

extern "C" void kernel_launch(void* const* d_in, const int* in_sizes, int n_in,
                              void* d_out, int out_size) {
    const float* q    = (const float*)d_in[0];
    const float* k    = (const float*)d_in[1];
    const float* v    = (const float*)d_in[2];
    const float* wq   = (const float*)d_in[3];
    const float* bq   = (const float*)d_in[4];
    const float* wk   = (const float*)d_in[5];
    const float* bk   = (const float*)d_in[6];
    const float* wv   = (const float*)d_in[7];
    const float* bv   = (const float*)d_in[8];
    const float* wfc  = (const float*)d_in[9];
    const float* bfc  = (const float*)d_in[10];
    const float* w1   = (const float*)d_in[11];
    const float* b1   = (const float*)d_in[12];
    const float* w2   = (const float*)d_in[13];
    const float* b2   = (const float*)d_in[14];
    const float* ln_g = (const float*)d_in[15];
    const float* ln_b = (const float*)d_in[16];
    const float* relk = (const float*)d_in[17];
    const float* relv = (const float*)d_in[18];
    float* out = (float*)d_out;

    float* pQ    = (float*)sym_addr(g_Q);
    float* pK    = (float*)sym_addr(g_K);
    float* pV    = (float*)sym_addr(g_V);
    float* pAttn = (float*)sym_addr(g_attn);
    float* pTmp  = (float*)sym_addr(g_tmp);
    float* pLn1  = (float*)sym_addr(g_ln1);
    float* pH1   = (float*)sym_addr(g_h1);
    float* pT2   = (float*)sym_addr(g_t2);
    __nv_bfloat16* pAhi = (__nv_bfloat16*)sym_addr(g_Ahi);
    __nv_bfloat16* pAlo = (__nv_bfloat16*)sym_addr(g_Alo);
    __nv_bfloat16* pWhi = (__nv_bfloat16*)sym_addr(g_Whi);
    __nv_bfloat16* pWlo = (__nv_bfloat16*)sym_addr(g_Wlo);
    __nv_bfloat16* pQhi = (__nv_bfloat16*)sym_addr(g_Qhi);
    __nv_bfloat16* pQlo = (__nv_bfloat16*)sym_addr(g_Qlo);
    __nv_bfloat16* pKhi = (__nv_bfloat16*)sym_addr(g_Khi);
    __nv_bfloat16* pKlo = (__nv_bfloat16*)sym_addr(g_Klo);
    __nv_bfloat16* pVthi = (__nv_bfloat16*)sym_addr(g_Vthi);
    __nv_bfloat16* pVtlo = (__nv_bfloat16*)sym_addr(g_Vtlo);

    cudaFuncSetAttribute(attn_scores_tc, cudaFuncAttributeMaxDynamicSharedMemorySize, SCORES_SMEM);

    const int nD4 = ROWS * DM / 4 / 256;
    const int nI4 = ROWS * DI / 4 / 256;
    dim3 tBlk(32, 8);
    dim3 tGridD(DM / 32, DM / 32);
    dim3 tGridW1(DI / 32, DM / 32);
    dim3 tGridW2(DM / 32, DI / 32);
    dim3 gD(DM / 128, ROWS / 128);
    dim3 gI(DI / 128, ROWS / 128);

    // QKV projections
    conv_split_T<<<tGridD, tBlk>>>(wq, pWhi, pWlo, DM, DM);
    conv_split<<<nD4, 256>>>(q, pAhi, pAlo);
    gemm_tc<<<gD, 256>>>(pAhi, pAlo, pWhi, pWlo, bq, pQ, ROWS, DM, DM, 0);

    conv_split_T<<<tGridD, tBlk>>>(wk, pWhi, pWlo, DM, DM);
    conv_split<<<nD4, 256>>>(k, pAhi, pAlo);
    gemm_tc<<<gD, 256>>>(pAhi, pAlo, pWhi, pWlo, bk, pK, ROWS, DM, DM, 0);

    conv_split_T<<<tGridD, tBlk>>>(wv, pWhi, pWlo, DM, DM);
    conv_split<<<nD4, 256>>>(v, pAhi, pAlo);
    gemm_tc<<<gD, 256>>>(pAhi, pAlo, pWhi, pWlo, bv, pV, ROWS, DM, DM, 0);

    // attention: splits + srel + scores(MMA) + softmax + AV(MMA)
    conv_split<<<nD4, 256>>>(pQ, pQhi, pQlo);
    conv_split<<<nD4, 256>>>(pK, pKhi, pKlo);
    dim3 gvt(LSEQ / 32, DK / 32, BHN);
    vt_split<<<gvt, tBlk>>>(pV, pVthi, pVtlo);

    srel_kernel<<<ROWS, 256>>>(relk);

    dim3 gs(LSEQ / 128, LSEQ / 128, BHN);
    attn_scores_tc<<<gs, 256, SCORES_SMEM>>>();

    softmax_bucket<<<BHN * LSEQ, 256>>>();

    dim3 gav(1, LSEQ / 128, BHN);
    attn_av_tc<<<gav, 256>>>(relv);

    // out-proj + LN1
    conv_split_T<<<tGridD, tBlk>>>(wfc, pWhi, pWlo, DM, DM);
    conv_split<<<nD4, 256>>>(pAttn, pAhi, pAlo);
    gemm_tc<<<gD, 256>>>(pAhi, pAlo, pWhi, pWlo, bfc, pTmp, ROWS, DM, DM, 0);
    layernorm_k<<<ROWS, 256>>>(pTmp, q, ln_g, ln_b, pLn1);

    // FFN
    conv_split_T<<<tGridW1, tBlk>>>(w1, pWhi, pWlo, DM, DI);
    conv_split<<<nD4, 256>>>(pLn1, pAhi, pAlo);
    gemm_tc<<<gI, 256>>>(pAhi, pAlo, pWhi, pWlo, b1, pH1, ROWS, DI, DM, 1);

    conv_split_T<<<tGridW2, tBlk>>>(w2, pWhi, pWlo, DI, DM);
    conv_split<<<nI4, 256>>>(pH1, pAhi, pAlo);
    gemm_tc<<<gD, 256>>>(pAhi, pAlo, pWhi, pWlo, b2, pT2, ROWS, DM, DI, 0);
    layernorm_k<<<ROWS, 256>>>(pT2, pLn1, ln_g, ln_b, out);
}

// round 6
// speedup vs baseline: 3.3024x; 1.0586x over previous
#include <cuda_runtime.h>
#include <cuda_bf16.h>
#include <cstdint>

#define LSEQ 1024
#define DM   1024
#define BATCH 8
#define NH   16
#define DK   64
#define BHN  (BATCH*NH)     // 128
#define NREL 33
#define DI   4096
#define ROWS (BATCH*LSEQ)   // 8192

// ---------------- scratch (static device arrays; no allocation) ----------------
__device__ float g_Q[ROWS*DM];
__device__ float g_K[ROWS*DM];
__device__ float g_V[ROWS*DM];
__device__ float g_Srel[(size_t)BHN*LSEQ*NREL];
__device__ float g_attn[ROWS*DM];
__device__ float g_tmp[ROWS*DM];
__device__ float g_ln1[ROWS*DM];
__device__ float g_h1[(size_t)ROWS*DI];
__device__ float g_t2[ROWS*DM];
// bf16 split buffers (GEMM path)
__device__ __nv_bfloat16 g_Ahi[(size_t)ROWS*DI];
__device__ __nv_bfloat16 g_Alo[(size_t)ROWS*DI];
__device__ __nv_bfloat16 g_Whi[(size_t)DM*DI];
__device__ __nv_bfloat16 g_Wlo[(size_t)DM*DI];
// bf16 split buffers (attention path)
__device__ __nv_bfloat16 g_Qhi[ROWS*DM];
__device__ __nv_bfloat16 g_Qlo[ROWS*DM];
__device__ __nv_bfloat16 g_Khi[ROWS*DM];
__device__ __nv_bfloat16 g_Klo[ROWS*DM];
__device__ __nv_bfloat16 g_Vthi[(size_t)BHN*DK*LSEQ];   // [bh][d][k]
__device__ __nv_bfloat16 g_Vtlo[(size_t)BHN*DK*LSEQ];

// ---------------- helpers ----------------
__device__ __forceinline__ uint32_t smem_u32(const void* p) {
    uint32_t a;
    asm("{ .reg .u64 t; cvta.to.shared.u64 t, %1; cvt.u32.u64 %0, t; }" : "=r"(a) : "l"(p));
    return a;
}
__device__ __forceinline__ void cp_async16(uint32_t saddr, const void* gaddr) {
    asm volatile("cp.async.cg.shared.global [%0], [%1], 16;" :: "r"(saddr), "l"(gaddr));
}
__device__ __forceinline__ void cp_async_wait_all() {
    asm volatile("cp.async.commit_group;\ncp.async.wait_group 0;" ::: "memory");
}
__device__ __forceinline__ void ldmx4(uint32_t* r, uint32_t addr) {
    asm volatile("ldmatrix.sync.aligned.m8n8.x4.shared.b16 {%0,%1,%2,%3}, [%4];"
        : "=r"(r[0]), "=r"(r[1]), "=r"(r[2]), "=r"(r[3]) : "r"(addr));
}
__device__ __forceinline__ void mma_bf16(float* c, const uint32_t* a, uint32_t b0, uint32_t b1) {
    asm volatile(
        "mma.sync.aligned.m16n8k16.row.col.f32.bf16.bf16.f32 "
        "{%0,%1,%2,%3}, {%4,%5,%6,%7}, {%8,%9}, {%0,%1,%2,%3};"
        : "+f"(c[0]), "+f"(c[1]), "+f"(c[2]), "+f"(c[3])
        : "r"(a[0]), "r"(a[1]), "r"(a[2]), "r"(a[3]), "r"(b0), "r"(b1));
}
__device__ __forceinline__ uint32_t pkbf2(__nv_bfloat16 lo, __nv_bfloat16 hi) {
    __nv_bfloat162 t(lo, hi);
    return *(uint32_t*)&t;
}

// ---------------- split conversion kernels ----------------
__global__ void conv_split(const float* __restrict__ X, __nv_bfloat16* __restrict__ hi,
                           __nv_bfloat16* __restrict__ lo) {
    int i = blockIdx.x * blockDim.x + threadIdx.x;       // per float4
    float4 v = ((const float4*)X)[i];
    __nv_bfloat16 h[4], l[4];
    float xs[4] = {v.x, v.y, v.z, v.w};
#pragma unroll
    for (int j = 0; j < 4; j++) {
        h[j] = __float2bfloat16(xs[j]);
        l[j] = __float2bfloat16(xs[j] - __bfloat162float(h[j]));
    }
    *(uint2*)(hi + (size_t)i * 4) = *(uint2*)h;
    *(uint2*)(lo + (size_t)i * 4) = *(uint2*)l;
}

// W[K,N] -> hiT/loT [N,K]
__global__ void conv_split_T(const float* __restrict__ W, __nv_bfloat16* __restrict__ hiT,
                             __nv_bfloat16* __restrict__ loT, int K, int N) {
    __shared__ float t[32][33];
    int n0 = blockIdx.x * 32, k0 = blockIdx.y * 32;
    int tx = threadIdx.x, ty = threadIdx.y;
    for (int i = ty; i < 32; i += 8)
        t[i][tx] = W[(size_t)(k0 + i) * N + n0 + tx];
    __syncthreads();
    for (int r = ty; r < 32; r += 8) {
        float x = t[tx][r];
        __nv_bfloat16 h = __float2bfloat16(x);
        __nv_bfloat16 l = __float2bfloat16(x - __bfloat162float(h));
        size_t o = (size_t)(n0 + r) * K + k0 + tx;
        hiT[o] = h;
        loT[o] = l;
    }
}

// V [b*L+k][h*64+d] -> Vt [bh][d][k] (hi/lo split)
__global__ void vt_split(const float* __restrict__ V, __nv_bfloat16* __restrict__ hiT,
                         __nv_bfloat16* __restrict__ loT) {
    __shared__ float t[32][33];
    int bh = blockIdx.z, b = bh >> 4, h = bh & 15;
    int k0 = blockIdx.x * 32, d0 = blockIdx.y * 32;
    int tx = threadIdx.x, ty = threadIdx.y;
    for (int i = ty; i < 32; i += 8)
        t[i][tx] = V[(size_t)(b * LSEQ + k0 + i) * DM + h * DK + d0 + tx];
    __syncthreads();
    for (int r = ty; r < 32; r += 8) {
        float x = t[tx][r];
        __nv_bfloat16 hh = __float2bfloat16(x);
        __nv_bfloat16 ll = __float2bfloat16(x - __bfloat162float(hh));
        size_t o = ((size_t)bh * DK + d0 + r) * LSEQ + k0 + tx;
        hiT[o] = hh;
        loT[o] = ll;
    }
}

// ---------------- bf16x3 mma.sync GEMM (unchanged, known-good) ----------------
#define SPAD 40
__global__ __launch_bounds__(256, 2) void gemm_tc(
    const __nv_bfloat16* __restrict__ Ahi, const __nv_bfloat16* __restrict__ Alo,
    const __nv_bfloat16* __restrict__ Bhi, const __nv_bfloat16* __restrict__ Blo,
    const float* __restrict__ bias, float* __restrict__ C,
    int M, int N, int K, int relu)
{
    __shared__ __nv_bfloat16 sAh[128 * SPAD];
    __shared__ __nv_bfloat16 sAl[128 * SPAD];
    __shared__ __nv_bfloat16 sBh[128 * SPAD];
    __shared__ __nv_bfloat16 sBl[128 * SPAD];

    const int tid = threadIdx.x;
    const int wid = tid >> 5, lane = tid & 31;
    const int wm = wid >> 2, wn = wid & 3;
    const int bm = blockIdx.y * 128, bn = blockIdx.x * 128;

    const uint32_t aAh = smem_u32(sAh), aAl = smem_u32(sAl);
    const uint32_t aBh = smem_u32(sBh), aBl = smem_u32(sBl);

    float c[4][4][4];
#pragma unroll
    for (int mt = 0; mt < 4; mt++)
#pragma unroll
        for (int nt = 0; nt < 4; nt++)
#pragma unroll
            for (int r = 0; r < 4; r++) c[mt][nt][r] = 0.f;

    const int a_m_base = wm * 64 + (lane & 7) + 8 * ((lane >> 3) & 1);
    const int a_kk = 8 * (lane >> 4);
    const int b_n_base = wn * 32 + (lane & 7) + 8 * (lane >> 4);
    const int b_kk = 8 * ((lane >> 3) & 1);

    const int ktiles = K >> 5;
    for (int t = 0; t < ktiles; t++) {
        const int kbase = t * 32;
#pragma unroll
        for (int i = 0; i < 2; i++) {
            int f = tid + i * 256;
            int row = f >> 2, seg = f & 3;
            uint32_t so = (uint32_t)(row * SPAD + seg * 8) * 2;
            size_t ga = (size_t)(bm + row) * K + kbase + seg * 8;
            size_t gb = (size_t)(bn + row) * K + kbase + seg * 8;
            cp_async16(aAh + so, Ahi + ga);
            cp_async16(aAl + so, Alo + ga);
            cp_async16(aBh + so, Bhi + gb);
            cp_async16(aBl + so, Blo + gb);
        }
        cp_async_wait_all();
        __syncthreads();

#pragma unroll
        for (int kh = 0; kh < 2; kh++) {
            const int k0 = kh * 16;
            uint32_t bh[8], bl[8];
#pragma unroll
            for (int p = 0; p < 2; p++) {
                uint32_t off = (uint32_t)((b_n_base + p * 16) * SPAD + k0 + b_kk) * 2;
                ldmx4(bh + p * 4, aBh + off);
                ldmx4(bl + p * 4, aBl + off);
            }
#pragma unroll
            for (int mt = 0; mt < 4; mt++) {
                uint32_t ah[4], al[4];
                uint32_t off = (uint32_t)((a_m_base + mt * 16) * SPAD + k0 + a_kk) * 2;
                ldmx4(ah, aAh + off);
                ldmx4(al, aAl + off);
#pragma unroll
                for (int nt = 0; nt < 4; nt++) {
                    mma_bf16(c[mt][nt], ah, bh[nt * 2], bh[nt * 2 + 1]);
                    mma_bf16(c[mt][nt], ah, bl[nt * 2], bl[nt * 2 + 1]);
                    mma_bf16(c[mt][nt], al, bh[nt * 2], bh[nt * 2 + 1]);
                }
            }
        }
        __syncthreads();
    }

    const int r0 = lane >> 2, c0 = (lane & 3) * 2;
#pragma unroll
    for (int mt = 0; mt < 4; mt++) {
        int row = bm + wm * 64 + mt * 16 + r0;
#pragma unroll
        for (int nt = 0; nt < 4; nt++) {
            int col = bn + wn * 32 + nt * 8 + c0;
            float b0v = bias[col], b1v = bias[col + 1];
            float v0 = c[mt][nt][0] + b0v, v1 = c[mt][nt][1] + b1v;
            float v2 = c[mt][nt][2] + b0v, v3 = c[mt][nt][3] + b1v;
            if (relu) {
                v0 = fmaxf(v0, 0.f); v1 = fmaxf(v1, 0.f);
                v2 = fmaxf(v2, 0.f); v3 = fmaxf(v3, 0.f);
            }
            *(float2*)(C + (size_t)row * N + col) = make_float2(v0, v1);
            *(float2*)(C + (size_t)(row + 8) * N + col) = make_float2(v2, v3);
        }
    }
}

// ---------------- fused flash attention (scores + softmax + buckets + AV) ----------------
// grid (8 qtiles, 128 bh), 256 threads = 8 warps; warp w owns q rows [w*16, w*16+16).
#define QP 72
#define VP 136
// dynamic smem offsets (bytes)
#define OFF_QH 0
#define OFF_QL 18432
#define OFF_KH 36864
#define OFF_KL 55296
#define OFF_VH 73728
#define OFF_VL 91136
#define OFF_WB 108544
#define OFF_SR 125952
#define OFF_F  143360
#define FLASH_SMEM 143872

__global__ __launch_bounds__(256, 1) void flash_attn(const float* __restrict__ rel_v) {
    extern __shared__ char fsm[];
    float* sWb = (float*)(fsm + OFF_WB);    // [128][34]
    float* sSr = (float*)(fsm + OFF_SR);    // [128][34]
    float* sF  = (float*)(fsm + OFF_F);     // [128]

    const int tid = threadIdx.x;
    const int wid = tid >> 5, lane = tid & 31;
    const int bh = blockIdx.y, b = bh >> 4, h = bh & 15;
    const int bq = blockIdx.x * 128;

    const uint32_t aQh = smem_u32(fsm + OFF_QH), aQl = smem_u32(fsm + OFF_QL);
    const uint32_t aKh = smem_u32(fsm + OFF_KH), aKl = smem_u32(fsm + OFF_KL);
    const uint32_t aVh = smem_u32(fsm + OFF_VH), aVl = smem_u32(fsm + OFF_VL);

    // ---- load Q tile + srel rows + zero Wb ----
#pragma unroll
    for (int i = 0; i < 4; i++) {
        int f = tid + i * 256;               // 1024 = 128 rows x 8 segs
        int row = f >> 3, seg = f & 7;
        uint32_t so = (uint32_t)(row * QP + seg * 8) * 2;
        size_t gq = (size_t)(b * LSEQ + bq + row) * DM + h * DK + seg * 8;
        cp_async16(aQh + so, g_Qhi + gq);
        cp_async16(aQl + so, g_Qlo + gq);
    }
    for (int o = tid; o < 128 * NREL; o += 256) {
        int r = o / NREL, cc = o % NREL;
        sSr[r * 34 + cc] = g_Srel[((size_t)bh * LSEQ + bq + r) * NREL + cc];
    }
    for (int o = tid; o < 128 * 34; o += 256) sWb[o] = 0.f;
    cp_async_wait_all();
    __syncthreads();

    // fragment bases
    const int a_row = wid * 16 + (lane & 7) + 8 * ((lane >> 3) & 1);
    const int a_kk = 8 * (lane >> 4);
    const int b_row = (lane & 7) + 8 * (lane >> 4);
    const int b_kk = 8 * ((lane >> 3) & 1);
    const int r0 = lane >> 2, c0 = (lane & 3) * 2;
    const int qrow0 = wid * 16 + r0;         // local row (rr=0); rr=1 -> +8
    const int q0 = bq + qrow0;

    float m0 = -1e30f, m1 = -1e30f, l0 = 0.f, l1 = 0.f;
    float O[8][4];
#pragma unroll
    for (int nt = 0; nt < 8; nt++)
#pragma unroll
        for (int j = 0; j < 4; j++) O[nt][j] = 0.f;

    for (int kt = 0; kt < 8; kt++) {
        const int k0 = kt * 128;
        // ---- load K tile (128x64) and Vt tile (64x128) hi/lo ----
#pragma unroll
        for (int i = 0; i < 4; i++) {
            int f = tid + i * 256;
            int row = f >> 3, seg = f & 7;
            uint32_t so = (uint32_t)(row * QP + seg * 8) * 2;
            size_t gk = (size_t)(b * LSEQ + k0 + row) * DM + h * DK + seg * 8;
            cp_async16(aKh + so, g_Khi + gk);
            cp_async16(aKl + so, g_Klo + gk);
        }
#pragma unroll
        for (int i = 0; i < 4; i++) {
            int f = tid + i * 256;
            int row = f >> 4, seg = f & 15;   // 64 rows x 16 segs
            uint32_t so = (uint32_t)(row * VP + seg * 8) * 2;
            size_t gv = ((size_t)bh * DK + row) * LSEQ + k0 + seg * 8;
            cp_async16(aVh + so, g_Vthi + gv);
            cp_async16(aVl + so, g_Vtlo + gv);
        }
        cp_async_wait_all();
        __syncthreads();

        // ---- S tile = Q K^T (bf16x3), warp computes 16x128 ----
        float c[16][4];
#pragma unroll
        for (int nt = 0; nt < 16; nt++)
#pragma unroll
            for (int j = 0; j < 4; j++) c[nt][j] = 0.f;

#pragma unroll
        for (int ks = 0; ks < 4; ks++) {
            uint32_t ah[4], al[4];
            uint32_t aoff = (uint32_t)(a_row * QP + ks * 16 + a_kk) * 2;
            ldmx4(ah, aQh + aoff);
            ldmx4(al, aQl + aoff);
#pragma unroll
            for (int hh = 0; hh < 2; hh++) {
                uint32_t bhf[16], blf[16];
#pragma unroll
                for (int p = 0; p < 4; p++) {
                    uint32_t boff = (uint32_t)((b_row + hh * 64 + p * 16) * QP + ks * 16 + b_kk) * 2;
                    ldmx4(bhf + p * 4, aKh + boff);
                    ldmx4(blf + p * 4, aKl + boff);
                }
#pragma unroll
                for (int nt = 0; nt < 8; nt++) {
                    float* cc = c[hh * 8 + nt];
                    mma_bf16(cc, ah, bhf[nt * 2], bhf[nt * 2 + 1]);
                    mma_bf16(cc, ah, blf[nt * 2], blf[nt * 2 + 1]);
                    mma_bf16(cc, al, bhf[nt * 2], bhf[nt * 2 + 1]);
                }
            }
        }

        // ---- srel add + scale; row max ----
        float tm0 = -1e30f, tm1 = -1e30f;
#pragma unroll
        for (int nt = 0; nt < 16; nt++) {
            int kA = k0 + nt * 8 + c0;
#pragma unroll
            for (int j = 0; j < 4; j++) {
                int kk = kA + (j & 1);
                bool low = (j < 2);
                int q = low ? q0 : q0 + 8;
                int lrow = low ? qrow0 : qrow0 + 8;
                int d = kk - q; d = max(-16, min(16, d));
                float s = (c[nt][j] + sSr[lrow * 34 + d + 16]) * 0.125f;
                c[nt][j] = s;
                if (low) tm0 = fmaxf(tm0, s); else tm1 = fmaxf(tm1, s);
            }
        }
        tm0 = fmaxf(tm0, __shfl_xor_sync(0xffffffffu, tm0, 1));
        tm0 = fmaxf(tm0, __shfl_xor_sync(0xffffffffu, tm0, 2));
        tm1 = fmaxf(tm1, __shfl_xor_sync(0xffffffffu, tm1, 1));
        tm1 = fmaxf(tm1, __shfl_xor_sync(0xffffffffu, tm1, 2));
        float nm0 = fmaxf(m0, tm0), nm1 = fmaxf(m1, tm1);
        float f0 = __expf(m0 - nm0), f1 = __expf(m1 - nm1);
        m0 = nm0; m1 = nm1;
        if ((lane & 3) == 0) { sF[qrow0] = f0; sF[qrow0 + 8] = f1; }
        __syncwarp();
        // rescale this warp's Wb rows
        for (int o = lane; o < 16 * 33; o += 32) {
            int rr = o / 33, cc2 = o % 33;
            sWb[(wid * 16 + rr) * 34 + cc2] *= sF[wid * 16 + rr];
        }
        __syncwarp();

        // ---- exponentiate; accumulate l and buckets ----
        float sum0 = 0.f, sum1 = 0.f, lo0 = 0.f, lo1 = 0.f, hi0 = 0.f, hi1 = 0.f;
#pragma unroll
        for (int nt = 0; nt < 16; nt++) {
#pragma unroll
            for (int j = 0; j < 4; j++) {
                int kk = k0 + nt * 8 + c0 + (j & 1);
                bool low = (j < 2);
                float p = __expf(c[nt][j] - (low ? nm0 : nm1));
                c[nt][j] = p;
                int q = low ? q0 : q0 + 8;
                int d = kk - q;
                if (low) sum0 += p; else sum1 += p;
                if (d <= -16) { if (low) lo0 += p; else lo1 += p; }
                else if (d >= 16) { if (low) hi0 += p; else hi1 += p; }
                else sWb[(low ? qrow0 : qrow0 + 8) * 34 + d + 16] += p;
            }
        }
        sum0 += __shfl_xor_sync(0xffffffffu, sum0, 1);
        sum0 += __shfl_xor_sync(0xffffffffu, sum0, 2);
        sum1 += __shfl_xor_sync(0xffffffffu, sum1, 1);
        sum1 += __shfl_xor_sync(0xffffffffu, sum1, 2);
        lo0 += __shfl_xor_sync(0xffffffffu, lo0, 1);
        lo0 += __shfl_xor_sync(0xffffffffu, lo0, 2);
        lo1 += __shfl_xor_sync(0xffffffffu, lo1, 1);
        lo1 += __shfl_xor_sync(0xffffffffu, lo1, 2);
        hi0 += __shfl_xor_sync(0xffffffffu, hi0, 1);
        hi0 += __shfl_xor_sync(0xffffffffu, hi0, 2);
        hi1 += __shfl_xor_sync(0xffffffffu, hi1, 1);
        hi1 += __shfl_xor_sync(0xffffffffu, hi1, 2);
        l0 = l0 * f0 + sum0;
        l1 = l1 * f1 + sum1;
        if ((lane & 3) == 0) {
            sWb[qrow0 * 34 + 0] += lo0;  sWb[qrow0 * 34 + 32] += hi0;
            sWb[(qrow0 + 8) * 34 + 0] += lo1;  sWb[(qrow0 + 8) * 34 + 32] += hi1;
        }
        // rescale O
#pragma unroll
        for (int nt = 0; nt < 8; nt++) {
            O[nt][0] *= f0; O[nt][1] *= f0; O[nt][2] *= f1; O[nt][3] *= f1;
        }

        // ---- PV: pack P from C regs (hi + lo residual), MMA against Vt ----
#pragma unroll
        for (int j = 0; j < 8; j++) {
            float x0 = c[2 * j][0], x1 = c[2 * j][1], x2 = c[2 * j][2], x3 = c[2 * j][3];
            float y0 = c[2 * j + 1][0], y1 = c[2 * j + 1][1], y2 = c[2 * j + 1][2], y3 = c[2 * j + 1][3];
            __nv_bfloat16 hx0 = __float2bfloat16(x0), hx1 = __float2bfloat16(x1);
            __nv_bfloat16 hx2 = __float2bfloat16(x2), hx3 = __float2bfloat16(x3);
            __nv_bfloat16 hy0 = __float2bfloat16(y0), hy1 = __float2bfloat16(y1);
            __nv_bfloat16 hy2 = __float2bfloat16(y2), hy3 = __float2bfloat16(y3);
            uint32_t pa[4], pl[4];
            pa[0] = pkbf2(hx0, hx1); pa[1] = pkbf2(hx2, hx3);
            pa[2] = pkbf2(hy0, hy1); pa[3] = pkbf2(hy2, hy3);
            pl[0] = pkbf2(__float2bfloat16(x0 - __bfloat162float(hx0)),
                          __float2bfloat16(x1 - __bfloat162float(hx1)));
            pl[1] = pkbf2(__float2bfloat16(x2 - __bfloat162float(hx2)),
                          __float2bfloat16(x3 - __bfloat162float(hx3)));
            pl[2] = pkbf2(__float2bfloat16(y0 - __bfloat162float(hy0)),
                          __float2bfloat16(y1 - __bfloat162float(hy1)));
            pl[3] = pkbf2(__float2bfloat16(y2 - __bfloat162float(hy2)),
                          __float2bfloat16(y3 - __bfloat162float(hy3)));
            uint32_t vh[16], vl[16];
#pragma unroll
            for (int p = 0; p < 4; p++) {
                uint32_t voff = (uint32_t)((b_row + p * 16) * VP + j * 16 + b_kk) * 2;
                ldmx4(vh + p * 4, aVh + voff);
                ldmx4(vl + p * 4, aVl + voff);
            }
#pragma unroll
            for (int nt = 0; nt < 8; nt++) {
                mma_bf16(O[nt], pa, vh[nt * 2], vh[nt * 2 + 1]);
                mma_bf16(O[nt], pa, vl[nt * 2], vl[nt * 2 + 1]);
                mma_bf16(O[nt], pl, vh[nt * 2], vh[nt * 2 + 1]);
            }
        }
        __syncthreads();
    }

    // ---- epilogue: rank-33 rel_v update, normalize, store ----
    float* rv = (float*)(fsm + OFF_KH);      // reuse K region: 33*64 fp32
    for (int o = tid; o < NREL * DK; o += 256) rv[o] = rel_v[o];
    __syncthreads();

#pragma unroll 1
    for (int r = 0; r < NREL; r++) {
        float wb0 = sWb[qrow0 * 34 + r];
        float wb1 = sWb[(qrow0 + 8) * 34 + r];
#pragma unroll
        for (int nt = 0; nt < 8; nt++) {
            int d = nt * 8 + c0;
            float rv0 = rv[r * DK + d], rv1 = rv[r * DK + d + 1];
            O[nt][0] += wb0 * rv0; O[nt][1] += wb0 * rv1;
            O[nt][2] += wb1 * rv0; O[nt][3] += wb1 * rv1;
        }
    }
    float inv0 = 1.f / l0, inv1 = 1.f / l1;
    float* orow0 = g_attn + (size_t)(b * LSEQ + q0) * DM + h * DK;
    float* orow1 = g_attn + (size_t)(b * LSEQ + q0 + 8) * DM + h * DK;
#pragma unroll
    for (int nt = 0; nt < 8; nt++) {
        int d = nt * 8 + c0;
        *(float2*)(orow0 + d) = make_float2(O[nt][0] * inv0, O[nt][1] * inv0);
        *(float2*)(orow1 + d) = make_float2(O[nt][2] * inv1, O[nt][3] * inv1);
    }
}

// ---------------- reductions (for layernorm) ----------------
__device__ __forceinline__ float block_sum(float v, float* red) {
    int lane = threadIdx.x & 31, w = threadIdx.x >> 5;
#pragma unroll
    for (int o = 16; o; o >>= 1) v += __shfl_xor_sync(0xffffffffu, v, o);
    if (lane == 0) red[w] = v;
    __syncthreads();
    if (w == 0) {
        float t = (lane < 8) ? red[lane] : 0.f;
#pragma unroll
        for (int o = 4; o; o >>= 1) t += __shfl_xor_sync(0xffffffffu, t, o);
        if (lane == 0) red[0] = t;
    }
    __syncthreads();
    float r = red[0];
    __syncthreads();
    return r;
}

// ---------------- S_rel[b,h,q,r] = Qh[b,q,h,:] . rel_k[r,:] ----------------
__global__ void srel_kernel(const float* __restrict__ rel_k) {
    int blk = blockIdx.x;
    int b = blk >> 10, q = blk & 1023;
    __shared__ float qrow[DM];
    __shared__ float rk[NREL * 65];
    int tid = threadIdx.x;
    *(float4*)(qrow + tid * 4) = *(const float4*)(g_Q + (size_t)blk * DM + tid * 4);
    for (int o = tid; o < NREL * DK; o += 256) {
        int r = o >> 6, d = o & 63;
        rk[r * 65 + d] = rel_k[o];
    }
    __syncthreads();
    for (int o = tid; o < NH * NREL; o += 256) {
        int h = o / NREL, r = o % NREL;
        float acc = 0.f;
#pragma unroll
        for (int d = 0; d < DK; d++) acc += qrow[h * DK + d] * rk[r * 65 + d];
        g_Srel[(((size_t)(b * NH + h)) * LSEQ + q) * NREL + r] = acc;
    }
}

// ---------------- layernorm ----------------
__global__ void layernorm_k(const float* __restrict__ X, const float* __restrict__ Res,
                            const float* __restrict__ gam, const float* __restrict__ bet,
                            float* __restrict__ O) {
    int row = blockIdx.x, tid = threadIdx.x;
    __shared__ float red[32];
    float4 v = *(const float4*)(X + (size_t)row * DM + tid * 4);
    if (Res) {
        float4 rr = *(const float4*)(Res + (size_t)row * DM + tid * 4);
        v.x += rr.x; v.y += rr.y; v.z += rr.z; v.w += rr.w;
    }
    float s = block_sum(v.x + v.y + v.z + v.w, red);
    float s2 = block_sum(v.x * v.x + v.y * v.y + v.z * v.z + v.w * v.w, red);
    float mu = s * (1.f / DM);
    float var = s2 * (1.f / DM) - mu * mu;
    float rstd = rsqrtf(var + 1e-6f);
    float4 g4 = *(const float4*)(gam + tid * 4);
    float4 b4 = *(const float4*)(bet + tid * 4);
    float4 o;
    o.x = (v.x - mu) * rstd * g4.x + b4.x;
    o.y = (v.y - mu) * rstd * g4.y + b4.y;
    o.z = (v.z - mu) * rstd * g4.z + b4.z;
    o.w = (v.w - mu) * rstd * g4.w + b4.w;
    *(float4*)(O + (size_t)row * DM + tid * 4) = o;
}

// ---------------- launch ----------------
static void* sym_addr(const void* s) { void* p = nullptr; cudaGetSymbolAddress(&p, s); return p; }

extern "C" void kernel_launch(void* const* d_in, const int* in_sizes, int n_in,
                              void* d_out, int out_size) {
    const float* q    = (const float*)d_in[0];
    const float* k    = (const float*)d_in[1];
    const float* v    = (const float*)d_in[2];
    const float* wq   = (const float*)d_in[3];
    const float* bq   = (const float*)d_in[4];
    const float* wk   = (const float*)d_in[5];
    const float* bk   = (const float*)d_in[6];
    const float* wv   = (const float*)d_in[7];
    const float* bv   = (const float*)d_in[8];
    const float* wfc  = (const float*)d_in[9];
    const float* bfc  = (const float*)d_in[10];
    const float* w1   = (const float*)d_in[11];
    const float* b1   = (const float*)d_in[12];
    const float* w2   = (const float*)d_in[13];
    const float* b2   = (const float*)d_in[14];
    const float* ln_g = (const float*)d_in[15];
    const float* ln_b = (const float*)d_in[16];
    const float* relk = (const float*)d_in[17];
    const float* relv = (const float*)d_in[18];
    float* out = (float*)d_out;

    float* pQ    = (float*)sym_addr(g_Q);
    float* pK    = (float*)sym_addr(g_K);
    float* pV    = (float*)sym_addr(g_V);
    float* pAttn = (float*)sym_addr(g_attn);
    float* pTmp  = (float*)sym_addr(g_tmp);
    float* pLn1  = (float*)sym_addr(g_ln1);
    float* pH1   = (float*)sym_addr(g_h1);
    float* pT2   = (float*)sym_addr(g_t2);
    __nv_bfloat16* pAhi = (__nv_bfloat16*)sym_addr(g_Ahi);
    __nv_bfloat16* pAlo = (__nv_bfloat16*)sym_addr(g_Alo);
    __nv_bfloat16* pWhi = (__nv_bfloat16*)sym_addr(g_Whi);
    __nv_bfloat16* pWlo = (__nv_bfloat16*)sym_addr(g_Wlo);
    __nv_bfloat16* pQhi = (__nv_bfloat16*)sym_addr(g_Qhi);
    __nv_bfloat16* pQlo = (__nv_bfloat16*)sym_addr(g_Qlo);
    __nv_bfloat16* pKhi = (__nv_bfloat16*)sym_addr(g_Khi);
    __nv_bfloat16* pKlo = (__nv_bfloat16*)sym_addr(g_Klo);
    __nv_bfloat16* pVthi = (__nv_bfloat16*)sym_addr(g_Vthi);
    __nv_bfloat16* pVtlo = (__nv_bfloat16*)sym_addr(g_Vtlo);

    cudaFuncSetAttribute(flash_attn, cudaFuncAttributeMaxDynamicSharedMemorySize, FLASH_SMEM);

    const int nD4 = ROWS * DM / 4 / 256;
    const int nI4 = ROWS * DI / 4 / 256;
    dim3 tBlk(32, 8);
    dim3 tGridD(DM / 32, DM / 32);
    dim3 tGridW1(DI / 32, DM / 32);
    dim3 tGridW2(DM / 32, DI / 32);
    dim3 gD(DM / 128, ROWS / 128);
    dim3 gI(DI / 128, ROWS / 128);

    // QKV projections
    conv_split_T<<<tGridD, tBlk>>>(wq, pWhi, pWlo, DM, DM);
    conv_split<<<nD4, 256>>>(q, pAhi, pAlo);
    gemm_tc<<<gD, 256>>>(pAhi, pAlo, pWhi, pWlo, bq, pQ, ROWS, DM, DM, 0);

    conv_split_T<<<tGridD, tBlk>>>(wk, pWhi, pWlo, DM, DM);
    conv_split<<<nD4, 256>>>(k, pAhi, pAlo);
    gemm_tc<<<gD, 256>>>(pAhi, pAlo, pWhi, pWlo, bk, pK, ROWS, DM, DM, 0);

    conv_split_T<<<tGridD, tBlk>>>(wv, pWhi, pWlo, DM, DM);
    conv_split<<<nD4, 256>>>(v, pAhi, pAlo);
    gemm_tc<<<gD, 256>>>(pAhi, pAlo, pWhi, pWlo, bv, pV, ROWS, DM, DM, 0);

    // attention prep: bf16 splits + srel
    conv_split<<<nD4, 256>>>(pQ, pQhi, pQlo);
    conv_split<<<nD4, 256>>>(pK, pKhi, pKlo);
    dim3 gvt(LSEQ / 32, DK / 32, BHN);
    vt_split<<<gvt, tBlk>>>(pV, pVthi, pVtlo);
    srel_kernel<<<ROWS, 256>>>(relk);

    // fused flash attention
    dim3 gfa(LSEQ / 128, BHN);
    flash_attn<<<gfa, 256, FLASH_SMEM>>>(relv);

    // out-proj + LN1
    conv_split_T<<<tGridD, tBlk>>>(wfc, pWhi, pWlo, DM, DM);
    conv_split<<<nD4, 256>>>(pAttn, pAhi, pAlo);
    gemm_tc<<<gD, 256>>>(pAhi, pAlo, pWhi, pWlo, bfc, pTmp, ROWS, DM, DM, 0);
    layernorm_k<<<ROWS, 256>>>(pTmp, q, ln_g, ln_b, pLn1);

    // FFN
    conv_split_T<<<tGridW1, tBlk>>>(w1, pWhi, pWlo, DM, DI);
    conv_split<<<nD4, 256>>>(pLn1, pAhi, pAlo);
    gemm_tc<<<gI, 256>>>(pAhi, pAlo, pWhi, pWlo, b1, pH1, ROWS, DI, DM, 1);

    conv_split_T<<<tGridW2, tBlk>>>(w2, pWhi, pWlo, DI, DM);
    conv_split<<<nI4, 256>>>(pH1, pAhi, pAlo);
    gemm_tc<<<gD, 256>>>(pAhi, pAlo, pWhi, pWlo, b2, pT2, ROWS, DM, DI, 0);
    layernorm_k<<<ROWS, 256>>>(pT2, pLn1, ln_g, ln_b, out);
}

// round 7
// speedup vs baseline: 3.5217x; 1.0664x over previous
#include <cuda_runtime.h>
#include <cuda_bf16.h>
#include <cstdint>

#define LSEQ 1024
#define DM   1024
#define BATCH 8
#define NH   16
#define DK   64
#define BHN  (BATCH*NH)     // 128
#define NREL 33
#define DI   4096
#define ROWS (BATCH*LSEQ)   // 8192

// ---------------- scratch (static device arrays; no allocation) ----------------
__device__ float g_Q[ROWS*DM];
__device__ float g_V[ROWS*DM];
__device__ float g_Srel[(size_t)BHN*LSEQ*NREL];
__device__ float g_tmp[ROWS*DM];
__device__ float g_ln1[ROWS*DM];
__device__ float g_t2[ROWS*DM];
// bf16 split buffers
__device__ __nv_bfloat16 g_Ahi[(size_t)ROWS*DI];    // big: h1 split
__device__ __nv_bfloat16 g_Alo[(size_t)ROWS*DI];
__device__ __nv_bfloat16 g_Xhi[ROWS*DM];            // current activation split
__device__ __nv_bfloat16 g_Xlo[ROWS*DM];
__device__ __nv_bfloat16 g_Whi[(size_t)DM*DI];
__device__ __nv_bfloat16 g_Wlo[(size_t)DM*DI];
__device__ __nv_bfloat16 g_Qhi[ROWS*DM];
__device__ __nv_bfloat16 g_Qlo[ROWS*DM];
__device__ __nv_bfloat16 g_Khi[ROWS*DM];
__device__ __nv_bfloat16 g_Klo[ROWS*DM];
__device__ __nv_bfloat16 g_Vthi[(size_t)BHN*DK*LSEQ];   // [bh][d][k]
__device__ __nv_bfloat16 g_Vtlo[(size_t)BHN*DK*LSEQ];

// ---------------- helpers ----------------
__device__ __forceinline__ uint32_t smem_u32(const void* p) {
    uint32_t a;
    asm("{ .reg .u64 t; cvta.to.shared.u64 t, %1; cvt.u32.u64 %0, t; }" : "=r"(a) : "l"(p));
    return a;
}
__device__ __forceinline__ void cp_async16(uint32_t saddr, const void* gaddr) {
    asm volatile("cp.async.cg.shared.global [%0], [%1], 16;" :: "r"(saddr), "l"(gaddr));
}
__device__ __forceinline__ void cp_commit() {
    asm volatile("cp.async.commit_group;" ::: "memory");
}
__device__ __forceinline__ void cp_wait1() {
    asm volatile("cp.async.wait_group 1;" ::: "memory");
}
__device__ __forceinline__ void cp_wait0() {
    asm volatile("cp.async.wait_group 0;" ::: "memory");
}
__device__ __forceinline__ void cp_async_wait_all() {
    asm volatile("cp.async.commit_group;\ncp.async.wait_group 0;" ::: "memory");
}
__device__ __forceinline__ void ldmx4(uint32_t* r, uint32_t addr) {
    asm volatile("ldmatrix.sync.aligned.m8n8.x4.shared.b16 {%0,%1,%2,%3}, [%4];"
        : "=r"(r[0]), "=r"(r[1]), "=r"(r[2]), "=r"(r[3]) : "r"(addr));
}
__device__ __forceinline__ void mma_bf16(float* c, const uint32_t* a, uint32_t b0, uint32_t b1) {
    asm volatile(
        "mma.sync.aligned.m16n8k16.row.col.f32.bf16.bf16.f32 "
        "{%0,%1,%2,%3}, {%4,%5,%6,%7}, {%8,%9}, {%0,%1,%2,%3};"
        : "+f"(c[0]), "+f"(c[1]), "+f"(c[2]), "+f"(c[3])
        : "r"(a[0]), "r"(a[1]), "r"(a[2]), "r"(a[3]), "r"(b0), "r"(b1));
}
__device__ __forceinline__ uint32_t pkbf2(__nv_bfloat16 lo, __nv_bfloat16 hi) {
    __nv_bfloat162 t(lo, hi);
    return *(uint32_t*)&t;
}

// ---------------- split conversion kernels ----------------
__global__ void conv_split(const float* __restrict__ X, __nv_bfloat16* __restrict__ hi,
                           __nv_bfloat16* __restrict__ lo) {
    int i = blockIdx.x * blockDim.x + threadIdx.x;
    float4 v = ((const float4*)X)[i];
    __nv_bfloat16 h[4], l[4];
    float xs[4] = {v.x, v.y, v.z, v.w};
#pragma unroll
    for (int j = 0; j < 4; j++) {
        h[j] = __float2bfloat16(xs[j]);
        l[j] = __float2bfloat16(xs[j] - __bfloat162float(h[j]));
    }
    *(uint2*)(hi + (size_t)i * 4) = *(uint2*)h;
    *(uint2*)(lo + (size_t)i * 4) = *(uint2*)l;
}

// W[K,N] -> hiT/loT [N,K]
__global__ void conv_split_T(const float* __restrict__ W, __nv_bfloat16* __restrict__ hiT,
                             __nv_bfloat16* __restrict__ loT, int K, int N) {
    __shared__ float t[32][33];
    int n0 = blockIdx.x * 32, k0 = blockIdx.y * 32;
    int tx = threadIdx.x, ty = threadIdx.y;
    for (int i = ty; i < 32; i += 8)
        t[i][tx] = W[(size_t)(k0 + i) * N + n0 + tx];
    __syncthreads();
    for (int r = ty; r < 32; r += 8) {
        float x = t[tx][r];
        __nv_bfloat16 h = __float2bfloat16(x);
        __nv_bfloat16 l = __float2bfloat16(x - __bfloat162float(h));
        size_t o = (size_t)(n0 + r) * K + k0 + tx;
        hiT[o] = h;
        loT[o] = l;
    }
}

// V [b*L+k][h*64+d] -> Vt [bh][d][k] (hi/lo split)
__global__ void vt_split(const float* __restrict__ V, __nv_bfloat16* __restrict__ hiT,
                         __nv_bfloat16* __restrict__ loT) {
    __shared__ float t[32][33];
    int bh = blockIdx.z, b = bh >> 4, h = bh & 15;
    int k0 = blockIdx.x * 32, d0 = blockIdx.y * 32;
    int tx = threadIdx.x, ty = threadIdx.y;
    for (int i = ty; i < 32; i += 8)
        t[i][tx] = V[(size_t)(b * LSEQ + k0 + i) * DM + h * DK + d0 + tx];
    __syncthreads();
    for (int r = ty; r < 32; r += 8) {
        float x = t[tx][r];
        __nv_bfloat16 hh = __float2bfloat16(x);
        __nv_bfloat16 ll = __float2bfloat16(x - __bfloat162float(hh));
        size_t o = ((size_t)bh * DK + d0 + r) * LSEQ + k0 + tx;
        hiT[o] = hh;
        loT[o] = ll;
    }
}

// ---------------- bf16x3 mma.sync GEMM, double-buffered ----------------
// C fp32 (optional) and/or Chi/Clo bf16 split (optional). bias (+relu) fused.
#define SPAD 40
#define GSTAGE 40960           // 4 arrays x 128*SPAD*2 bytes
#define GEMM_SMEM (2 * GSTAGE)
__global__ __launch_bounds__(256, 2) void gemm_tc(
    const __nv_bfloat16* __restrict__ Ahi, const __nv_bfloat16* __restrict__ Alo,
    const __nv_bfloat16* __restrict__ Bhi, const __nv_bfloat16* __restrict__ Blo,
    const float* __restrict__ bias, float* __restrict__ C,
    __nv_bfloat16* __restrict__ Chi, __nv_bfloat16* __restrict__ Clo,
    int M, int N, int K, int relu)
{
    extern __shared__ char gsm[];
    const uint32_t base = smem_u32(gsm);

    const int tid = threadIdx.x;
    const int wid = tid >> 5, lane = tid & 31;
    const int wm = wid >> 2, wn = wid & 3;
    const int bm = blockIdx.y * 128, bn = blockIdx.x * 128;

    float c[4][4][4];
#pragma unroll
    for (int mt = 0; mt < 4; mt++)
#pragma unroll
        for (int nt = 0; nt < 4; nt++)
#pragma unroll
            for (int r = 0; r < 4; r++) c[mt][nt][r] = 0.f;

    const int a_m_base = wm * 64 + (lane & 7) + 8 * ((lane >> 3) & 1);
    const int a_kk = 8 * (lane >> 4);
    const int b_n_base = wn * 32 + (lane & 7) + 8 * (lane >> 4);
    const int b_kk = 8 * ((lane >> 3) & 1);

    const int row_l = tid >> 2, seg_l = (tid & 3);        // loader mapping pt1
    const int ktiles = K >> 5;

    // issue tile-load for tile t into stage s
    auto load_tile = [&](int t, int s) {
        const int kbase = t * 32;
        const uint32_t sb = base + s * GSTAGE;
#pragma unroll
        for (int i = 0; i < 2; i++) {
            int f = tid + i * 256;
            int row = f >> 2, seg = f & 3;
            uint32_t so = (uint32_t)(row * SPAD + seg * 8) * 2;
            size_t ga = (size_t)(bm + row) * K + kbase + seg * 8;
            size_t gb = (size_t)(bn + row) * K + kbase + seg * 8;
            cp_async16(sb + so, Ahi + ga);
            cp_async16(sb + 10240 + so, Alo + ga);
            cp_async16(sb + 20480 + so, Bhi + gb);
            cp_async16(sb + 30720 + so, Blo + gb);
        }
        cp_commit();
    };

    load_tile(0, 0);
    for (int t = 0; t < ktiles; t++) {
        if (t + 1 < ktiles) {
            load_tile(t + 1, (t + 1) & 1);
            cp_wait1();
        } else {
            cp_wait0();
        }
        __syncthreads();

        const uint32_t sb = base + (t & 1) * GSTAGE;
        const uint32_t aAh = sb, aAl = sb + 10240, aBh = sb + 20480, aBl = sb + 30720;
#pragma unroll
        for (int kh = 0; kh < 2; kh++) {
            const int k0 = kh * 16;
            uint32_t bh[8], bl[8];
#pragma unroll
            for (int p = 0; p < 2; p++) {
                uint32_t off = (uint32_t)((b_n_base + p * 16) * SPAD + k0 + b_kk) * 2;
                ldmx4(bh + p * 4, aBh + off);
                ldmx4(bl + p * 4, aBl + off);
            }
#pragma unroll
            for (int mt = 0; mt < 4; mt++) {
                uint32_t ah[4], al[4];
                uint32_t off = (uint32_t)((a_m_base + mt * 16) * SPAD + k0 + a_kk) * 2;
                ldmx4(ah, aAh + off);
                ldmx4(al, aAl + off);
#pragma unroll
                for (int nt = 0; nt < 4; nt++) {
                    mma_bf16(c[mt][nt], ah, bh[nt * 2], bh[nt * 2 + 1]);
                    mma_bf16(c[mt][nt], ah, bl[nt * 2], bl[nt * 2 + 1]);
                    mma_bf16(c[mt][nt], al, bh[nt * 2], bh[nt * 2 + 1]);
                }
            }
        }
        __syncthreads();
    }

    const int r0 = lane >> 2, c0 = (lane & 3) * 2;
#pragma unroll
    for (int mt = 0; mt < 4; mt++) {
        int row = bm + wm * 64 + mt * 16 + r0;
#pragma unroll
        for (int nt = 0; nt < 4; nt++) {
            int col = bn + wn * 32 + nt * 8 + c0;
            float b0v = bias[col], b1v = bias[col + 1];
            float v0 = c[mt][nt][0] + b0v, v1 = c[mt][nt][1] + b1v;
            float v2 = c[mt][nt][2] + b0v, v3 = c[mt][nt][3] + b1v;
            if (relu) {
                v0 = fmaxf(v0, 0.f); v1 = fmaxf(v1, 0.f);
                v2 = fmaxf(v2, 0.f); v3 = fmaxf(v3, 0.f);
            }
            if (C) {
                *(float2*)(C + (size_t)row * N + col) = make_float2(v0, v1);
                *(float2*)(C + (size_t)(row + 8) * N + col) = make_float2(v2, v3);
            }
            if (Chi) {
                __nv_bfloat16 h0 = __float2bfloat16(v0), h1 = __float2bfloat16(v1);
                __nv_bfloat16 h2 = __float2bfloat16(v2), h3 = __float2bfloat16(v3);
                *(uint32_t*)(Chi + (size_t)row * N + col) = pkbf2(h0, h1);
                *(uint32_t*)(Chi + (size_t)(row + 8) * N + col) = pkbf2(h2, h3);
                *(uint32_t*)(Clo + (size_t)row * N + col) =
                    pkbf2(__float2bfloat16(v0 - __bfloat162float(h0)),
                          __float2bfloat16(v1 - __bfloat162float(h1)));
                *(uint32_t*)(Clo + (size_t)(row + 8) * N + col) =
                    pkbf2(__float2bfloat16(v2 - __bfloat162float(h2)),
                          __float2bfloat16(v3 - __bfloat162float(h3)));
            }
        }
    }
}

// ---------------- fused flash attention ----------------
#define QP 72
#define VP 136
#define OFF_QH 0
#define OFF_QL 18432
#define OFF_KH 36864
#define OFF_KL 55296
#define OFF_VH 73728
#define OFF_VL 91136
#define OFF_WB 108544
#define OFF_SR 125952
#define OFF_F  143360
#define FLASH_SMEM 143872

__global__ __launch_bounds__(256, 1) void flash_attn(const float* __restrict__ rel_v) {
    extern __shared__ char fsm[];
    float* sWb = (float*)(fsm + OFF_WB);    // [128][34]
    float* sSr = (float*)(fsm + OFF_SR);    // [128][34]
    float* sF  = (float*)(fsm + OFF_F);     // [128]

    const int tid = threadIdx.x;
    const int wid = tid >> 5, lane = tid & 31;
    const int bh = blockIdx.y, b = bh >> 4, h = bh & 15;
    const int bq = blockIdx.x * 128;

    const uint32_t aQh = smem_u32(fsm + OFF_QH), aQl = smem_u32(fsm + OFF_QL);
    const uint32_t aKh = smem_u32(fsm + OFF_KH), aKl = smem_u32(fsm + OFF_KL);
    const uint32_t aVh = smem_u32(fsm + OFF_VH), aVl = smem_u32(fsm + OFF_VL);

#pragma unroll
    for (int i = 0; i < 4; i++) {
        int f = tid + i * 256;
        int row = f >> 3, seg = f & 7;
        uint32_t so = (uint32_t)(row * QP + seg * 8) * 2;
        size_t gq = (size_t)(b * LSEQ + bq + row) * DM + h * DK + seg * 8;
        cp_async16(aQh + so, g_Qhi + gq);
        cp_async16(aQl + so, g_Qlo + gq);
    }
    for (int o = tid; o < 128 * NREL; o += 256) {
        int r = o / NREL, cc = o % NREL;
        sSr[r * 34 + cc] = g_Srel[((size_t)bh * LSEQ + bq + r) * NREL + cc];
    }
    for (int o = tid; o < 128 * 34; o += 256) sWb[o] = 0.f;
    cp_async_wait_all();
    __syncthreads();

    const int a_row = wid * 16 + (lane & 7) + 8 * ((lane >> 3) & 1);
    const int a_kk = 8 * (lane >> 4);
    const int b_row = (lane & 7) + 8 * (lane >> 4);
    const int b_kk = 8 * ((lane >> 3) & 1);
    const int r0 = lane >> 2, c0 = (lane & 3) * 2;
    const int qrow0 = wid * 16 + r0;
    const int q0 = bq + qrow0;

    float m0 = -1e30f, m1 = -1e30f, l0 = 0.f, l1 = 0.f;
    float O[8][4];
#pragma unroll
    for (int nt = 0; nt < 8; nt++)
#pragma unroll
        for (int j = 0; j < 4; j++) O[nt][j] = 0.f;

    for (int kt = 0; kt < 8; kt++) {
        const int k0 = kt * 128;
#pragma unroll
        for (int i = 0; i < 4; i++) {
            int f = tid + i * 256;
            int row = f >> 3, seg = f & 7;
            uint32_t so = (uint32_t)(row * QP + seg * 8) * 2;
            size_t gk = (size_t)(b * LSEQ + k0 + row) * DM + h * DK + seg * 8;
            cp_async16(aKh + so, g_Khi + gk);
            cp_async16(aKl + so, g_Klo + gk);
        }
#pragma unroll
        for (int i = 0; i < 4; i++) {
            int f = tid + i * 256;
            int row = f >> 4, seg = f & 15;
            uint32_t so = (uint32_t)(row * VP + seg * 8) * 2;
            size_t gv = ((size_t)bh * DK + row) * LSEQ + k0 + seg * 8;
            cp_async16(aVh + so, g_Vthi + gv);
            cp_async16(aVl + so, g_Vtlo + gv);
        }
        cp_async_wait_all();
        __syncthreads();

        float c[16][4];
#pragma unroll
        for (int nt = 0; nt < 16; nt++)
#pragma unroll
            for (int j = 0; j < 4; j++) c[nt][j] = 0.f;

#pragma unroll
        for (int ks = 0; ks < 4; ks++) {
            uint32_t ah[4], al[4];
            uint32_t aoff = (uint32_t)(a_row * QP + ks * 16 + a_kk) * 2;
            ldmx4(ah, aQh + aoff);
            ldmx4(al, aQl + aoff);
#pragma unroll
            for (int hh = 0; hh < 2; hh++) {
                uint32_t bhf[16], blf[16];
#pragma unroll
                for (int p = 0; p < 4; p++) {
                    uint32_t boff = (uint32_t)((b_row + hh * 64 + p * 16) * QP + ks * 16 + b_kk) * 2;
                    ldmx4(bhf + p * 4, aKh + boff);
                    ldmx4(blf + p * 4, aKl + boff);
                }
#pragma unroll
                for (int nt = 0; nt < 8; nt++) {
                    float* cc = c[hh * 8 + nt];
                    mma_bf16(cc, ah, bhf[nt * 2], bhf[nt * 2 + 1]);
                    mma_bf16(cc, ah, blf[nt * 2], blf[nt * 2 + 1]);
                    mma_bf16(cc, al, bhf[nt * 2], bhf[nt * 2 + 1]);
                }
            }
        }

        float tm0 = -1e30f, tm1 = -1e30f;
#pragma unroll
        for (int nt = 0; nt < 16; nt++) {
            int kA = k0 + nt * 8 + c0;
#pragma unroll
            for (int j = 0; j < 4; j++) {
                int kk = kA + (j & 1);
                bool low = (j < 2);
                int q = low ? q0 : q0 + 8;
                int lrow = low ? qrow0 : qrow0 + 8;
                int d = kk - q; d = max(-16, min(16, d));
                float s = (c[nt][j] + sSr[lrow * 34 + d + 16]) * 0.125f;
                c[nt][j] = s;
                if (low) tm0 = fmaxf(tm0, s); else tm1 = fmaxf(tm1, s);
            }
        }
        tm0 = fmaxf(tm0, __shfl_xor_sync(0xffffffffu, tm0, 1));
        tm0 = fmaxf(tm0, __shfl_xor_sync(0xffffffffu, tm0, 2));
        tm1 = fmaxf(tm1, __shfl_xor_sync(0xffffffffu, tm1, 1));
        tm1 = fmaxf(tm1, __shfl_xor_sync(0xffffffffu, tm1, 2));
        float nm0 = fmaxf(m0, tm0), nm1 = fmaxf(m1, tm1);
        float f0 = __expf(m0 - nm0), f1 = __expf(m1 - nm1);
        m0 = nm0; m1 = nm1;
        if ((lane & 3) == 0) { sF[qrow0] = f0; sF[qrow0 + 8] = f1; }
        __syncwarp();
        for (int o = lane; o < 16 * 33; o += 32) {
            int rr = o / 33, cc2 = o % 33;
            sWb[(wid * 16 + rr) * 34 + cc2] *= sF[wid * 16 + rr];
        }
        __syncwarp();

        float sum0 = 0.f, sum1 = 0.f, lo0 = 0.f, lo1 = 0.f, hi0 = 0.f, hi1 = 0.f;
#pragma unroll
        for (int nt = 0; nt < 16; nt++) {
#pragma unroll
            for (int j = 0; j < 4; j++) {
                int kk = k0 + nt * 8 + c0 + (j & 1);
                bool low = (j < 2);
                float p = __expf(c[nt][j] - (low ? nm0 : nm1));
                c[nt][j] = p;
                int q = low ? q0 : q0 + 8;
                int d = kk - q;
                if (low) sum0 += p; else sum1 += p;
                if (d <= -16) { if (low) lo0 += p; else lo1 += p; }
                else if (d >= 16) { if (low) hi0 += p; else hi1 += p; }
                else sWb[(low ? qrow0 : qrow0 + 8) * 34 + d + 16] += p;
            }
        }
        sum0 += __shfl_xor_sync(0xffffffffu, sum0, 1);
        sum0 += __shfl_xor_sync(0xffffffffu, sum0, 2);
        sum1 += __shfl_xor_sync(0xffffffffu, sum1, 1);
        sum1 += __shfl_xor_sync(0xffffffffu, sum1, 2);
        lo0 += __shfl_xor_sync(0xffffffffu, lo0, 1);
        lo0 += __shfl_xor_sync(0xffffffffu, lo0, 2);
        lo1 += __shfl_xor_sync(0xffffffffu, lo1, 1);
        lo1 += __shfl_xor_sync(0xffffffffu, lo1, 2);
        hi0 += __shfl_xor_sync(0xffffffffu, hi0, 1);
        hi0 += __shfl_xor_sync(0xffffffffu, hi0, 2);
        hi1 += __shfl_xor_sync(0xffffffffu, hi1, 1);
        hi1 += __shfl_xor_sync(0xffffffffu, hi1, 2);
        l0 = l0 * f0 + sum0;
        l1 = l1 * f1 + sum1;
        if ((lane & 3) == 0) {
            sWb[qrow0 * 34 + 0] += lo0;  sWb[qrow0 * 34 + 32] += hi0;
            sWb[(qrow0 + 8) * 34 + 0] += lo1;  sWb[(qrow0 + 8) * 34 + 32] += hi1;
        }
#pragma unroll
        for (int nt = 0; nt < 8; nt++) {
            O[nt][0] *= f0; O[nt][1] *= f0; O[nt][2] *= f1; O[nt][3] *= f1;
        }

#pragma unroll
        for (int j = 0; j < 8; j++) {
            float x0 = c[2 * j][0], x1 = c[2 * j][1], x2 = c[2 * j][2], x3 = c[2 * j][3];
            float y0 = c[2 * j + 1][0], y1 = c[2 * j + 1][1], y2 = c[2 * j + 1][2], y3 = c[2 * j + 1][3];
            __nv_bfloat16 hx0 = __float2bfloat16(x0), hx1 = __float2bfloat16(x1);
            __nv_bfloat16 hx2 = __float2bfloat16(x2), hx3 = __float2bfloat16(x3);
            __nv_bfloat16 hy0 = __float2bfloat16(y0), hy1 = __float2bfloat16(y1);
            __nv_bfloat16 hy2 = __float2bfloat16(y2), hy3 = __float2bfloat16(y3);
            uint32_t pa[4], pl[4];
            pa[0] = pkbf2(hx0, hx1); pa[1] = pkbf2(hx2, hx3);
            pa[2] = pkbf2(hy0, hy1); pa[3] = pkbf2(hy2, hy3);
            pl[0] = pkbf2(__float2bfloat16(x0 - __bfloat162float(hx0)),
                          __float2bfloat16(x1 - __bfloat162float(hx1)));
            pl[1] = pkbf2(__float2bfloat16(x2 - __bfloat162float(hx2)),
                          __float2bfloat16(x3 - __bfloat162float(hx3)));
            pl[2] = pkbf2(__float2bfloat16(y0 - __bfloat162float(hy0)),
                          __float2bfloat16(y1 - __bfloat162float(hy1)));
            pl[3] = pkbf2(__float2bfloat16(y2 - __bfloat162float(hy2)),
                          __float2bfloat16(y3 - __bfloat162float(hy3)));
            uint32_t vh[16], vl[16];
#pragma unroll
            for (int p = 0; p < 4; p++) {
                uint32_t voff = (uint32_t)((b_row + p * 16) * VP + j * 16 + b_kk) * 2;
                ldmx4(vh + p * 4, aVh + voff);
                ldmx4(vl + p * 4, aVl + voff);
            }
#pragma unroll
            for (int nt = 0; nt < 8; nt++) {
                mma_bf16(O[nt], pa, vh[nt * 2], vh[nt * 2 + 1]);
                mma_bf16(O[nt], pa, vl[nt * 2], vl[nt * 2 + 1]);
                mma_bf16(O[nt], pl, vh[nt * 2], vh[nt * 2 + 1]);
            }
        }
        __syncthreads();
    }

    // ---- epilogue: rank-33 rel_v update, normalize, store as bf16 hi/lo split ----
    float* rv = (float*)(fsm + OFF_KH);
    for (int o = tid; o < NREL * DK; o += 256) rv[o] = rel_v[o];
    __syncthreads();

#pragma unroll 1
    for (int r = 0; r < NREL; r++) {
        float wb0 = sWb[qrow0 * 34 + r];
        float wb1 = sWb[(qrow0 + 8) * 34 + r];
#pragma unroll
        for (int nt = 0; nt < 8; nt++) {
            int d = nt * 8 + c0;
            float rv0 = rv[r * DK + d], rv1 = rv[r * DK + d + 1];
            O[nt][0] += wb0 * rv0; O[nt][1] += wb0 * rv1;
            O[nt][2] += wb1 * rv0; O[nt][3] += wb1 * rv1;
        }
    }
    float inv0 = 1.f / l0, inv1 = 1.f / l1;
    size_t o0 = (size_t)(b * LSEQ + q0) * DM + h * DK;
    size_t o1 = (size_t)(b * LSEQ + q0 + 8) * DM + h * DK;
#pragma unroll
    for (int nt = 0; nt < 8; nt++) {
        int d = nt * 8 + c0;
        float v0 = O[nt][0] * inv0, v1 = O[nt][1] * inv0;
        float v2 = O[nt][2] * inv1, v3 = O[nt][3] * inv1;
        __nv_bfloat16 h0 = __float2bfloat16(v0), h1 = __float2bfloat16(v1);
        __nv_bfloat16 h2 = __float2bfloat16(v2), h3 = __float2bfloat16(v3);
        *(uint32_t*)(g_Xhi + o0 + d) = pkbf2(h0, h1);
        *(uint32_t*)(g_Xhi + o1 + d) = pkbf2(h2, h3);
        *(uint32_t*)(g_Xlo + o0 + d) =
            pkbf2(__float2bfloat16(v0 - __bfloat162float(h0)),
                  __float2bfloat16(v1 - __bfloat162float(h1)));
        *(uint32_t*)(g_Xlo + o1 + d) =
            pkbf2(__float2bfloat16(v2 - __bfloat162float(h2)),
                  __float2bfloat16(v3 - __bfloat162float(h3)));
    }
}

// ---------------- reductions ----------------
__device__ __forceinline__ float block_sum(float v, float* red) {
    int lane = threadIdx.x & 31, w = threadIdx.x >> 5;
#pragma unroll
    for (int o = 16; o; o >>= 1) v += __shfl_xor_sync(0xffffffffu, v, o);
    if (lane == 0) red[w] = v;
    __syncthreads();
    if (w == 0) {
        float t = (lane < 8) ? red[lane] : 0.f;
#pragma unroll
        for (int o = 4; o; o >>= 1) t += __shfl_xor_sync(0xffffffffu, t, o);
        if (lane == 0) red[0] = t;
    }
    __syncthreads();
    float r = red[0];
    __syncthreads();
    return r;
}

// ---------------- S_rel ----------------
__global__ void srel_kernel(const float* __restrict__ rel_k) {
    int blk = blockIdx.x;
    int b = blk >> 10, q = blk & 1023;
    __shared__ float qrow[DM];
    __shared__ float rk[NREL * 65];
    int tid = threadIdx.x;
    *(float4*)(qrow + tid * 4) = *(const float4*)(g_Q + (size_t)blk * DM + tid * 4);
    for (int o = tid; o < NREL * DK; o += 256) {
        int r = o >> 6, d = o & 63;
        rk[r * 65 + d] = rel_k[o];
    }
    __syncthreads();
    for (int o = tid; o < NH * NREL; o += 256) {
        int h = o / NREL, r = o % NREL;
        float acc = 0.f;
#pragma unroll
        for (int d = 0; d < DK; d++) acc += qrow[h * DK + d] * rk[r * 65 + d];
        g_Srel[(((size_t)(b * NH + h)) * LSEQ + q) * NREL + r] = acc;
    }
}

// ---------------- layernorm (optional bf16 hi/lo outputs) ----------------
__global__ void layernorm_k(const float* __restrict__ X, const float* __restrict__ Res,
                            const float* __restrict__ gam, const float* __restrict__ bet,
                            float* __restrict__ O,
                            __nv_bfloat16* __restrict__ Ohi, __nv_bfloat16* __restrict__ Olo) {
    int row = blockIdx.x, tid = threadIdx.x;
    __shared__ float red[32];
    float4 v = *(const float4*)(X + (size_t)row * DM + tid * 4);
    if (Res) {
        float4 rr = *(const float4*)(Res + (size_t)row * DM + tid * 4);
        v.x += rr.x; v.y += rr.y; v.z += rr.z; v.w += rr.w;
    }
    float s = block_sum(v.x + v.y + v.z + v.w, red);
    float s2 = block_sum(v.x * v.x + v.y * v.y + v.z * v.z + v.w * v.w, red);
    float mu = s * (1.f / DM);
    float var = s2 * (1.f / DM) - mu * mu;
    float rstd = rsqrtf(var + 1e-6f);
    float4 g4 = *(const float4*)(gam + tid * 4);
    float4 b4 = *(const float4*)(bet + tid * 4);
    float4 o;
    o.x = (v.x - mu) * rstd * g4.x + b4.x;
    o.y = (v.y - mu) * rstd * g4.y + b4.y;
    o.z = (v.z - mu) * rstd * g4.z + b4.z;
    o.w = (v.w - mu) * rstd * g4.w + b4.w;
    if (O) *(float4*)(O + (size_t)row * DM + tid * 4) = o;
    if (Ohi) {
        __nv_bfloat16 h0 = __float2bfloat16(o.x), h1 = __float2bfloat16(o.y);
        __nv_bfloat16 h2 = __float2bfloat16(o.z), h3 = __float2bfloat16(o.w);
        uint2 ph = make_uint2(pkbf2(h0, h1), pkbf2(h2, h3));
        uint2 pl = make_uint2(
            pkbf2(__float2bfloat16(o.x - __bfloat162float(h0)),
                  __float2bfloat16(o.y - __bfloat162float(h1))),
            pkbf2(__float2bfloat16(o.z - __bfloat162float(h2)),
                  __float2bfloat16(o.w - __bfloat162float(h3))));
        *(uint2*)(Ohi + (size_t)row * DM + tid * 4) = ph;
        *(uint2*)(Olo + (size_t)row * DM + tid * 4) = pl;
    }
}

// ---------------- launch ----------------
static void* sym_addr(const void* s) { void* p = nullptr; cudaGetSymbolAddress(&p, s); return p; }

extern "C" void kernel_launch(void* const* d_in, const int* in_sizes, int n_in,
                              void* d_out, int out_size) {
    const float* q    = (const float*)d_in[0];
    const float* k    = (const float*)d_in[1];
    const float* v    = (const float*)d_in[2];
    const float* wq   = (const float*)d_in[3];
    const float* bq   = (const float*)d_in[4];
    const float* wk   = (const float*)d_in[5];
    const float* bk   = (const float*)d_in[6];
    const float* wv   = (const float*)d_in[7];
    const float* bv   = (const float*)d_in[8];
    const float* wfc  = (const float*)d_in[9];
    const float* bfc  = (const float*)d_in[10];
    const float* w1   = (const float*)d_in[11];
    const float* b1   = (const float*)d_in[12];
    const float* w2   = (const float*)d_in[13];
    const float* b2   = (const float*)d_in[14];
    const float* ln_g = (const float*)d_in[15];
    const float* ln_b = (const float*)d_in[16];
    const float* relk = (const float*)d_in[17];
    const float* relv = (const float*)d_in[18];
    float* out = (float*)d_out;

    float* pQ    = (float*)sym_addr(g_Q);
    float* pV    = (float*)sym_addr(g_V);
    float* pTmp  = (float*)sym_addr(g_tmp);
    float* pLn1  = (float*)sym_addr(g_ln1);
    float* pT2   = (float*)sym_addr(g_t2);
    __nv_bfloat16* pAhi = (__nv_bfloat16*)sym_addr(g_Ahi);
    __nv_bfloat16* pAlo = (__nv_bfloat16*)sym_addr(g_Alo);
    __nv_bfloat16* pXhi = (__nv_bfloat16*)sym_addr(g_Xhi);
    __nv_bfloat16* pXlo = (__nv_bfloat16*)sym_addr(g_Xlo);
    __nv_bfloat16* pWhi = (__nv_bfloat16*)sym_addr(g_Whi);
    __nv_bfloat16* pWlo = (__nv_bfloat16*)sym_addr(g_Wlo);
    __nv_bfloat16* pQhi = (__nv_bfloat16*)sym_addr(g_Qhi);
    __nv_bfloat16* pQlo = (__nv_bfloat16*)sym_addr(g_Qlo);
    __nv_bfloat16* pKhi = (__nv_bfloat16*)sym_addr(g_Khi);
    __nv_bfloat16* pKlo = (__nv_bfloat16*)sym_addr(g_Klo);
    __nv_bfloat16* pVthi = (__nv_bfloat16*)sym_addr(g_Vthi);
    __nv_bfloat16* pVtlo = (__nv_bfloat16*)sym_addr(g_Vtlo);

    cudaFuncSetAttribute(gemm_tc, cudaFuncAttributeMaxDynamicSharedMemorySize, GEMM_SMEM);
    cudaFuncSetAttribute(flash_attn, cudaFuncAttributeMaxDynamicSharedMemorySize, FLASH_SMEM);

    const int nD4 = ROWS * DM / 4 / 256;
    dim3 tBlk(32, 8);
    dim3 tGridD(DM / 32, DM / 32);
    dim3 tGridW1(DI / 32, DM / 32);
    dim3 tGridW2(DM / 32, DI / 32);
    dim3 gD(DM / 128, ROWS / 128);
    dim3 gI(DI / 128, ROWS / 128);

    // QKV projections (Q: fp32 for srel + split for flash; K: split only; V: fp32 for vt)
    conv_split_T<<<tGridD, tBlk>>>(wq, pWhi, pWlo, DM, DM);
    conv_split<<<nD4, 256>>>(q, pXhi, pXlo);
    gemm_tc<<<gD, 256, GEMM_SMEM>>>(pXhi, pXlo, pWhi, pWlo, bq, pQ, pQhi, pQlo, ROWS, DM, DM, 0);

    conv_split_T<<<tGridD, tBlk>>>(wk, pWhi, pWlo, DM, DM);
    conv_split<<<nD4, 256>>>(k, pXhi, pXlo);
    gemm_tc<<<gD, 256, GEMM_SMEM>>>(pXhi, pXlo, pWhi, pWlo, bk, nullptr, pKhi, pKlo, ROWS, DM, DM, 0);

    conv_split_T<<<tGridD, tBlk>>>(wv, pWhi, pWlo, DM, DM);
    conv_split<<<nD4, 256>>>(v, pXhi, pXlo);
    gemm_tc<<<gD, 256, GEMM_SMEM>>>(pXhi, pXlo, pWhi, pWlo, bv, pV, nullptr, nullptr, ROWS, DM, DM, 0);

    // attention prep
    dim3 gvt(LSEQ / 32, DK / 32, BHN);
    vt_split<<<gvt, tBlk>>>(pV, pVthi, pVtlo);
    srel_kernel<<<ROWS, 256>>>(relk);

    // fused flash attention -> writes attn split into g_Xhi/g_Xlo
    dim3 gfa(LSEQ / 128, BHN);
    flash_attn<<<gfa, 256, FLASH_SMEM>>>(relv);

    // out-proj + LN1 (LN emits split for FFN1)
    conv_split_T<<<tGridD, tBlk>>>(wfc, pWhi, pWlo, DM, DM);
    gemm_tc<<<gD, 256, GEMM_SMEM>>>(pXhi, pXlo, pWhi, pWlo, bfc, pTmp, nullptr, nullptr, ROWS, DM, DM, 0);
    layernorm_k<<<ROWS, 256>>>(pTmp, q, ln_g, ln_b, pLn1, pXhi, pXlo);

    // FFN
    conv_split_T<<<tGridW1, tBlk>>>(w1, pWhi, pWlo, DM, DI);
    gemm_tc<<<gI, 256, GEMM_SMEM>>>(pXhi, pXlo, pWhi, pWlo, b1, nullptr, pAhi, pAlo, ROWS, DI, DM, 1);

    conv_split_T<<<tGridW2, tBlk>>>(w2, pWhi, pWlo, DI, DM);
    gemm_tc<<<gD, 256, GEMM_SMEM>>>(pAhi, pAlo, pWhi, pWlo, b2, pT2, nullptr, nullptr, ROWS, DM, DI, 0);
    layernorm_k<<<ROWS, 256>>>(pT2, pLn1, ln_g, ln_b, out, nullptr, nullptr);
}

// round 9
// speedup vs baseline: 3.8189x; 1.0844x over previous
#include <cuda_runtime.h>
#include <cuda_bf16.h>
#include <cstdint>

#define LSEQ 1024
#define DM   1024
#define BATCH 8
#define NH   16
#define DK   64
#define BHN  (BATCH*NH)     // 128
#define NREL 33
#define DI   4096
#define ROWS (BATCH*LSEQ)   // 8192

// ---------------- scratch (static device arrays; no allocation) ----------------
__device__ float g_V[ROWS*DM];
__device__ float g_tmp[ROWS*DM];
__device__ float g_ln1[ROWS*DM];
__device__ float g_t2[ROWS*DM];
__device__ float g_bqkv[3*DM];
// bf16 split buffers
__device__ __nv_bfloat16 g_Ahi[(size_t)ROWS*DI];    // stacked QKV inputs / h1 split
__device__ __nv_bfloat16 g_Alo[(size_t)ROWS*DI];
__device__ __nv_bfloat16 g_Xhi[ROWS*DM];            // current activation split
__device__ __nv_bfloat16 g_Xlo[ROWS*DM];
__device__ __nv_bfloat16 g_Whi[(size_t)DM*DI];
__device__ __nv_bfloat16 g_Wlo[(size_t)DM*DI];
__device__ __nv_bfloat16 g_Qhi[ROWS*DM];
__device__ __nv_bfloat16 g_Qlo[ROWS*DM];
__device__ __nv_bfloat16 g_Khi[ROWS*DM];
__device__ __nv_bfloat16 g_Klo[ROWS*DM];
__device__ __nv_bfloat16 g_Vthi[(size_t)BHN*DK*LSEQ];   // [bh][d][k]
__device__ __nv_bfloat16 g_Vtlo[(size_t)BHN*DK*LSEQ];
__device__ __nv_bfloat16 g_RKhi[48*DK];             // rel_k split, padded to 48 rows
__device__ __nv_bfloat16 g_RKlo[48*DK];

// ---------------- helpers ----------------
__device__ __forceinline__ uint32_t smem_u32(const void* p) {
    uint32_t a;
    asm("{ .reg .u64 t; cvta.to.shared.u64 t, %1; cvt.u32.u64 %0, t; }" : "=r"(a) : "l"(p));
    return a;
}
__device__ __forceinline__ void cp_async16(uint32_t saddr, const void* gaddr) {
    asm volatile("cp.async.cg.shared.global [%0], [%1], 16;" :: "r"(saddr), "l"(gaddr));
}
__device__ __forceinline__ void cp_commit() {
    asm volatile("cp.async.commit_group;" ::: "memory");
}
__device__ __forceinline__ void cp_wait1() {
    asm volatile("cp.async.wait_group 1;" ::: "memory");
}
__device__ __forceinline__ void cp_wait0() {
    asm volatile("cp.async.wait_group 0;" ::: "memory");
}
__device__ __forceinline__ void cp_async_wait_all() {
    asm volatile("cp.async.commit_group;\ncp.async.wait_group 0;" ::: "memory");
}
__device__ __forceinline__ void ldmx4(uint32_t* r, uint32_t addr) {
    asm volatile("ldmatrix.sync.aligned.m8n8.x4.shared.b16 {%0,%1,%2,%3}, [%4];"
        : "=r"(r[0]), "=r"(r[1]), "=r"(r[2]), "=r"(r[3]) : "r"(addr));
}
__device__ __forceinline__ void mma_bf16(float* c, const uint32_t* a, uint32_t b0, uint32_t b1) {
    asm volatile(
        "mma.sync.aligned.m16n8k16.row.col.f32.bf16.bf16.f32 "
        "{%0,%1,%2,%3}, {%4,%5,%6,%7}, {%8,%9}, {%0,%1,%2,%3};"
        : "+f"(c[0]), "+f"(c[1]), "+f"(c[2]), "+f"(c[3])
        : "r"(a[0]), "r"(a[1]), "r"(a[2]), "r"(a[3]), "r"(b0), "r"(b1));
}
__device__ __forceinline__ uint32_t pkbf2(__nv_bfloat16 lo, __nv_bfloat16 hi) {
    __nv_bfloat162 t(lo, hi);
    return *(uint32_t*)&t;
}

// ---------------- split conversion kernels ----------------
__global__ void conv_split(const float* __restrict__ X, __nv_bfloat16* __restrict__ hi,
                           __nv_bfloat16* __restrict__ lo) {
    int i = blockIdx.x * blockDim.x + threadIdx.x;
    float4 v = ((const float4*)X)[i];
    __nv_bfloat16 h[4], l[4];
    float xs[4] = {v.x, v.y, v.z, v.w};
#pragma unroll
    for (int j = 0; j < 4; j++) {
        h[j] = __float2bfloat16(xs[j]);
        l[j] = __float2bfloat16(xs[j] - __bfloat162float(h[j]));
    }
    *(uint2*)(hi + (size_t)i * 4) = *(uint2*)h;
    *(uint2*)(lo + (size_t)i * 4) = *(uint2*)l;
}

// W[K,N] -> hiT/loT [N,K]
__global__ void conv_split_T(const float* __restrict__ W, __nv_bfloat16* __restrict__ hiT,
                             __nv_bfloat16* __restrict__ loT, int K, int N) {
    __shared__ float t[32][33];
    int n0 = blockIdx.x * 32, k0 = blockIdx.y * 32;
    int tx = threadIdx.x, ty = threadIdx.y;
    for (int i = ty; i < 32; i += 8)
        t[i][tx] = W[(size_t)(k0 + i) * N + n0 + tx];
    __syncthreads();
    for (int r = ty; r < 32; r += 8) {
        float x = t[tx][r];
        __nv_bfloat16 h = __float2bfloat16(x);
        __nv_bfloat16 l = __float2bfloat16(x - __bfloat162float(h));
        size_t o = (size_t)(n0 + r) * K + k0 + tx;
        hiT[o] = h;
        loT[o] = l;
    }
}

// V [b*L+k][h*64+d] -> Vt [bh][d][k] (hi/lo split)
__global__ void vt_split(const float* __restrict__ V, __nv_bfloat16* __restrict__ hiT,
                         __nv_bfloat16* __restrict__ loT) {
    __shared__ float t[32][33];
    int bh = blockIdx.z, b = bh >> 4, h = bh & 15;
    int k0 = blockIdx.x * 32, d0 = blockIdx.y * 32;
    int tx = threadIdx.x, ty = threadIdx.y;
    for (int i = ty; i < 32; i += 8)
        t[i][tx] = V[(size_t)(b * LSEQ + k0 + i) * DM + h * DK + d0 + tx];
    __syncthreads();
    for (int r = ty; r < 32; r += 8) {
        float x = t[tx][r];
        __nv_bfloat16 hh = __float2bfloat16(x);
        __nv_bfloat16 ll = __float2bfloat16(x - __bfloat162float(hh));
        size_t o = ((size_t)bh * DK + d0 + r) * LSEQ + k0 + tx;
        hiT[o] = hh;
        loT[o] = ll;
    }
}

// rel_k [33,64] -> padded [48,64] bf16 hi/lo
__global__ void relk_split(const float* __restrict__ rel_k) {
    int i = blockIdx.x * 256 + threadIdx.x;   // 0..3071
    int r = i >> 6;
    float x = (r < NREL) ? rel_k[i] : 0.f;
    __nv_bfloat16 h = __float2bfloat16(x);
    g_RKhi[i] = h;
    g_RKlo[i] = __float2bfloat16(x - __bfloat162float(h));
}

__global__ void bias_concat(const float* __restrict__ b0, const float* __restrict__ b1,
                            const float* __restrict__ b2) {
    int i = blockIdx.x * 256 + threadIdx.x;   // 0..3071
    g_bqkv[i] = (i < DM) ? b0[i] : ((i < 2 * DM) ? b1[i - DM] : b2[i - 2 * DM]);
}

// ---------------- bf16x3 mma.sync GEMM, double-buffered ----------------
// qkv mode: A/B stacked by segment (seg = bn>>10); epilogue writes to
// Qhi/Qlo (seg0), Khi/Klo (seg1), fp32 g_V (seg2).
#define SPAD 40
#define GSTAGE 40960           // 4 arrays x 128*SPAD*2 bytes
#define GEMM_SMEM (2 * GSTAGE)
__global__ __launch_bounds__(256, 2) void gemm_tc(
    const __nv_bfloat16* __restrict__ Ahi, const __nv_bfloat16* __restrict__ Alo,
    const __nv_bfloat16* __restrict__ Bhi, const __nv_bfloat16* __restrict__ Blo,
    const float* __restrict__ bias, float* __restrict__ C,
    __nv_bfloat16* __restrict__ Chi, __nv_bfloat16* __restrict__ Clo,
    int M, int N, int K, int relu, int qkv)
{
    extern __shared__ char gsm[];
    const uint32_t base = smem_u32(gsm);

    const int tid = threadIdx.x;
    const int wid = tid >> 5, lane = tid & 31;
    const int wm = wid >> 2, wn = wid & 3;
    const int bm = blockIdx.y * 128, bn = blockIdx.x * 128;

    int seg = 0, bnl = bn;
    if (qkv) {
        seg = bn >> 10;
        bnl = bn & (DM - 1);
        Ahi += (size_t)seg * ROWS * DM;
        Alo += (size_t)seg * ROWS * DM;
        Bhi += (size_t)seg * DM * DM;
        Blo += (size_t)seg * DM * DM;
    }

    float c[4][4][4];
#pragma unroll
    for (int mt = 0; mt < 4; mt++)
#pragma unroll
        for (int nt = 0; nt < 4; nt++)
#pragma unroll
            for (int r = 0; r < 4; r++) c[mt][nt][r] = 0.f;

    const int a_m_base = wm * 64 + (lane & 7) + 8 * ((lane >> 3) & 1);
    const int a_kk = 8 * (lane >> 4);
    const int b_n_base = wn * 32 + (lane & 7) + 8 * (lane >> 4);
    const int b_kk = 8 * ((lane >> 3) & 1);

    const int ktiles = K >> 5;

    auto load_tile = [&](int t, int s) {
        const int kbase = t * 32;
        const uint32_t sb = base + s * GSTAGE;
#pragma unroll
        for (int i = 0; i < 2; i++) {
            int f = tid + i * 256;
            int row = f >> 2, seg2 = f & 3;
            uint32_t so = (uint32_t)(row * SPAD + seg2 * 8) * 2;
            size_t ga = (size_t)(bm + row) * K + kbase + seg2 * 8;
            size_t gb = (size_t)(bnl + row) * K + kbase + seg2 * 8;
            cp_async16(sb + so, Ahi + ga);
            cp_async16(sb + 10240 + so, Alo + ga);
            cp_async16(sb + 20480 + so, Bhi + gb);
            cp_async16(sb + 30720 + so, Blo + gb);
        }
        cp_commit();
    };

    load_tile(0, 0);
    for (int t = 0; t < ktiles; t++) {
        if (t + 1 < ktiles) {
            load_tile(t + 1, (t + 1) & 1);
            cp_wait1();
        } else {
            cp_wait0();
        }
        __syncthreads();

        const uint32_t sb = base + (t & 1) * GSTAGE;
        const uint32_t aAh = sb, aAl = sb + 10240, aBh = sb + 20480, aBl = sb + 30720;
#pragma unroll
        for (int kh = 0; kh < 2; kh++) {
            const int k0 = kh * 16;
            uint32_t bh[8], bl[8];
#pragma unroll
            for (int p = 0; p < 2; p++) {
                uint32_t off = (uint32_t)((b_n_base + p * 16) * SPAD + k0 + b_kk) * 2;
                ldmx4(bh + p * 4, aBh + off);
                ldmx4(bl + p * 4, aBl + off);
            }
#pragma unroll
            for (int mt = 0; mt < 4; mt++) {
                uint32_t ah[4], al[4];
                uint32_t off = (uint32_t)((a_m_base + mt * 16) * SPAD + k0 + a_kk) * 2;
                ldmx4(ah, aAh + off);
                ldmx4(al, aAl + off);
#pragma unroll
                for (int nt = 0; nt < 4; nt++) {
                    mma_bf16(c[mt][nt], ah, bh[nt * 2], bh[nt * 2 + 1]);
                    mma_bf16(c[mt][nt], ah, bl[nt * 2], bl[nt * 2 + 1]);
                    mma_bf16(c[mt][nt], al, bh[nt * 2], bh[nt * 2 + 1]);
                }
            }
        }
        __syncthreads();
    }

    const int r0 = lane >> 2, c0 = (lane & 3) * 2;
#pragma unroll
    for (int mt = 0; mt < 4; mt++) {
        int row = bm + wm * 64 + mt * 16 + r0;
#pragma unroll
        for (int nt = 0; nt < 4; nt++) {
            int col = bn + wn * 32 + nt * 8 + c0;
            float b0v = bias[col], b1v = bias[col + 1];
            float v0 = c[mt][nt][0] + b0v, v1 = c[mt][nt][1] + b1v;
            float v2 = c[mt][nt][2] + b0v, v3 = c[mt][nt][3] + b1v;
            if (relu) {
                v0 = fmaxf(v0, 0.f); v1 = fmaxf(v1, 0.f);
                v2 = fmaxf(v2, 0.f); v3 = fmaxf(v3, 0.f);
            }
            if (qkv) {
                int coll = bnl + wn * 32 + nt * 8 + c0;
                if (seg == 2) {
                    *(float2*)(g_V + (size_t)row * DM + coll) = make_float2(v0, v1);
                    *(float2*)(g_V + (size_t)(row + 8) * DM + coll) = make_float2(v2, v3);
                } else {
                    __nv_bfloat16* dh = (seg == 0) ? g_Qhi : g_Khi;
                    __nv_bfloat16* dl = (seg == 0) ? g_Qlo : g_Klo;
                    __nv_bfloat16 h0 = __float2bfloat16(v0), h1 = __float2bfloat16(v1);
                    __nv_bfloat16 h2 = __float2bfloat16(v2), h3 = __float2bfloat16(v3);
                    *(uint32_t*)(dh + (size_t)row * DM + coll) = pkbf2(h0, h1);
                    *(uint32_t*)(dh + (size_t)(row + 8) * DM + coll) = pkbf2(h2, h3);
                    *(uint32_t*)(dl + (size_t)row * DM + coll) =
                        pkbf2(__float2bfloat16(v0 - __bfloat162float(h0)),
                              __float2bfloat16(v1 - __bfloat162float(h1)));
                    *(uint32_t*)(dl + (size_t)(row + 8) * DM + coll) =
                        pkbf2(__float2bfloat16(v2 - __bfloat162float(h2)),
                              __float2bfloat16(v3 - __bfloat162float(h3)));
                }
            } else {
                if (C) {
                    *(float2*)(C + (size_t)row * N + col) = make_float2(v0, v1);
                    *(float2*)(C + (size_t)(row + 8) * N + col) = make_float2(v2, v3);
                }
                if (Chi) {
                    __nv_bfloat16 h0 = __float2bfloat16(v0), h1 = __float2bfloat16(v1);
                    __nv_bfloat16 h2 = __float2bfloat16(v2), h3 = __float2bfloat16(v3);
                    *(uint32_t*)(Chi + (size_t)row * N + col) = pkbf2(h0, h1);
                    *(uint32_t*)(Chi + (size_t)(row + 8) * N + col) = pkbf2(h2, h3);
                    *(uint32_t*)(Clo + (size_t)row * N + col) =
                        pkbf2(__float2bfloat16(v0 - __bfloat162float(h0)),
                              __float2bfloat16(v1 - __bfloat162float(h1)));
                    *(uint32_t*)(Clo + (size_t)(row + 8) * N + col) =
                        pkbf2(__float2bfloat16(v2 - __bfloat162float(h2)),
                              __float2bfloat16(v3 - __bfloat162float(h3)));
                }
            }
        }
    }
}

// ---------------- fused flash attention (srel-MMA + scores + softmax + buckets + AV) ----------------
#define QP 72
#define VP 136
#define OFF_QH 0
#define OFF_QL 18432
#define OFF_KH 36864
#define OFF_KL 55296
#define OFF_VH 73728
#define OFF_VL 91136
#define OFF_WB 108544
#define OFF_SR 125952
#define OFF_F  143360
#define OFF_RKH 143872
#define OFF_RKL 150784
#define FLASH_SMEM 157696

__global__ __launch_bounds__(256, 1) void flash_attn(const float* __restrict__ rel_v) {
    extern __shared__ char fsm[];
    float* sWb = (float*)(fsm + OFF_WB);    // [128][34]
    float* sSr = (float*)(fsm + OFF_SR);    // [128][34]
    float* sF  = (float*)(fsm + OFF_F);     // [128]

    const int tid = threadIdx.x;
    const int wid = tid >> 5, lane = tid & 31;
    const int bh = blockIdx.y, b = bh >> 4, h = bh & 15;
    const int bq = blockIdx.x * 128;

    const uint32_t aQh = smem_u32(fsm + OFF_QH), aQl = smem_u32(fsm + OFF_QL);
    const uint32_t aKh = smem_u32(fsm + OFF_KH), aKl = smem_u32(fsm + OFF_KL);
    const uint32_t aVh = smem_u32(fsm + OFF_VH), aVl = smem_u32(fsm + OFF_VL);
    const uint32_t aRKh = smem_u32(fsm + OFF_RKH), aRKl = smem_u32(fsm + OFF_RKL);

#pragma unroll
    for (int i = 0; i < 4; i++) {
        int f = tid + i * 256;
        int row = f >> 3, seg = f & 7;
        uint32_t so = (uint32_t)(row * QP + seg * 8) * 2;
        size_t gq = (size_t)(b * LSEQ + bq + row) * DM + h * DK + seg * 8;
        cp_async16(aQh + so, g_Qhi + gq);
        cp_async16(aQl + so, g_Qlo + gq);
    }
    // rel_k padded 48 rows x 8 segs
    for (int f = tid; f < 384; f += 256) {
        int row = f >> 3, seg = f & 7;
        uint32_t so = (uint32_t)(row * QP + seg * 8) * 2;
        cp_async16(aRKh + so, g_RKhi + row * DK + seg * 8);
        cp_async16(aRKl + so, g_RKlo + row * DK + seg * 8);
    }
    for (int o = tid; o < 128 * 34; o += 256) sWb[o] = 0.f;
    cp_async_wait_all();
    __syncthreads();

    const int a_row = wid * 16 + (lane & 7) + 8 * ((lane >> 3) & 1);
    const int a_kk = 8 * (lane >> 4);
    const int b_row = (lane & 7) + 8 * (lane >> 4);
    const int b_kk = 8 * ((lane >> 3) & 1);
    const int r0 = lane >> 2, c0 = (lane & 3) * 2;
    const int qrow0 = wid * 16 + r0;
    const int q0 = bq + qrow0;

    // ---- compute sSr = Q . rel_k^T via MMA (6 n-tiles, cols < 34 kept) ----
    {
        float csr[6][4];
#pragma unroll
        for (int nt = 0; nt < 6; nt++)
#pragma unroll
            for (int j = 0; j < 4; j++) csr[nt][j] = 0.f;
#pragma unroll
        for (int ks = 0; ks < 4; ks++) {
            uint32_t ah[4], al[4];
            uint32_t aoff = (uint32_t)(a_row * QP + ks * 16 + a_kk) * 2;
            ldmx4(ah, aQh + aoff);
            ldmx4(al, aQl + aoff);
            uint32_t rbh[12], rbl[12];
#pragma unroll
            for (int p = 0; p < 3; p++) {
                uint32_t boff = (uint32_t)((b_row + p * 16) * QP + ks * 16 + b_kk) * 2;
                ldmx4(rbh + p * 4, aRKh + boff);
                ldmx4(rbl + p * 4, aRKl + boff);
            }
#pragma unroll
            for (int nt = 0; nt < 6; nt++) {
                mma_bf16(csr[nt], ah, rbh[nt * 2], rbh[nt * 2 + 1]);
                mma_bf16(csr[nt], ah, rbl[nt * 2], rbl[nt * 2 + 1]);
                mma_bf16(csr[nt], al, rbh[nt * 2], rbh[nt * 2 + 1]);
            }
        }
#pragma unroll
        for (int nt = 0; nt < 6; nt++) {
#pragma unroll
            for (int j = 0; j < 4; j++) {
                int col = nt * 8 + c0 + (j & 1);
                if (col < 34) {
                    int row = (j < 2) ? qrow0 : qrow0 + 8;
                    sSr[row * 34 + col] = csr[nt][j];
                }
            }
        }
        __syncwarp();
    }

    float m0 = -1e30f, m1 = -1e30f, l0 = 0.f, l1 = 0.f;
    float O[8][4];
#pragma unroll
    for (int nt = 0; nt < 8; nt++)
#pragma unroll
        for (int j = 0; j < 4; j++) O[nt][j] = 0.f;

    for (int kt = 0; kt < 8; kt++) {
        const int k0 = kt * 128;
#pragma unroll
        for (int i = 0; i < 4; i++) {
            int f = tid + i * 256;
            int row = f >> 3, seg = f & 7;
            uint32_t so = (uint32_t)(row * QP + seg * 8) * 2;
            size_t gk = (size_t)(b * LSEQ + k0 + row) * DM + h * DK + seg * 8;
            cp_async16(aKh + so, g_Khi + gk);
            cp_async16(aKl + so, g_Klo + gk);
        }
#pragma unroll
        for (int i = 0; i < 4; i++) {
            int f = tid + i * 256;
            int row = f >> 4, seg = f & 15;
            uint32_t so = (uint32_t)(row * VP + seg * 8) * 2;
            size_t gv = ((size_t)bh * DK + row) * LSEQ + k0 + seg * 8;
            cp_async16(aVh + so, g_Vthi + gv);
            cp_async16(aVl + so, g_Vtlo + gv);
        }
        cp_async_wait_all();
        __syncthreads();

        float c[16][4];
#pragma unroll
        for (int nt = 0; nt < 16; nt++)
#pragma unroll
            for (int j = 0; j < 4; j++) c[nt][j] = 0.f;

#pragma unroll
        for (int ks = 0; ks < 4; ks++) {
            uint32_t ah[4], al[4];
            uint32_t aoff = (uint32_t)(a_row * QP + ks * 16 + a_kk) * 2;
            ldmx4(ah, aQh + aoff);
            ldmx4(al, aQl + aoff);
#pragma unroll
            for (int hh = 0; hh < 2; hh++) {
                uint32_t bhf[16], blf[16];
#pragma unroll
                for (int p = 0; p < 4; p++) {
                    uint32_t boff = (uint32_t)((b_row + hh * 64 + p * 16) * QP + ks * 16 + b_kk) * 2;
                    ldmx4(bhf + p * 4, aKh + boff);
                    ldmx4(blf + p * 4, aKl + boff);
                }
#pragma unroll
                for (int nt = 0; nt < 8; nt++) {
                    float* cc = c[hh * 8 + nt];
                    mma_bf16(cc, ah, bhf[nt * 2], bhf[nt * 2 + 1]);
                    mma_bf16(cc, ah, blf[nt * 2], blf[nt * 2 + 1]);
                    mma_bf16(cc, al, bhf[nt * 2], bhf[nt * 2 + 1]);
                }
            }
        }

        float tm0 = -1e30f, tm1 = -1e30f;
#pragma unroll
        for (int nt = 0; nt < 16; nt++) {
            int kA = k0 + nt * 8 + c0;
#pragma unroll
            for (int j = 0; j < 4; j++) {
                int kk = kA + (j & 1);
                bool low = (j < 2);
                int q = low ? q0 : q0 + 8;
                int lrow = low ? qrow0 : qrow0 + 8;
                int d = kk - q; d = max(-16, min(16, d));
                float s = (c[nt][j] + sSr[lrow * 34 + d + 16]) * 0.125f;
                c[nt][j] = s;
                if (low) tm0 = fmaxf(tm0, s); else tm1 = fmaxf(tm1, s);
            }
        }
        tm0 = fmaxf(tm0, __shfl_xor_sync(0xffffffffu, tm0, 1));
        tm0 = fmaxf(tm0, __shfl_xor_sync(0xffffffffu, tm0, 2));
        tm1 = fmaxf(tm1, __shfl_xor_sync(0xffffffffu, tm1, 1));
        tm1 = fmaxf(tm1, __shfl_xor_sync(0xffffffffu, tm1, 2));
        float nm0 = fmaxf(m0, tm0), nm1 = fmaxf(m1, tm1);
        float f0 = __expf(m0 - nm0), f1 = __expf(m1 - nm1);
        m0 = nm0; m1 = nm1;
        if ((lane & 3) == 0) { sF[qrow0] = f0; sF[qrow0 + 8] = f1; }
        __syncwarp();
        for (int o = lane; o < 16 * 33; o += 32) {
            int rr = o / 33, cc2 = o % 33;
            sWb[(wid * 16 + rr) * 34 + cc2] *= sF[wid * 16 + rr];
        }
        __syncwarp();

        float sum0 = 0.f, sum1 = 0.f, lo0 = 0.f, lo1 = 0.f, hi0 = 0.f, hi1 = 0.f;
#pragma unroll
        for (int nt = 0; nt < 16; nt++) {
#pragma unroll
            for (int j = 0; j < 4; j++) {
                int kk = k0 + nt * 8 + c0 + (j & 1);
                bool low = (j < 2);
                float p = __expf(c[nt][j] - (low ? nm0 : nm1));
                c[nt][j] = p;
                int q = low ? q0 : q0 + 8;
                int d = kk - q;
                if (low) sum0 += p; else sum1 += p;
                if (d <= -16) { if (low) lo0 += p; else lo1 += p; }
                else if (d >= 16) { if (low) hi0 += p; else hi1 += p; }
                else sWb[(low ? qrow0 : qrow0 + 8) * 34 + d + 16] += p;
            }
        }
        sum0 += __shfl_xor_sync(0xffffffffu, sum0, 1);
        sum0 += __shfl_xor_sync(0xffffffffu, sum0, 2);
        sum1 += __shfl_xor_sync(0xffffffffu, sum1, 1);
        sum1 += __shfl_xor_sync(0xffffffffu, sum1, 2);
        lo0 += __shfl_xor_sync(0xffffffffu, lo0, 1);
        lo0 += __shfl_xor_sync(0xffffffffu, lo0, 2);
        lo1 += __shfl_xor_sync(0xffffffffu, lo1, 1);
        lo1 += __shfl_xor_sync(0xffffffffu, lo1, 2);
        hi0 += __shfl_xor_sync(0xffffffffu, hi0, 1);
        hi0 += __shfl_xor_sync(0xffffffffu, hi0, 2);
        hi1 += __shfl_xor_sync(0xffffffffu, hi1, 1);
        hi1 += __shfl_xor_sync(0xffffffffu, hi1, 2);
        l0 = l0 * f0 + sum0;
        l1 = l1 * f1 + sum1;
        if ((lane & 3) == 0) {
            sWb[qrow0 * 34 + 0] += lo0;  sWb[qrow0 * 34 + 32] += hi0;
            sWb[(qrow0 + 8) * 34 + 0] += lo1;  sWb[(qrow0 + 8) * 34 + 32] += hi1;
        }
#pragma unroll
        for (int nt = 0; nt < 8; nt++) {
            O[nt][0] *= f0; O[nt][1] *= f0; O[nt][2] *= f1; O[nt][3] *= f1;
        }

#pragma unroll
        for (int j = 0; j < 8; j++) {
            float x0 = c[2 * j][0], x1 = c[2 * j][1], x2 = c[2 * j][2], x3 = c[2 * j][3];
            float y0 = c[2 * j + 1][0], y1 = c[2 * j + 1][1], y2 = c[2 * j + 1][2], y3 = c[2 * j + 1][3];
            __nv_bfloat16 hx0 = __float2bfloat16(x0), hx1 = __float2bfloat16(x1);
            __nv_bfloat16 hx2 = __float2bfloat16(x2), hx3 = __float2bfloat16(x3);
            __nv_bfloat16 hy0 = __float2bfloat16(y0), hy1 = __float2bfloat16(y1);
            __nv_bfloat16 hy2 = __float2bfloat16(y2), hy3 = __float2bfloat16(y3);
            uint32_t pa[4], pl[4];
            pa[0] = pkbf2(hx0, hx1); pa[1] = pkbf2(hx2, hx3);
            pa[2] = pkbf2(hy0, hy1); pa[3] = pkbf2(hy2, hy3);
            pl[0] = pkbf2(__float2bfloat16(x0 - __bfloat162float(hx0)),
                          __float2bfloat16(x1 - __bfloat162float(hx1)));
            pl[1] = pkbf2(__float2bfloat16(x2 - __bfloat162float(hx2)),
                          __float2bfloat16(x3 - __bfloat162float(hx3)));
            pl[2] = pkbf2(__float2bfloat16(y0 - __bfloat162float(hy0)),
                          __float2bfloat16(y1 - __bfloat162float(hy1)));
            pl[3] = pkbf2(__float2bfloat16(y2 - __bfloat162float(hy2)),
                          __float2bfloat16(y3 - __bfloat162float(hy3)));
            uint32_t vh[16], vl[16];
#pragma unroll
            for (int p = 0; p < 4; p++) {
                uint32_t voff = (uint32_t)((b_row + p * 16) * VP + j * 16 + b_kk) * 2;
                ldmx4(vh + p * 4, aVh + voff);
                ldmx4(vl + p * 4, aVl + voff);
            }
#pragma unroll
            for (int nt = 0; nt < 8; nt++) {
                mma_bf16(O[nt], pa, vh[nt * 2], vh[nt * 2 + 1]);
                mma_bf16(O[nt], pa, vl[nt * 2], vl[nt * 2 + 1]);
                mma_bf16(O[nt], pl, vh[nt * 2], vh[nt * 2 + 1]);
            }
        }
        __syncthreads();
    }

    // ---- epilogue: rank-33 rel_v update, normalize, store as bf16 hi/lo split ----
    float* rv = (float*)(fsm + OFF_KH);
    for (int o = tid; o < NREL * DK; o += 256) rv[o] = rel_v[o];
    __syncthreads();

#pragma unroll 1
    for (int r = 0; r < NREL; r++) {
        float wb0 = sWb[qrow0 * 34 + r];
        float wb1 = sWb[(qrow0 + 8) * 34 + r];
#pragma unroll
        for (int nt = 0; nt < 8; nt++) {
            int d = nt * 8 + c0;
            float rv0 = rv[r * DK + d], rv1 = rv[r * DK + d + 1];
            O[nt][0] += wb0 * rv0; O[nt][1] += wb0 * rv1;
            O[nt][2] += wb1 * rv0; O[nt][3] += wb1 * rv1;
        }
    }
    float inv0 = 1.f / l0, inv1 = 1.f / l1;
    size_t o0 = (size_t)(b * LSEQ + q0) * DM + h * DK;
    size_t o1 = (size_t)(b * LSEQ + q0 + 8) * DM + h * DK;
#pragma unroll
    for (int nt = 0; nt < 8; nt++) {
        int d = nt * 8 + c0;
        float v0 = O[nt][0] * inv0, v1 = O[nt][1] * inv0;
        float v2 = O[nt][2] * inv1, v3 = O[nt][3] * inv1;
        __nv_bfloat16 h0 = __float2bfloat16(v0), h1 = __float2bfloat16(v1);
        __nv_bfloat16 h2 = __float2bfloat16(v2), h3 = __float2bfloat16(v3);
        *(uint32_t*)(g_Xhi + o0 + d) = pkbf2(h0, h1);
        *(uint32_t*)(g_Xhi + o1 + d) = pkbf2(h2, h3);
        *(uint32_t*)(g_Xlo + o0 + d) =
            pkbf2(__float2bfloat16(v0 - __bfloat162float(h0)),
                  __float2bfloat16(v1 - __bfloat162float(h1)));
        *(uint32_t*)(g_Xlo + o1 + d) =
            pkbf2(__float2bfloat16(v2 - __bfloat162float(h2)),
                  __float2bfloat16(v3 - __bfloat162float(h3)));
    }
}

// ---------------- reductions ----------------
__device__ __forceinline__ float block_sum(float v, float* red) {
    int lane = threadIdx.x & 31, w = threadIdx.x >> 5;
#pragma unroll
    for (int o = 16; o; o >>= 1) v += __shfl_xor_sync(0xffffffffu, v, o);
    if (lane == 0) red[w] = v;
    __syncthreads();
    if (w == 0) {
        float t = (lane < 8) ? red[lane] : 0.f;
#pragma unroll
        for (int o = 4; o; o >>= 1) t += __shfl_xor_sync(0xffffffffu, t, o);
        if (lane == 0) red[0] = t;
    }
    __syncthreads();
    float r = red[0];
    __syncthreads();
    return r;
}

// ---------------- layernorm (optional bf16 hi/lo outputs) ----------------
__global__ void layernorm_k(const float* __restrict__ X, const float* __restrict__ Res,
                            const float* __restrict__ gam, const float* __restrict__ bet,
                            float* __restrict__ O,
                            __nv_bfloat16* __restrict__ Ohi, __nv_bfloat16* __restrict__ Olo) {
    int row = blockIdx.x, tid = threadIdx.x;
    __shared__ float red[32];
    float4 v = *(const float4*)(X + (size_t)row * DM + tid * 4);
    if (Res) {
        float4 rr = *(const float4*)(Res + (size_t)row * DM + tid * 4);
        v.x += rr.x; v.y += rr.y; v.z += rr.z; v.w += rr.w;
    }
    float s = block_sum(v.x + v.y + v.z + v.w, red);
    float s2 = block_sum(v.x * v.x + v.y * v.y + v.z * v.z + v.w * v.w, red);
    float mu = s * (1.f / DM);
    float var = s2 * (1.f / DM) - mu * mu;
    float rstd = rsqrtf(var + 1e-6f);
    float4 g4 = *(const float4*)(gam + tid * 4);
    float4 b4 = *(const float4*)(bet + tid * 4);
    float4 o;
    o.x = (v.x - mu) * rstd * g4.x + b4.x;
    o.y = (v.y - mu) * rstd * g4.y + b4.y;
    o.z = (v.z - mu) * rstd * g4.z + b4.z;
    o.w = (v.w - mu) * rstd * g4.w + b4.w;
    if (O) *(float4*)(O + (size_t)row * DM + tid * 4) = o;
    if (Ohi) {
        __nv_bfloat16 h0 = __float2bfloat16(o.x), h1 = __float2bfloat16(o.y);
        __nv_bfloat16 h2 = __float2bfloat16(o.z), h3 = __float2bfloat16(o.w);
        uint2 ph = make_uint2(pkbf2(h0, h1), pkbf2(h2, h3));
        uint2 pl = make_uint2(
            pkbf2(__float2bfloat16(o.x - __bfloat162float(h0)),
                  __float2bfloat16(o.y - __bfloat162float(h1))),
            pkbf2(__float2bfloat16(o.z - __bfloat162float(h2)),
                  __float2bfloat16(o.w - __bfloat162float(h3))));
        *(uint2*)(Ohi + (size_t)row * DM + tid * 4) = ph;
        *(uint2*)(Olo + (size_t)row * DM + tid * 4) = pl;
    }
}

// ---------------- launch ----------------
static void* sym_addr(const void* s) { void* p = nullptr; cudaGetSymbolAddress(&p, s); return p; }

extern "C" void kernel_launch(void* const* d_in, const int* in_sizes, int n_in,
                              void* d_out, int out_size) {
    const float* q    = (const float*)d_in[0];
    const float* k    = (const float*)d_in[1];
    const float* v    = (const float*)d_in[2];
    const float* wq   = (const float*)d_in[3];
    const float* bq   = (const float*)d_in[4];
    const float* wk   = (const float*)d_in[5];
    const float* bk   = (const float*)d_in[6];
    const float* wv   = (const float*)d_in[7];
    const float* bv   = (const float*)d_in[8];
    const float* wfc  = (const float*)d_in[9];
    const float* bfc  = (const float*)d_in[10];
    const float* w1   = (const float*)d_in[11];
    const float* b1   = (const float*)d_in[12];
    const float* w2   = (const float*)d_in[13];
    const float* b2   = (const float*)d_in[14];
    const float* ln_g = (const float*)d_in[15];
    const float* ln_b = (const float*)d_in[16];
    const float* relk = (const float*)d_in[17];
    const float* relv = (const float*)d_in[18];
    float* out = (float*)d_out;

    float* pV    = (float*)sym_addr(g_V);
    float* pTmp  = (float*)sym_addr(g_tmp);
    float* pLn1  = (float*)sym_addr(g_ln1);
    float* pT2   = (float*)sym_addr(g_t2);
    float* pBqkv = (float*)sym_addr(g_bqkv);
    __nv_bfloat16* pAhi = (__nv_bfloat16*)sym_addr(g_Ahi);
    __nv_bfloat16* pAlo = (__nv_bfloat16*)sym_addr(g_Alo);
    __nv_bfloat16* pXhi = (__nv_bfloat16*)sym_addr(g_Xhi);
    __nv_bfloat16* pXlo = (__nv_bfloat16*)sym_addr(g_Xlo);
    __nv_bfloat16* pWhi = (__nv_bfloat16*)sym_addr(g_Whi);
    __nv_bfloat16* pWlo = (__nv_bfloat16*)sym_addr(g_Wlo);
    __nv_bfloat16* pVthi = (__nv_bfloat16*)sym_addr(g_Vthi);
    __nv_bfloat16* pVtlo = (__nv_bfloat16*)sym_addr(g_Vtlo);

    cudaFuncSetAttribute(gemm_tc, cudaFuncAttributeMaxDynamicSharedMemorySize, GEMM_SMEM);
    cudaFuncSetAttribute(flash_attn, cudaFuncAttributeMaxDynamicSharedMemorySize, FLASH_SMEM);

    const int nD4 = ROWS * DM / 4 / 256;
    dim3 tBlk(32, 8);
    dim3 tGridD(DM / 32, DM / 32);
    dim3 tGridW1(DI / 32, DM / 32);
    dim3 tGridW2(DM / 32, DI / 32);
    dim3 gD(DM / 128, ROWS / 128);
    dim3 gI(DI / 128, ROWS / 128);
    dim3 gQKV(3 * DM / 128, ROWS / 128);

    // ---- merged QKV: stacked weights, stacked inputs, concat bias ----
    bias_concat<<<12, 256>>>(bq, bk, bv);
    relk_split<<<12, 256>>>(relk);
    conv_split_T<<<tGridD, tBlk>>>(wq, pWhi, pWlo, DM, DM);
    conv_split_T<<<tGridD, tBlk>>>(wk, pWhi + (size_t)DM * DM, pWlo + (size_t)DM * DM, DM, DM);
    conv_split_T<<<tGridD, tBlk>>>(wv, pWhi + 2 * (size_t)DM * DM, pWlo + 2 * (size_t)DM * DM, DM, DM);
    conv_split<<<nD4, 256>>>(q, pAhi, pAlo);
    conv_split<<<nD4, 256>>>(k, pAhi + (size_t)ROWS * DM, pAlo + (size_t)ROWS * DM);
    conv_split<<<nD4, 256>>>(v, pAhi + 2 * (size_t)ROWS * DM, pAlo + 2 * (size_t)ROWS * DM);
    gemm_tc<<<gQKV, 256, GEMM_SMEM>>>(pAhi, pAlo, pWhi, pWlo, pBqkv,
                                      nullptr, nullptr, nullptr, ROWS, 3 * DM, DM, 0, 1);

    // attention prep
    dim3 gvt(LSEQ / 32, DK / 32, BHN);
    vt_split<<<gvt, tBlk>>>(pV, pVthi, pVtlo);

    // fused flash attention (computes srel internally) -> attn split into g_Xhi/g_Xlo
    dim3 gfa(LSEQ / 128, BHN);
    flash_attn<<<gfa, 256, FLASH_SMEM>>>(relv);

    // out-proj + LN1 (LN emits split for FFN1)
    conv_split_T<<<tGridD, tBlk>>>(wfc, pWhi, pWlo, DM, DM);
    gemm_tc<<<gD, 256, GEMM_SMEM>>>(pXhi, pXlo, pWhi, pWlo, bfc, pTmp, nullptr, nullptr,
                                    ROWS, DM, DM, 0, 0);
    layernorm_k<<<ROWS, 256>>>(pTmp, q, ln_g, ln_b, pLn1, pXhi, pXlo);

    // FFN
    conv_split_T<<<tGridW1, tBlk>>>(w1, pWhi, pWlo, DM, DI);
    gemm_tc<<<gI, 256, GEMM_SMEM>>>(pXhi, pXlo, pWhi, pWlo, b1, nullptr, pAhi, pAlo,
                                    ROWS, DI, DM, 1, 0);

    conv_split_T<<<tGridW2, tBlk>>>(w2, pWhi, pWlo, DI, DM);
    gemm_tc<<<gD, 256, GEMM_SMEM>>>(pAhi, pAlo, pWhi, pWlo, b2, pT2, nullptr, nullptr,
                                    ROWS, DM, DI, 0, 0);
    layernorm_k<<<ROWS, 256>>>(pT2, pLn1, ln_g, ln_b, out, nullptr, nullptr);
}

// round 10
// speedup vs baseline: 4.4373x; 1.1619x over previous
#include <cuda_runtime.h>
#include <cuda_bf16.h>
#include <cuda_fp16.h>
#include <cstdint>

#define LSEQ 1024
#define DM   1024
#define BATCH 8
#define NH   16
#define DK   64
#define BHN  (BATCH*NH)     // 128
#define NREL 33
#define DI   4096
#define ROWS (BATCH*LSEQ)   // 8192

// ---------------- scratch (static device arrays; no allocation) ----------------
__device__ float g_V[ROWS*DM];
__device__ float g_tmp[ROWS*DM];
__device__ float g_ln1[ROWS*DM];
__device__ float g_t2[ROWS*DM];
__device__ float g_bqkv[3*DM];
// 2-byte split buffers (bf16 for QKV/attention path; fp16 for FFN path via cast)
__device__ __nv_bfloat16 g_Ahi[(size_t)ROWS*DI];    // stacked QKV inputs / h1 split
__device__ __nv_bfloat16 g_Alo[(size_t)ROWS*DI];
__device__ __nv_bfloat16 g_Xhi[ROWS*DM];            // current activation split
__device__ __nv_bfloat16 g_Xlo[ROWS*DM];
__device__ __nv_bfloat16 g_Whi[(size_t)DM*DI];
__device__ __nv_bfloat16 g_Wlo[(size_t)DM*DI];
__device__ __nv_bfloat16 g_Qhi[ROWS*DM];
__device__ __nv_bfloat16 g_Qlo[ROWS*DM];
__device__ __nv_bfloat16 g_Khi[ROWS*DM];
__device__ __nv_bfloat16 g_Klo[ROWS*DM];
__device__ __nv_bfloat16 g_Vthi[(size_t)BHN*DK*LSEQ];   // [bh][d][k]
__device__ __nv_bfloat16 g_Vtlo[(size_t)BHN*DK*LSEQ];
__device__ __nv_bfloat16 g_RKhi[48*DK];             // rel_k split, padded to 48 rows
__device__ __nv_bfloat16 g_RKlo[48*DK];

// ---------------- helpers ----------------
__device__ __forceinline__ uint32_t smem_u32(const void* p) {
    uint32_t a;
    asm("{ .reg .u64 t; cvta.to.shared.u64 t, %1; cvt.u32.u64 %0, t; }" : "=r"(a) : "l"(p));
    return a;
}
__device__ __forceinline__ void cp_async16(uint32_t saddr, const void* gaddr) {
    asm volatile("cp.async.cg.shared.global [%0], [%1], 16;" :: "r"(saddr), "l"(gaddr));
}
__device__ __forceinline__ void cp_commit() {
    asm volatile("cp.async.commit_group;" ::: "memory");
}
__device__ __forceinline__ void cp_wait1() {
    asm volatile("cp.async.wait_group 1;" ::: "memory");
}
__device__ __forceinline__ void cp_wait0() {
    asm volatile("cp.async.wait_group 0;" ::: "memory");
}
__device__ __forceinline__ void cp_async_wait_all() {
    asm volatile("cp.async.commit_group;\ncp.async.wait_group 0;" ::: "memory");
}
__device__ __forceinline__ void ldmx4(uint32_t* r, uint32_t addr) {
    asm volatile("ldmatrix.sync.aligned.m8n8.x4.shared.b16 {%0,%1,%2,%3}, [%4];"
        : "=r"(r[0]), "=r"(r[1]), "=r"(r[2]), "=r"(r[3]) : "r"(addr));
}
__device__ __forceinline__ void mma_bf16(float* c, const uint32_t* a, uint32_t b0, uint32_t b1) {
    asm volatile(
        "mma.sync.aligned.m16n8k16.row.col.f32.bf16.bf16.f32 "
        "{%0,%1,%2,%3}, {%4,%5,%6,%7}, {%8,%9}, {%0,%1,%2,%3};"
        : "+f"(c[0]), "+f"(c[1]), "+f"(c[2]), "+f"(c[3])
        : "r"(a[0]), "r"(a[1]), "r"(a[2]), "r"(a[3]), "r"(b0), "r"(b1));
}
__device__ __forceinline__ void mma_f16(float* c, const uint32_t* a, uint32_t b0, uint32_t b1) {
    asm volatile(
        "mma.sync.aligned.m16n8k16.row.col.f32.f16.f16.f32 "
        "{%0,%1,%2,%3}, {%4,%5,%6,%7}, {%8,%9}, {%0,%1,%2,%3};"
        : "+f"(c[0]), "+f"(c[1]), "+f"(c[2]), "+f"(c[3])
        : "r"(a[0]), "r"(a[1]), "r"(a[2]), "r"(a[3]), "r"(b0), "r"(b1));
}
__device__ __forceinline__ uint32_t pkbf2(__nv_bfloat16 lo, __nv_bfloat16 hi) {
    __nv_bfloat162 t(lo, hi);
    return *(uint32_t*)&t;
}
__device__ __forceinline__ uint32_t pkh2(__half lo, __half hi) {
    __half2 t(lo, hi);
    return *(uint32_t*)&t;
}

// ---------------- split conversion kernels ----------------
__global__ void conv_split(const float* __restrict__ X, __nv_bfloat16* __restrict__ hi,
                           __nv_bfloat16* __restrict__ lo) {
    int i = blockIdx.x * blockDim.x + threadIdx.x;
    float4 v = ((const float4*)X)[i];
    __nv_bfloat16 h[4], l[4];
    float xs[4] = {v.x, v.y, v.z, v.w};
#pragma unroll
    for (int j = 0; j < 4; j++) {
        h[j] = __float2bfloat16(xs[j]);
        l[j] = __float2bfloat16(xs[j] - __bfloat162float(h[j]));
    }
    *(uint2*)(hi + (size_t)i * 4) = *(uint2*)h;
    *(uint2*)(lo + (size_t)i * 4) = *(uint2*)l;
}

// W[K,N] -> hiT/loT [N,K] (bf16, for QKV)
__global__ void conv_split_T(const float* __restrict__ W, __nv_bfloat16* __restrict__ hiT,
                             __nv_bfloat16* __restrict__ loT, int K, int N) {
    __shared__ float t[32][33];
    int n0 = blockIdx.x * 32, k0 = blockIdx.y * 32;
    int tx = threadIdx.x, ty = threadIdx.y;
    for (int i = ty; i < 32; i += 8)
        t[i][tx] = W[(size_t)(k0 + i) * N + n0 + tx];
    __syncthreads();
    for (int r = ty; r < 32; r += 8) {
        float x = t[tx][r];
        __nv_bfloat16 h = __float2bfloat16(x);
        __nv_bfloat16 l = __float2bfloat16(x - __bfloat162float(h));
        size_t o = (size_t)(n0 + r) * K + k0 + tx;
        hiT[o] = h;
        loT[o] = l;
    }
}

// W[K,N] -> fp16 single T [N,K] (for FFN path)
__global__ void conv_T_h(const float* __restrict__ W, __half* __restrict__ hT, int K, int N) {
    __shared__ float t[32][33];
    int n0 = blockIdx.x * 32, k0 = blockIdx.y * 32;
    int tx = threadIdx.x, ty = threadIdx.y;
    for (int i = ty; i < 32; i += 8)
        t[i][tx] = W[(size_t)(k0 + i) * N + n0 + tx];
    __syncthreads();
    for (int r = ty; r < 32; r += 8)
        hT[(size_t)(n0 + r) * K + k0 + tx] = __float2half_rn(t[tx][r]);
}

// V [b*L+k][h*64+d] -> Vt [bh][d][k] (bf16 hi/lo split)
__global__ void vt_split(const float* __restrict__ V, __nv_bfloat16* __restrict__ hiT,
                         __nv_bfloat16* __restrict__ loT) {
    __shared__ float t[32][33];
    int bh = blockIdx.z, b = bh >> 4, h = bh & 15;
    int k0 = blockIdx.x * 32, d0 = blockIdx.y * 32;
    int tx = threadIdx.x, ty = threadIdx.y;
    for (int i = ty; i < 32; i += 8)
        t[i][tx] = V[(size_t)(b * LSEQ + k0 + i) * DM + h * DK + d0 + tx];
    __syncthreads();
    for (int r = ty; r < 32; r += 8) {
        float x = t[tx][r];
        __nv_bfloat16 hh = __float2bfloat16(x);
        __nv_bfloat16 ll = __float2bfloat16(x - __bfloat162float(hh));
        size_t o = ((size_t)bh * DK + d0 + r) * LSEQ + k0 + tx;
        hiT[o] = hh;
        loT[o] = ll;
    }
}

// rel_k [33,64] -> padded [48,64] bf16 hi/lo
__global__ void relk_split(const float* __restrict__ rel_k) {
    int i = blockIdx.x * 256 + threadIdx.x;   // 0..3071
    int r = i >> 6;
    float x = (r < NREL) ? rel_k[i] : 0.f;
    __nv_bfloat16 h = __float2bfloat16(x);
    g_RKhi[i] = h;
    g_RKlo[i] = __float2bfloat16(x - __bfloat162float(h));
}

__global__ void bias_concat(const float* __restrict__ b0, const float* __restrict__ b1,
                            const float* __restrict__ b2) {
    int i = blockIdx.x * 256 + threadIdx.x;   // 0..3071
    g_bqkv[i] = (i < DM) ? b0[i] : ((i < 2 * DM) ? b1[i - DM] : b2[i - 2 * DM]);
}

// ---------------- bf16x3 mma.sync GEMM, double-buffered (QKV path) ----------------
#define SPAD 40
#define GSTAGE 40960           // 4 arrays x 128*SPAD*2 bytes
#define GEMM_SMEM (2 * GSTAGE)
__global__ __launch_bounds__(256, 2) void gemm_tc(
    const __nv_bfloat16* __restrict__ Ahi, const __nv_bfloat16* __restrict__ Alo,
    const __nv_bfloat16* __restrict__ Bhi, const __nv_bfloat16* __restrict__ Blo,
    const float* __restrict__ bias, int M, int N, int K)
{
    extern __shared__ char gsm[];
    const uint32_t base = smem_u32(gsm);

    const int tid = threadIdx.x;
    const int wid = tid >> 5, lane = tid & 31;
    const int wm = wid >> 2, wn = wid & 3;
    const int bm = blockIdx.y * 128, bn = blockIdx.x * 128;

    // QKV stacked segments
    const int seg = bn >> 10;
    const int bnl = bn & (DM - 1);
    Ahi += (size_t)seg * ROWS * DM;
    Alo += (size_t)seg * ROWS * DM;
    Bhi += (size_t)seg * DM * DM;
    Blo += (size_t)seg * DM * DM;

    float c[4][4][4];
#pragma unroll
    for (int mt = 0; mt < 4; mt++)
#pragma unroll
        for (int nt = 0; nt < 4; nt++)
#pragma unroll
            for (int r = 0; r < 4; r++) c[mt][nt][r] = 0.f;

    const int a_m_base = wm * 64 + (lane & 7) + 8 * ((lane >> 3) & 1);
    const int a_kk = 8 * (lane >> 4);
    const int b_n_base = wn * 32 + (lane & 7) + 8 * (lane >> 4);
    const int b_kk = 8 * ((lane >> 3) & 1);

    const int ktiles = K >> 5;

    auto load_tile = [&](int t, int s) {
        const int kbase = t * 32;
        const uint32_t sb = base + s * GSTAGE;
#pragma unroll
        for (int i = 0; i < 2; i++) {
            int f = tid + i * 256;
            int row = f >> 2, seg2 = f & 3;
            uint32_t so = (uint32_t)(row * SPAD + seg2 * 8) * 2;
            size_t ga = (size_t)(bm + row) * K + kbase + seg2 * 8;
            size_t gb = (size_t)(bnl + row) * K + kbase + seg2 * 8;
            cp_async16(sb + so, Ahi + ga);
            cp_async16(sb + 10240 + so, Alo + ga);
            cp_async16(sb + 20480 + so, Bhi + gb);
            cp_async16(sb + 30720 + so, Blo + gb);
        }
        cp_commit();
    };

    load_tile(0, 0);
    for (int t = 0; t < ktiles; t++) {
        if (t + 1 < ktiles) {
            load_tile(t + 1, (t + 1) & 1);
            cp_wait1();
        } else {
            cp_wait0();
        }
        __syncthreads();

        const uint32_t sb = base + (t & 1) * GSTAGE;
        const uint32_t aAh = sb, aAl = sb + 10240, aBh = sb + 20480, aBl = sb + 30720;
#pragma unroll
        for (int kh = 0; kh < 2; kh++) {
            const int k0 = kh * 16;
            uint32_t bh[8], bl[8];
#pragma unroll
            for (int p = 0; p < 2; p++) {
                uint32_t off = (uint32_t)((b_n_base + p * 16) * SPAD + k0 + b_kk) * 2;
                ldmx4(bh + p * 4, aBh + off);
                ldmx4(bl + p * 4, aBl + off);
            }
#pragma unroll
            for (int mt = 0; mt < 4; mt++) {
                uint32_t ah[4], al[4];
                uint32_t off = (uint32_t)((a_m_base + mt * 16) * SPAD + k0 + a_kk) * 2;
                ldmx4(ah, aAh + off);
                ldmx4(al, aAl + off);
#pragma unroll
                for (int nt = 0; nt < 4; nt++) {
                    mma_bf16(c[mt][nt], ah, bh[nt * 2], bh[nt * 2 + 1]);
                    mma_bf16(c[mt][nt], ah, bl[nt * 2], bl[nt * 2 + 1]);
                    mma_bf16(c[mt][nt], al, bh[nt * 2], bh[nt * 2 + 1]);
                }
            }
        }
        __syncthreads();
    }

    const int r0 = lane >> 2, c0 = (lane & 3) * 2;
#pragma unroll
    for (int mt = 0; mt < 4; mt++) {
        int row = bm + wm * 64 + mt * 16 + r0;
#pragma unroll
        for (int nt = 0; nt < 4; nt++) {
            int col = bn + wn * 32 + nt * 8 + c0;
            float b0v = bias[col], b1v = bias[col + 1];
            float v0 = c[mt][nt][0] + b0v, v1 = c[mt][nt][1] + b1v;
            float v2 = c[mt][nt][2] + b0v, v3 = c[mt][nt][3] + b1v;
            int coll = bnl + wn * 32 + nt * 8 + c0;
            if (seg == 2) {
                *(float2*)(g_V + (size_t)row * DM + coll) = make_float2(v0, v1);
                *(float2*)(g_V + (size_t)(row + 8) * DM + coll) = make_float2(v2, v3);
            } else {
                __nv_bfloat16* dh = (seg == 0) ? g_Qhi : g_Khi;
                __nv_bfloat16* dl = (seg == 0) ? g_Qlo : g_Klo;
                __nv_bfloat16 h0 = __float2bfloat16(v0), h1 = __float2bfloat16(v1);
                __nv_bfloat16 h2 = __float2bfloat16(v2), h3 = __float2bfloat16(v3);
                *(uint32_t*)(dh + (size_t)row * DM + coll) = pkbf2(h0, h1);
                *(uint32_t*)(dh + (size_t)(row + 8) * DM + coll) = pkbf2(h2, h3);
                *(uint32_t*)(dl + (size_t)row * DM + coll) =
                    pkbf2(__float2bfloat16(v0 - __bfloat162float(h0)),
                          __float2bfloat16(v1 - __bfloat162float(h1)));
                *(uint32_t*)(dl + (size_t)(row + 8) * DM + coll) =
                    pkbf2(__float2bfloat16(v2 - __bfloat162float(h2)),
                          __float2bfloat16(v3 - __bfloat162float(h3)));
            }
        }
    }
}

// ---------------- fp16 2-pass GEMM (A exact hi/lo fp16, B single fp16) ----------------
// C = (Ah+Al) @ B^T + bias (opt relu); outputs fp32 C and/or fp16 split Chi/Clo.
#define GSTAGE_H 30720          // 3 arrays x 10240
#define GEMM_H_SMEM (2 * GSTAGE_H)
__global__ __launch_bounds__(256, 2) void gemm_fp16(
    const __half* __restrict__ Ahi, const __half* __restrict__ Alo,
    const __half* __restrict__ Bh,
    const float* __restrict__ bias, float* __restrict__ C,
    __half* __restrict__ Chi, __half* __restrict__ Clo,
    int M, int N, int K, int relu)
{
    extern __shared__ char gsm[];
    const uint32_t base = smem_u32(gsm);

    const int tid = threadIdx.x;
    const int wid = tid >> 5, lane = tid & 31;
    const int wm = wid >> 2, wn = wid & 3;
    const int bm = blockIdx.y * 128, bn = blockIdx.x * 128;

    float c[4][4][4];
#pragma unroll
    for (int mt = 0; mt < 4; mt++)
#pragma unroll
        for (int nt = 0; nt < 4; nt++)
#pragma unroll
            for (int r = 0; r < 4; r++) c[mt][nt][r] = 0.f;

    const int a_m_base = wm * 64 + (lane & 7) + 8 * ((lane >> 3) & 1);
    const int a_kk = 8 * (lane >> 4);
    const int b_n_base = wn * 32 + (lane & 7) + 8 * (lane >> 4);
    const int b_kk = 8 * ((lane >> 3) & 1);

    const int ktiles = K >> 5;

    auto load_tile = [&](int t, int s) {
        const int kbase = t * 32;
        const uint32_t sb = base + s * GSTAGE_H;
#pragma unroll
        for (int i = 0; i < 2; i++) {
            int f = tid + i * 256;
            int row = f >> 2, seg2 = f & 3;
            uint32_t so = (uint32_t)(row * SPAD + seg2 * 8) * 2;
            size_t ga = (size_t)(bm + row) * K + kbase + seg2 * 8;
            size_t gb = (size_t)(bn + row) * K + kbase + seg2 * 8;
            cp_async16(sb + so, Ahi + ga);
            cp_async16(sb + 10240 + so, Alo + ga);
            cp_async16(sb + 20480 + so, Bh + gb);
        }
        cp_commit();
    };

    load_tile(0, 0);
    for (int t = 0; t < ktiles; t++) {
        if (t + 1 < ktiles) {
            load_tile(t + 1, (t + 1) & 1);
            cp_wait1();
        } else {
            cp_wait0();
        }
        __syncthreads();

        const uint32_t sb = base + (t & 1) * GSTAGE_H;
        const uint32_t aAh = sb, aAl = sb + 10240, aBh = sb + 20480;
#pragma unroll
        for (int kh = 0; kh < 2; kh++) {
            const int k0 = kh * 16;
            uint32_t bh[8];
#pragma unroll
            for (int p = 0; p < 2; p++) {
                uint32_t off = (uint32_t)((b_n_base + p * 16) * SPAD + k0 + b_kk) * 2;
                ldmx4(bh + p * 4, aBh + off);
            }
#pragma unroll
            for (int mt = 0; mt < 4; mt++) {
                uint32_t ah[4], al[4];
                uint32_t off = (uint32_t)((a_m_base + mt * 16) * SPAD + k0 + a_kk) * 2;
                ldmx4(ah, aAh + off);
                ldmx4(al, aAl + off);
#pragma unroll
                for (int nt = 0; nt < 4; nt++) {
                    mma_f16(c[mt][nt], ah, bh[nt * 2], bh[nt * 2 + 1]);
                    mma_f16(c[mt][nt], al, bh[nt * 2], bh[nt * 2 + 1]);
                }
            }
        }
        __syncthreads();
    }

    const int r0 = lane >> 2, c0 = (lane & 3) * 2;
#pragma unroll
    for (int mt = 0; mt < 4; mt++) {
        int row = bm + wm * 64 + mt * 16 + r0;
#pragma unroll
        for (int nt = 0; nt < 4; nt++) {
            int col = bn + wn * 32 + nt * 8 + c0;
            float b0v = bias[col], b1v = bias[col + 1];
            float v0 = c[mt][nt][0] + b0v, v1 = c[mt][nt][1] + b1v;
            float v2 = c[mt][nt][2] + b0v, v3 = c[mt][nt][3] + b1v;
            if (relu) {
                v0 = fmaxf(v0, 0.f); v1 = fmaxf(v1, 0.f);
                v2 = fmaxf(v2, 0.f); v3 = fmaxf(v3, 0.f);
            }
            if (C) {
                *(float2*)(C + (size_t)row * N + col) = make_float2(v0, v1);
                *(float2*)(C + (size_t)(row + 8) * N + col) = make_float2(v2, v3);
            }
            if (Chi) {
                __half h0 = __float2half_rn(v0), h1 = __float2half_rn(v1);
                __half h2 = __float2half_rn(v2), h3 = __float2half_rn(v3);
                *(uint32_t*)(Chi + (size_t)row * N + col) = pkh2(h0, h1);
                *(uint32_t*)(Chi + (size_t)(row + 8) * N + col) = pkh2(h2, h3);
                *(uint32_t*)(Clo + (size_t)row * N + col) =
                    pkh2(__float2half_rn(v0 - __half2float(h0)),
                         __float2half_rn(v1 - __half2float(h1)));
                *(uint32_t*)(Clo + (size_t)(row + 8) * N + col) =
                    pkh2(__float2half_rn(v2 - __half2float(h2)),
                         __float2half_rn(v3 - __half2float(h3)));
            }
        }
    }
}

// ---------------- fused flash attention (srel-MMA + scores + softmax + buckets + AV) ----------------
#define QP 72
#define VP 136
#define OFF_QH 0
#define OFF_QL 18432
#define OFF_KH 36864
#define OFF_KL 55296
#define OFF_VH 73728
#define OFF_VL 91136
#define OFF_WB 108544
#define OFF_SR 125952
#define OFF_F  143360
#define OFF_RKH 143872
#define OFF_RKL 150784
#define FLASH_SMEM 157696

__global__ __launch_bounds__(256, 1) void flash_attn(const float* __restrict__ rel_v) {
    extern __shared__ char fsm[];
    float* sWb = (float*)(fsm + OFF_WB);    // [128][34]
    float* sSr = (float*)(fsm + OFF_SR);    // [128][34]
    float* sF  = (float*)(fsm + OFF_F);     // [128]

    const int tid = threadIdx.x;
    const int wid = tid >> 5, lane = tid & 31;
    const int bh = blockIdx.y, b = bh >> 4, h = bh & 15;
    const int bq = blockIdx.x * 128;

    const uint32_t aQh = smem_u32(fsm + OFF_QH), aQl = smem_u32(fsm + OFF_QL);
    const uint32_t aKh = smem_u32(fsm + OFF_KH), aKl = smem_u32(fsm + OFF_KL);
    const uint32_t aVh = smem_u32(fsm + OFF_VH), aVl = smem_u32(fsm + OFF_VL);
    const uint32_t aRKh = smem_u32(fsm + OFF_RKH), aRKl = smem_u32(fsm + OFF_RKL);

#pragma unroll
    for (int i = 0; i < 4; i++) {
        int f = tid + i * 256;
        int row = f >> 3, seg = f & 7;
        uint32_t so = (uint32_t)(row * QP + seg * 8) * 2;
        size_t gq = (size_t)(b * LSEQ + bq + row) * DM + h * DK + seg * 8;
        cp_async16(aQh + so, g_Qhi + gq);
        cp_async16(aQl + so, g_Qlo + gq);
    }
    for (int f = tid; f < 384; f += 256) {
        int row = f >> 3, seg = f & 7;
        uint32_t so = (uint32_t)(row * QP + seg * 8) * 2;
        cp_async16(aRKh + so, g_RKhi + row * DK + seg * 8);
        cp_async16(aRKl + so, g_RKlo + row * DK + seg * 8);
    }
    for (int o = tid; o < 128 * 34; o += 256) sWb[o] = 0.f;
    cp_async_wait_all();
    __syncthreads();

    const int a_row = wid * 16 + (lane & 7) + 8 * ((lane >> 3) & 1);
    const int a_kk = 8 * (lane >> 4);
    const int b_row = (lane & 7) + 8 * (lane >> 4);
    const int b_kk = 8 * ((lane >> 3) & 1);
    const int r0 = lane >> 2, c0 = (lane & 3) * 2;
    const int qrow0 = wid * 16 + r0;
    const int q0 = bq + qrow0;

    // ---- sSr = Q . rel_k^T via MMA ----
    {
        float csr[6][4];
#pragma unroll
        for (int nt = 0; nt < 6; nt++)
#pragma unroll
            for (int j = 0; j < 4; j++) csr[nt][j] = 0.f;
#pragma unroll
        for (int ks = 0; ks < 4; ks++) {
            uint32_t ah[4], al[4];
            uint32_t aoff = (uint32_t)(a_row * QP + ks * 16 + a_kk) * 2;
            ldmx4(ah, aQh + aoff);
            ldmx4(al, aQl + aoff);
            uint32_t rbh[12], rbl[12];
#pragma unroll
            for (int p = 0; p < 3; p++) {
                uint32_t boff = (uint32_t)((b_row + p * 16) * QP + ks * 16 + b_kk) * 2;
                ldmx4(rbh + p * 4, aRKh + boff);
                ldmx4(rbl + p * 4, aRKl + boff);
            }
#pragma unroll
            for (int nt = 0; nt < 6; nt++) {
                mma_bf16(csr[nt], ah, rbh[nt * 2], rbh[nt * 2 + 1]);
                mma_bf16(csr[nt], ah, rbl[nt * 2], rbl[nt * 2 + 1]);
                mma_bf16(csr[nt], al, rbh[nt * 2], rbh[nt * 2 + 1]);
            }
        }
#pragma unroll
        for (int nt = 0; nt < 6; nt++) {
#pragma unroll
            for (int j = 0; j < 4; j++) {
                int col = nt * 8 + c0 + (j & 1);
                if (col < 34) {
                    int row = (j < 2) ? qrow0 : qrow0 + 8;
                    sSr[row * 34 + col] = csr[nt][j];
                }
            }
        }
        __syncwarp();
    }

    float m0 = -1e30f, m1 = -1e30f, l0 = 0.f, l1 = 0.f;
    float O[8][4];
#pragma unroll
    for (int nt = 0; nt < 8; nt++)
#pragma unroll
        for (int j = 0; j < 4; j++) O[nt][j] = 0.f;

    for (int kt = 0; kt < 8; kt++) {
        const int k0 = kt * 128;
#pragma unroll
        for (int i = 0; i < 4; i++) {
            int f = tid + i * 256;
            int row = f >> 3, seg = f & 7;
            uint32_t so = (uint32_t)(row * QP + seg * 8) * 2;
            size_t gk = (size_t)(b * LSEQ + k0 + row) * DM + h * DK + seg * 8;
            cp_async16(aKh + so, g_Khi + gk);
            cp_async16(aKl + so, g_Klo + gk);
        }
#pragma unroll
        for (int i = 0; i < 4; i++) {
            int f = tid + i * 256;
            int row = f >> 4, seg = f & 15;
            uint32_t so = (uint32_t)(row * VP + seg * 8) * 2;
            size_t gv = ((size_t)bh * DK + row) * LSEQ + k0 + seg * 8;
            cp_async16(aVh + so, g_Vthi + gv);
            cp_async16(aVl + so, g_Vtlo + gv);
        }
        cp_async_wait_all();
        __syncthreads();

        float c[16][4];
#pragma unroll
        for (int nt = 0; nt < 16; nt++)
#pragma unroll
            for (int j = 0; j < 4; j++) c[nt][j] = 0.f;

#pragma unroll
        for (int ks = 0; ks < 4; ks++) {
            uint32_t ah[4], al[4];
            uint32_t aoff = (uint32_t)(a_row * QP + ks * 16 + a_kk) * 2;
            ldmx4(ah, aQh + aoff);
            ldmx4(al, aQl + aoff);
#pragma unroll
            for (int hh = 0; hh < 2; hh++) {
                uint32_t bhf[16], blf[16];
#pragma unroll
                for (int p = 0; p < 4; p++) {
                    uint32_t boff = (uint32_t)((b_row + hh * 64 + p * 16) * QP + ks * 16 + b_kk) * 2;
                    ldmx4(bhf + p * 4, aKh + boff);
                    ldmx4(blf + p * 4, aKl + boff);
                }
#pragma unroll
                for (int nt = 0; nt < 8; nt++) {
                    float* cc = c[hh * 8 + nt];
                    mma_bf16(cc, ah, bhf[nt * 2], bhf[nt * 2 + 1]);
                    mma_bf16(cc, ah, blf[nt * 2], blf[nt * 2 + 1]);
                    mma_bf16(cc, al, bhf[nt * 2], bhf[nt * 2 + 1]);
                }
            }
        }

        float tm0 = -1e30f, tm1 = -1e30f;
#pragma unroll
        for (int nt = 0; nt < 16; nt++) {
            int kA = k0 + nt * 8 + c0;
#pragma unroll
            for (int j = 0; j < 4; j++) {
                int kk = kA + (j & 1);
                bool low = (j < 2);
                int q = low ? q0 : q0 + 8;
                int lrow = low ? qrow0 : qrow0 + 8;
                int d = kk - q; d = max(-16, min(16, d));
                float s = (c[nt][j] + sSr[lrow * 34 + d + 16]) * 0.125f;
                c[nt][j] = s;
                if (low) tm0 = fmaxf(tm0, s); else tm1 = fmaxf(tm1, s);
            }
        }
        tm0 = fmaxf(tm0, __shfl_xor_sync(0xffffffffu, tm0, 1));
        tm0 = fmaxf(tm0, __shfl_xor_sync(0xffffffffu, tm0, 2));
        tm1 = fmaxf(tm1, __shfl_xor_sync(0xffffffffu, tm1, 1));
        tm1 = fmaxf(tm1, __shfl_xor_sync(0xffffffffu, tm1, 2));
        float nm0 = fmaxf(m0, tm0), nm1 = fmaxf(m1, tm1);
        float f0 = __expf(m0 - nm0), f1 = __expf(m1 - nm1);
        m0 = nm0; m1 = nm1;
        if ((lane & 3) == 0) { sF[qrow0] = f0; sF[qrow0 + 8] = f1; }
        __syncwarp();
        for (int o = lane; o < 16 * 33; o += 32) {
            int rr = o / 33, cc2 = o % 33;
            sWb[(wid * 16 + rr) * 34 + cc2] *= sF[wid * 16 + rr];
        }
        __syncwarp();

        float sum0 = 0.f, sum1 = 0.f, lo0 = 0.f, lo1 = 0.f, hi0 = 0.f, hi1 = 0.f;
#pragma unroll
        for (int nt = 0; nt < 16; nt++) {
#pragma unroll
            for (int j = 0; j < 4; j++) {
                int kk = k0 + nt * 8 + c0 + (j & 1);
                bool low = (j < 2);
                float p = __expf(c[nt][j] - (low ? nm0 : nm1));
                c[nt][j] = p;
                int q = low ? q0 : q0 + 8;
                int d = kk - q;
                if (low) sum0 += p; else sum1 += p;
                if (d <= -16) { if (low) lo0 += p; else lo1 += p; }
                else if (d >= 16) { if (low) hi0 += p; else hi1 += p; }
                else sWb[(low ? qrow0 : qrow0 + 8) * 34 + d + 16] += p;
            }
        }
        sum0 += __shfl_xor_sync(0xffffffffu, sum0, 1);
        sum0 += __shfl_xor_sync(0xffffffffu, sum0, 2);
        sum1 += __shfl_xor_sync(0xffffffffu, sum1, 1);
        sum1 += __shfl_xor_sync(0xffffffffu, sum1, 2);
        lo0 += __shfl_xor_sync(0xffffffffu, lo0, 1);
        lo0 += __shfl_xor_sync(0xffffffffu, lo0, 2);
        lo1 += __shfl_xor_sync(0xffffffffu, lo1, 1);
        lo1 += __shfl_xor_sync(0xffffffffu, lo1, 2);
        hi0 += __shfl_xor_sync(0xffffffffu, hi0, 1);
        hi0 += __shfl_xor_sync(0xffffffffu, hi0, 2);
        hi1 += __shfl_xor_sync(0xffffffffu, hi1, 1);
        hi1 += __shfl_xor_sync(0xffffffffu, hi1, 2);
        l0 = l0 * f0 + sum0;
        l1 = l1 * f1 + sum1;
        if ((lane & 3) == 0) {
            sWb[qrow0 * 34 + 0] += lo0;  sWb[qrow0 * 34 + 32] += hi0;
            sWb[(qrow0 + 8) * 34 + 0] += lo1;  sWb[(qrow0 + 8) * 34 + 32] += hi1;
        }
#pragma unroll
        for (int nt = 0; nt < 8; nt++) {
            O[nt][0] *= f0; O[nt][1] *= f0; O[nt][2] *= f1; O[nt][3] *= f1;
        }

#pragma unroll
        for (int j = 0; j < 8; j++) {
            float x0 = c[2 * j][0], x1 = c[2 * j][1], x2 = c[2 * j][2], x3 = c[2 * j][3];
            float y0 = c[2 * j + 1][0], y1 = c[2 * j + 1][1], y2 = c[2 * j + 1][2], y3 = c[2 * j + 1][3];
            __nv_bfloat16 hx0 = __float2bfloat16(x0), hx1 = __float2bfloat16(x1);
            __nv_bfloat16 hx2 = __float2bfloat16(x2), hx3 = __float2bfloat16(x3);
            __nv_bfloat16 hy0 = __float2bfloat16(y0), hy1 = __float2bfloat16(y1);
            __nv_bfloat16 hy2 = __float2bfloat16(y2), hy3 = __float2bfloat16(y3);
            uint32_t pa[4], pl[4];
            pa[0] = pkbf2(hx0, hx1); pa[1] = pkbf2(hx2, hx3);
            pa[2] = pkbf2(hy0, hy1); pa[3] = pkbf2(hy2, hy3);
            pl[0] = pkbf2(__float2bfloat16(x0 - __bfloat162float(hx0)),
                          __float2bfloat16(x1 - __bfloat162float(hx1)));
            pl[1] = pkbf2(__float2bfloat16(x2 - __bfloat162float(hx2)),
                          __float2bfloat16(x3 - __bfloat162float(hx3)));
            pl[2] = pkbf2(__float2bfloat16(y0 - __bfloat162float(hy0)),
                          __float2bfloat16(y1 - __bfloat162float(hy1)));
            pl[3] = pkbf2(__float2bfloat16(y2 - __bfloat162float(hy2)),
                          __float2bfloat16(y3 - __bfloat162float(hy3)));
            uint32_t vh[16], vl[16];
#pragma unroll
            for (int p = 0; p < 4; p++) {
                uint32_t voff = (uint32_t)((b_row + p * 16) * VP + j * 16 + b_kk) * 2;
                ldmx4(vh + p * 4, aVh + voff);
                ldmx4(vl + p * 4, aVl + voff);
            }
#pragma unroll
            for (int nt = 0; nt < 8; nt++) {
                mma_bf16(O[nt], pa, vh[nt * 2], vh[nt * 2 + 1]);
                mma_bf16(O[nt], pa, vl[nt * 2], vl[nt * 2 + 1]);
                mma_bf16(O[nt], pl, vh[nt * 2], vh[nt * 2 + 1]);
            }
        }
        __syncthreads();
    }

    // ---- epilogue: rank-33 rel_v update, normalize, store as fp16 hi/lo split ----
    float* rv = (float*)(fsm + OFF_KH);
    for (int o = tid; o < NREL * DK; o += 256) rv[o] = rel_v[o];
    __syncthreads();

#pragma unroll 1
    for (int r = 0; r < NREL; r++) {
        float wb0 = sWb[qrow0 * 34 + r];
        float wb1 = sWb[(qrow0 + 8) * 34 + r];
#pragma unroll
        for (int nt = 0; nt < 8; nt++) {
            int d = nt * 8 + c0;
            float rv0 = rv[r * DK + d], rv1 = rv[r * DK + d + 1];
            O[nt][0] += wb0 * rv0; O[nt][1] += wb0 * rv1;
            O[nt][2] += wb1 * rv0; O[nt][3] += wb1 * rv1;
        }
    }
    float inv0 = 1.f / l0, inv1 = 1.f / l1;
    __half* Xh = (__half*)g_Xhi;
    __half* Xl = (__half*)g_Xlo;
    size_t o0 = (size_t)(b * LSEQ + q0) * DM + h * DK;
    size_t o1 = (size_t)(b * LSEQ + q0 + 8) * DM + h * DK;
#pragma unroll
    for (int nt = 0; nt < 8; nt++) {
        int d = nt * 8 + c0;
        float v0 = O[nt][0] * inv0, v1 = O[nt][1] * inv0;
        float v2 = O[nt][2] * inv1, v3 = O[nt][3] * inv1;
        __half h0 = __float2half_rn(v0), h1 = __float2half_rn(v1);
        __half h2 = __float2half_rn(v2), h3 = __float2half_rn(v3);
        *(uint32_t*)(Xh + o0 + d) = pkh2(h0, h1);
        *(uint32_t*)(Xh + o1 + d) = pkh2(h2, h3);
        *(uint32_t*)(Xl + o0 + d) =
            pkh2(__float2half_rn(v0 - __half2float(h0)),
                 __float2half_rn(v1 - __half2float(h1)));
        *(uint32_t*)(Xl + o1 + d) =
            pkh2(__float2half_rn(v2 - __half2float(h2)),
                 __float2half_rn(v3 - __half2float(h3)));
    }
}

// ---------------- reductions ----------------
__device__ __forceinline__ float block_sum(float v, float* red) {
    int lane = threadIdx.x & 31, w = threadIdx.x >> 5;
#pragma unroll
    for (int o = 16; o; o >>= 1) v += __shfl_xor_sync(0xffffffffu, v, o);
    if (lane == 0) red[w] = v;
    __syncthreads();
    if (w == 0) {
        float t = (lane < 8) ? red[lane] : 0.f;
#pragma unroll
        for (int o = 4; o; o >>= 1) t += __shfl_xor_sync(0xffffffffu, t, o);
        if (lane == 0) red[0] = t;
    }
    __syncthreads();
    float r = red[0];
    __syncthreads();
    return r;
}

// ---------------- layernorm (optional fp16 hi/lo outputs) ----------------
__global__ void layernorm_k(const float* __restrict__ X, const float* __restrict__ Res,
                            const float* __restrict__ gam, const float* __restrict__ bet,
                            float* __restrict__ O,
                            __half* __restrict__ Ohi, __half* __restrict__ Olo) {
    int row = blockIdx.x, tid = threadIdx.x;
    __shared__ float red[32];
    float4 v = *(const float4*)(X + (size_t)row * DM + tid * 4);
    if (Res) {
        float4 rr = *(const float4*)(Res + (size_t)row * DM + tid * 4);
        v.x += rr.x; v.y += rr.y; v.z += rr.z; v.w += rr.w;
    }
    float s = block_sum(v.x + v.y + v.z + v.w, red);
    float s2 = block_sum(v.x * v.x + v.y * v.y + v.z * v.z + v.w * v.w, red);
    float mu = s * (1.f / DM);
    float var = s2 * (1.f / DM) - mu * mu;
    float rstd = rsqrtf(var + 1e-6f);
    float4 g4 = *(const float4*)(gam + tid * 4);
    float4 b4 = *(const float4*)(bet + tid * 4);
    float4 o;
    o.x = (v.x - mu) * rstd * g4.x + b4.x;
    o.y = (v.y - mu) * rstd * g4.y + b4.y;
    o.z = (v.z - mu) * rstd * g4.z + b4.z;
    o.w = (v.w - mu) * rstd * g4.w + b4.w;
    if (O) *(float4*)(O + (size_t)row * DM + tid * 4) = o;
    if (Ohi) {
        __half h0 = __float2half_rn(o.x), h1 = __float2half_rn(o.y);
        __half h2 = __float2half_rn(o.z), h3 = __float2half_rn(o.w);
        uint2 ph = make_uint2(pkh2(h0, h1), pkh2(h2, h3));
        uint2 pl = make_uint2(
            pkh2(__float2half_rn(o.x - __half2float(h0)),
                 __float2half_rn(o.y - __half2float(h1))),
            pkh2(__float2half_rn(o.z - __half2float(h2)),
                 __float2half_rn(o.w - __half2float(h3))));
        *(uint2*)(Ohi + (size_t)row * DM + tid * 4) = ph;
        *(uint2*)(Olo + (size_t)row * DM + tid * 4) = pl;
    }
}

// ---------------- launch ----------------
static void* sym_addr(const void* s) { void* p = nullptr; cudaGetSymbolAddress(&p, s); return p; }

extern "C" void kernel_launch(void* const* d_in, const int* in_sizes, int n_in,
                              void* d_out, int out_size) {
    const float* q    = (const float*)d_in[0];
    const float* k    = (const float*)d_in[1];
    const float* v    = (const float*)d_in[2];
    const float* wq   = (const float*)d_in[3];
    const float* bq   = (const float*)d_in[4];
    const float* wk   = (const float*)d_in[5];
    const float* bk   = (const float*)d_in[6];
    const float* wv   = (const float*)d_in[7];
    const float* bv   = (const float*)d_in[8];
    const float* wfc  = (const float*)d_in[9];
    const float* bfc  = (const float*)d_in[10];
    const float* w1   = (const float*)d_in[11];
    const float* b1   = (const float*)d_in[12];
    const float* w2   = (const float*)d_in[13];
    const float* b2   = (const float*)d_in[14];
    const float* ln_g = (const float*)d_in[15];
    const float* ln_b = (const float*)d_in[16];
    const float* relk = (const float*)d_in[17];
    const float* relv = (const float*)d_in[18];
    float* out = (float*)d_out;

    float* pV    = (float*)sym_addr(g_V);
    float* pTmp  = (float*)sym_addr(g_tmp);
    float* pLn1  = (float*)sym_addr(g_ln1);
    float* pT2   = (float*)sym_addr(g_t2);
    float* pBqkv = (float*)sym_addr(g_bqkv);
    __nv_bfloat16* pAhi = (__nv_bfloat16*)sym_addr(g_Ahi);
    __nv_bfloat16* pAlo = (__nv_bfloat16*)sym_addr(g_Alo);
    __nv_bfloat16* pXhi = (__nv_bfloat16*)sym_addr(g_Xhi);
    __nv_bfloat16* pXlo = (__nv_bfloat16*)sym_addr(g_Xlo);
    __nv_bfloat16* pWhi = (__nv_bfloat16*)sym_addr(g_Whi);
    __nv_bfloat16* pWlo = (__nv_bfloat16*)sym_addr(g_Wlo);
    __nv_bfloat16* pVthi = (__nv_bfloat16*)sym_addr(g_Vthi);
    __nv_bfloat16* pVtlo = (__nv_bfloat16*)sym_addr(g_Vtlo);

    cudaFuncSetAttribute(gemm_tc, cudaFuncAttributeMaxDynamicSharedMemorySize, GEMM_SMEM);
    cudaFuncSetAttribute(gemm_fp16, cudaFuncAttributeMaxDynamicSharedMemorySize, GEMM_H_SMEM);
    cudaFuncSetAttribute(flash_attn, cudaFuncAttributeMaxDynamicSharedMemorySize, FLASH_SMEM);

    const int nD4 = ROWS * DM / 4 / 256;
    dim3 tBlk(32, 8);
    dim3 tGridD(DM / 32, DM / 32);
    dim3 tGridW1(DI / 32, DM / 32);
    dim3 tGridW2(DM / 32, DI / 32);
    dim3 gD(DM / 128, ROWS / 128);
    dim3 gI(DI / 128, ROWS / 128);
    dim3 gQKV(3 * DM / 128, ROWS / 128);

    // ---- merged QKV (bf16x3): stacked weights, stacked inputs, concat bias ----
    bias_concat<<<12, 256>>>(bq, bk, bv);
    relk_split<<<12, 256>>>(relk);
    conv_split_T<<<tGridD, tBlk>>>(wq, pWhi, pWlo, DM, DM);
    conv_split_T<<<tGridD, tBlk>>>(wk, pWhi + (size_t)DM * DM, pWlo + (size_t)DM * DM, DM, DM);
    conv_split_T<<<tGridD, tBlk>>>(wv, pWhi + 2 * (size_t)DM * DM, pWlo + 2 * (size_t)DM * DM, DM, DM);
    conv_split<<<nD4, 256>>>(q, pAhi, pAlo);
    conv_split<<<nD4, 256>>>(k, pAhi + (size_t)ROWS * DM, pAlo + (size_t)ROWS * DM);
    conv_split<<<nD4, 256>>>(v, pAhi + 2 * (size_t)ROWS * DM, pAlo + 2 * (size_t)ROWS * DM);
    gemm_tc<<<gQKV, 256, GEMM_SMEM>>>(pAhi, pAlo, pWhi, pWlo, pBqkv, ROWS, 3 * DM, DM);

    // attention prep
    dim3 gvt(LSEQ / 32, DK / 32, BHN);
    vt_split<<<gvt, tBlk>>>(pV, pVthi, pVtlo);

    // fused flash attention -> attn fp16 split into g_Xhi/g_Xlo
    dim3 gfa(LSEQ / 128, BHN);
    flash_attn<<<gfa, 256, FLASH_SMEM>>>(relv);

    // out-proj (fp16 2-pass) + LN1 (emits fp16 split for FFN1)
    conv_T_h<<<tGridD, tBlk>>>(wfc, (__half*)pWhi, DM, DM);
    gemm_fp16<<<gD, 256, GEMM_H_SMEM>>>((const __half*)pXhi, (const __half*)pXlo,
                                        (const __half*)pWhi, bfc, pTmp, nullptr, nullptr,
                                        ROWS, DM, DM, 0);
    layernorm_k<<<ROWS, 256>>>(pTmp, q, ln_g, ln_b, pLn1, (__half*)pXhi, (__half*)pXlo);

    // FFN (fp16 2-pass)
    conv_T_h<<<tGridW1, tBlk>>>(w1, (__half*)pWhi, DM, DI);
    gemm_fp16<<<gI, 256, GEMM_H_SMEM>>>((const __half*)pXhi, (const __half*)pXlo,
                                        (const __half*)pWhi, b1, nullptr,
                                        (__half*)pAhi, (__half*)pAlo, ROWS, DI, DM, 1);

    conv_T_h<<<tGridW2, tBlk>>>(w2, (__half*)pWhi, DI, DM);
    gemm_fp16<<<gD, 256, GEMM_H_SMEM>>>((const __half*)pAhi, (const __half*)pAlo,
                                        (const __half*)pWhi, b2, pT2, nullptr, nullptr,
                                        ROWS, DM, DI, 0);
    layernorm_k<<<ROWS, 256>>>(pT2, pLn1, ln_g, ln_b, out, nullptr, nullptr);
}

// round 11
// speedup vs baseline: 4.8837x; 1.1006x over previous
#include <cuda_runtime.h>
#include <cuda_bf16.h>
#include <cuda_fp16.h>
#include <cstdint>

#define LSEQ 1024
#define DM   1024
#define BATCH 8
#define NH   16
#define DK   64
#define BHN  (BATCH*NH)     // 128
#define NREL 33
#define DI   4096
#define ROWS (BATCH*LSEQ)   // 8192

// ---------------- scratch (static device arrays; no allocation) ----------------
__device__ float g_V[ROWS*DM];
__device__ float g_tmp[ROWS*DM];
__device__ float g_ln1[ROWS*DM];
__device__ float g_t2[ROWS*DM];
__device__ float g_bqkv[3*DM];
// 2-byte buffers (bf16 or fp16 by phase; sized for the largest use)
__device__ __nv_bfloat16 g_Ahi[(size_t)ROWS*DI];    // stacked QKV inputs / h1 split
__device__ __nv_bfloat16 g_Alo[(size_t)ROWS*DI];
__device__ __nv_bfloat16 g_Xhi[ROWS*DM];            // current activation split
__device__ __nv_bfloat16 g_Xlo[ROWS*DM];
__device__ __nv_bfloat16 g_Whi[(size_t)DM*DI];      // weights (fp16 single, stacked for QKV)
__device__ __nv_bfloat16 g_Qhi[ROWS*DM];
__device__ __nv_bfloat16 g_Qlo[ROWS*DM];
__device__ __nv_bfloat16 g_Khi[ROWS*DM];
__device__ __nv_bfloat16 g_Klo[ROWS*DM];
__device__ __nv_bfloat16 g_Vth[(size_t)BHN*DK*LSEQ];    // [bh][d][k] fp16 single
__device__ __nv_bfloat16 g_RKhi[48*DK];             // rel_k split, padded to 48 rows
__device__ __nv_bfloat16 g_RKlo[48*DK];

// ---------------- helpers ----------------
__device__ __forceinline__ uint32_t smem_u32(const void* p) {
    uint32_t a;
    asm("{ .reg .u64 t; cvta.to.shared.u64 t, %1; cvt.u32.u64 %0, t; }" : "=r"(a) : "l"(p));
    return a;
}
__device__ __forceinline__ void cp_async16(uint32_t saddr, const void* gaddr) {
    asm volatile("cp.async.cg.shared.global [%0], [%1], 16;" :: "r"(saddr), "l"(gaddr));
}
__device__ __forceinline__ void cp_commit() {
    asm volatile("cp.async.commit_group;" ::: "memory");
}
__device__ __forceinline__ void cp_wait1() {
    asm volatile("cp.async.wait_group 1;" ::: "memory");
}
__device__ __forceinline__ void cp_wait0() {
    asm volatile("cp.async.wait_group 0;" ::: "memory");
}
__device__ __forceinline__ void cp_async_wait_all() {
    asm volatile("cp.async.commit_group;\ncp.async.wait_group 0;" ::: "memory");
}
__device__ __forceinline__ void ldmx4(uint32_t* r, uint32_t addr) {
    asm volatile("ldmatrix.sync.aligned.m8n8.x4.shared.b16 {%0,%1,%2,%3}, [%4];"
        : "=r"(r[0]), "=r"(r[1]), "=r"(r[2]), "=r"(r[3]) : "r"(addr));
}
__device__ __forceinline__ void mma_bf16(float* c, const uint32_t* a, uint32_t b0, uint32_t b1) {
    asm volatile(
        "mma.sync.aligned.m16n8k16.row.col.f32.bf16.bf16.f32 "
        "{%0,%1,%2,%3}, {%4,%5,%6,%7}, {%8,%9}, {%0,%1,%2,%3};"
        : "+f"(c[0]), "+f"(c[1]), "+f"(c[2]), "+f"(c[3])
        : "r"(a[0]), "r"(a[1]), "r"(a[2]), "r"(a[3]), "r"(b0), "r"(b1));
}
__device__ __forceinline__ void mma_f16(float* c, const uint32_t* a, uint32_t b0, uint32_t b1) {
    asm volatile(
        "mma.sync.aligned.m16n8k16.row.col.f32.f16.f16.f32 "
        "{%0,%1,%2,%3}, {%4,%5,%6,%7}, {%8,%9}, {%0,%1,%2,%3};"
        : "+f"(c[0]), "+f"(c[1]), "+f"(c[2]), "+f"(c[3])
        : "r"(a[0]), "r"(a[1]), "r"(a[2]), "r"(a[3]), "r"(b0), "r"(b1));
}
__device__ __forceinline__ uint32_t pkbf2(__nv_bfloat16 lo, __nv_bfloat16 hi) {
    __nv_bfloat162 t(lo, hi);
    return *(uint32_t*)&t;
}
__device__ __forceinline__ uint32_t pkh2(__half lo, __half hi) {
    __half2 t(lo, hi);
    return *(uint32_t*)&t;
}

// ---------------- conversion kernels ----------------
// fp32 -> fp16 exact hi/lo pair
__global__ void conv_split_h(const float* __restrict__ X, __half* __restrict__ hi,
                             __half* __restrict__ lo) {
    int i = blockIdx.x * blockDim.x + threadIdx.x;
    float4 v = ((const float4*)X)[i];
    __half h[4], l[4];
    float xs[4] = {v.x, v.y, v.z, v.w};
#pragma unroll
    for (int j = 0; j < 4; j++) {
        h[j] = __float2half_rn(xs[j]);
        l[j] = __float2half_rn(xs[j] - __half2float(h[j]));
    }
    *(uint2*)(hi + (size_t)i * 4) = *(uint2*)h;
    *(uint2*)(lo + (size_t)i * 4) = *(uint2*)l;
}

// W[K,N] -> fp16 single T [N,K]
__global__ void conv_T_h(const float* __restrict__ W, __half* __restrict__ hT, int K, int N) {
    __shared__ float t[32][33];
    int n0 = blockIdx.x * 32, k0 = blockIdx.y * 32;
    int tx = threadIdx.x, ty = threadIdx.y;
    for (int i = ty; i < 32; i += 8)
        t[i][tx] = W[(size_t)(k0 + i) * N + n0 + tx];
    __syncthreads();
    for (int r = ty; r < 32; r += 8)
        hT[(size_t)(n0 + r) * K + k0 + tx] = __float2half_rn(t[tx][r]);
}

// V [b*L+k][h*64+d] -> Vt [bh][d][k] fp16 single
__global__ void vt_split_h(const float* __restrict__ V, __half* __restrict__ hT) {
    __shared__ float t[32][33];
    int bh = blockIdx.z, b = bh >> 4, h = bh & 15;
    int k0 = blockIdx.x * 32, d0 = blockIdx.y * 32;
    int tx = threadIdx.x, ty = threadIdx.y;
    for (int i = ty; i < 32; i += 8)
        t[i][tx] = V[(size_t)(b * LSEQ + k0 + i) * DM + h * DK + d0 + tx];
    __syncthreads();
    for (int r = ty; r < 32; r += 8)
        hT[((size_t)bh * DK + d0 + r) * LSEQ + k0 + tx] = __float2half_rn(t[tx][r]);
}

// rel_k [33,64] -> padded [48,64] bf16 hi/lo
__global__ void relk_split(const float* __restrict__ rel_k) {
    int i = blockIdx.x * 256 + threadIdx.x;   // 0..3071
    int r = i >> 6;
    float x = (r < NREL) ? rel_k[i] : 0.f;
    __nv_bfloat16 h = __float2bfloat16(x);
    g_RKhi[i] = h;
    g_RKlo[i] = __float2bfloat16(x - __bfloat162float(h));
}

__global__ void bias_concat(const float* __restrict__ b0, const float* __restrict__ b1,
                            const float* __restrict__ b2) {
    int i = blockIdx.x * 256 + threadIdx.x;   // 0..3071
    g_bqkv[i] = (i < DM) ? b0[i] : ((i < 2 * DM) ? b1[i - DM] : b2[i - 2 * DM]);
}

#define SPAD 40
#define GSTAGE_H 30720          // 3 arrays x 10240
#define GEMM_H_SMEM (2 * GSTAGE_H)

// ---------------- fp16 2-pass QKV GEMM (stacked segments) ----------------
// A = x exact fp16 hi/lo; B = W single fp16. Epilogue: seg0->Qhi/lo(bf16),
// seg1->Khi/lo(bf16), seg2->fp32 g_V.
__global__ __launch_bounds__(256, 2) void gemm_qkv_h(
    const __half* __restrict__ Ahi, const __half* __restrict__ Alo,
    const __half* __restrict__ Bh, const float* __restrict__ bias)
{
    extern __shared__ char gsm[];
    const uint32_t base = smem_u32(gsm);

    const int tid = threadIdx.x;
    const int wid = tid >> 5, lane = tid & 31;
    const int wm = wid >> 2, wn = wid & 3;
    const int bm = blockIdx.y * 128, bn = blockIdx.x * 128;

    const int seg = bn >> 10;
    const int bnl = bn & (DM - 1);
    Ahi += (size_t)seg * ROWS * DM;
    Alo += (size_t)seg * ROWS * DM;
    Bh  += (size_t)seg * DM * DM;

    float c[4][4][4];
#pragma unroll
    for (int mt = 0; mt < 4; mt++)
#pragma unroll
        for (int nt = 0; nt < 4; nt++)
#pragma unroll
            for (int r = 0; r < 4; r++) c[mt][nt][r] = 0.f;

    const int a_m_base = wm * 64 + (lane & 7) + 8 * ((lane >> 3) & 1);
    const int a_kk = 8 * (lane >> 4);
    const int b_n_base = wn * 32 + (lane & 7) + 8 * (lane >> 4);
    const int b_kk = 8 * ((lane >> 3) & 1);

    const int ktiles = DM >> 5;

    auto load_tile = [&](int t, int s) {
        const int kbase = t * 32;
        const uint32_t sb = base + s * GSTAGE_H;
#pragma unroll
        for (int i = 0; i < 2; i++) {
            int f = tid + i * 256;
            int row = f >> 2, seg2 = f & 3;
            uint32_t so = (uint32_t)(row * SPAD + seg2 * 8) * 2;
            size_t ga = (size_t)(bm + row) * DM + kbase + seg2 * 8;
            size_t gb = (size_t)(bnl + row) * DM + kbase + seg2 * 8;
            cp_async16(sb + so, Ahi + ga);
            cp_async16(sb + 10240 + so, Alo + ga);
            cp_async16(sb + 20480 + so, Bh + gb);
        }
        cp_commit();
    };

    load_tile(0, 0);
    for (int t = 0; t < ktiles; t++) {
        if (t + 1 < ktiles) {
            load_tile(t + 1, (t + 1) & 1);
            cp_wait1();
        } else {
            cp_wait0();
        }
        __syncthreads();

        const uint32_t sb = base + (t & 1) * GSTAGE_H;
        const uint32_t aAh = sb, aAl = sb + 10240, aBh = sb + 20480;
#pragma unroll
        for (int kh = 0; kh < 2; kh++) {
            const int k0 = kh * 16;
            uint32_t bh[8];
#pragma unroll
            for (int p = 0; p < 2; p++) {
                uint32_t off = (uint32_t)((b_n_base + p * 16) * SPAD + k0 + b_kk) * 2;
                ldmx4(bh + p * 4, aBh + off);
            }
#pragma unroll
            for (int mt = 0; mt < 4; mt++) {
                uint32_t ah[4], al[4];
                uint32_t off = (uint32_t)((a_m_base + mt * 16) * SPAD + k0 + a_kk) * 2;
                ldmx4(ah, aAh + off);
                ldmx4(al, aAl + off);
#pragma unroll
                for (int nt = 0; nt < 4; nt++) {
                    mma_f16(c[mt][nt], ah, bh[nt * 2], bh[nt * 2 + 1]);
                    mma_f16(c[mt][nt], al, bh[nt * 2], bh[nt * 2 + 1]);
                }
            }
        }
        __syncthreads();
    }

    const int r0 = lane >> 2, c0 = (lane & 3) * 2;
#pragma unroll
    for (int mt = 0; mt < 4; mt++) {
        int row = bm + wm * 64 + mt * 16 + r0;
#pragma unroll
        for (int nt = 0; nt < 4; nt++) {
            int col = bn + wn * 32 + nt * 8 + c0;
            float b0v = bias[col], b1v = bias[col + 1];
            float v0 = c[mt][nt][0] + b0v, v1 = c[mt][nt][1] + b1v;
            float v2 = c[mt][nt][2] + b0v, v3 = c[mt][nt][3] + b1v;
            int coll = bnl + wn * 32 + nt * 8 + c0;
            if (seg == 2) {
                *(float2*)(g_V + (size_t)row * DM + coll) = make_float2(v0, v1);
                *(float2*)(g_V + (size_t)(row + 8) * DM + coll) = make_float2(v2, v3);
            } else {
                __nv_bfloat16* dh = (seg == 0) ? g_Qhi : g_Khi;
                __nv_bfloat16* dl = (seg == 0) ? g_Qlo : g_Klo;
                __nv_bfloat16 h0 = __float2bfloat16(v0), h1 = __float2bfloat16(v1);
                __nv_bfloat16 h2 = __float2bfloat16(v2), h3 = __float2bfloat16(v3);
                *(uint32_t*)(dh + (size_t)row * DM + coll) = pkbf2(h0, h1);
                *(uint32_t*)(dh + (size_t)(row + 8) * DM + coll) = pkbf2(h2, h3);
                *(uint32_t*)(dl + (size_t)row * DM + coll) =
                    pkbf2(__float2bfloat16(v0 - __bfloat162float(h0)),
                          __float2bfloat16(v1 - __bfloat162float(h1)));
                *(uint32_t*)(dl + (size_t)(row + 8) * DM + coll) =
                    pkbf2(__float2bfloat16(v2 - __bfloat162float(h2)),
                          __float2bfloat16(v3 - __bfloat162float(h3)));
            }
        }
    }
}

// ---------------- fp16 2-pass GEMM (A exact hi/lo fp16, B single fp16) ----------------
__global__ __launch_bounds__(256, 2) void gemm_fp16(
    const __half* __restrict__ Ahi, const __half* __restrict__ Alo,
    const __half* __restrict__ Bh,
    const float* __restrict__ bias, float* __restrict__ C,
    __half* __restrict__ Chi, __half* __restrict__ Clo,
    int M, int N, int K, int relu)
{
    extern __shared__ char gsm[];
    const uint32_t base = smem_u32(gsm);

    const int tid = threadIdx.x;
    const int wid = tid >> 5, lane = tid & 31;
    const int wm = wid >> 2, wn = wid & 3;
    const int bm = blockIdx.y * 128, bn = blockIdx.x * 128;

    float c[4][4][4];
#pragma unroll
    for (int mt = 0; mt < 4; mt++)
#pragma unroll
        for (int nt = 0; nt < 4; nt++)
#pragma unroll
            for (int r = 0; r < 4; r++) c[mt][nt][r] = 0.f;

    const int a_m_base = wm * 64 + (lane & 7) + 8 * ((lane >> 3) & 1);
    const int a_kk = 8 * (lane >> 4);
    const int b_n_base = wn * 32 + (lane & 7) + 8 * (lane >> 4);
    const int b_kk = 8 * ((lane >> 3) & 1);

    const int ktiles = K >> 5;

    auto load_tile = [&](int t, int s) {
        const int kbase = t * 32;
        const uint32_t sb = base + s * GSTAGE_H;
#pragma unroll
        for (int i = 0; i < 2; i++) {
            int f = tid + i * 256;
            int row = f >> 2, seg2 = f & 3;
            uint32_t so = (uint32_t)(row * SPAD + seg2 * 8) * 2;
            size_t ga = (size_t)(bm + row) * K + kbase + seg2 * 8;
            size_t gb = (size_t)(bn + row) * K + kbase + seg2 * 8;
            cp_async16(sb + so, Ahi + ga);
            cp_async16(sb + 10240 + so, Alo + ga);
            cp_async16(sb + 20480 + so, Bh + gb);
        }
        cp_commit();
    };

    load_tile(0, 0);
    for (int t = 0; t < ktiles; t++) {
        if (t + 1 < ktiles) {
            load_tile(t + 1, (t + 1) & 1);
            cp_wait1();
        } else {
            cp_wait0();
        }
        __syncthreads();

        const uint32_t sb = base + (t & 1) * GSTAGE_H;
        const uint32_t aAh = sb, aAl = sb + 10240, aBh = sb + 20480;
#pragma unroll
        for (int kh = 0; kh < 2; kh++) {
            const int k0 = kh * 16;
            uint32_t bh[8];
#pragma unroll
            for (int p = 0; p < 2; p++) {
                uint32_t off = (uint32_t)((b_n_base + p * 16) * SPAD + k0 + b_kk) * 2;
                ldmx4(bh + p * 4, aBh + off);
            }
#pragma unroll
            for (int mt = 0; mt < 4; mt++) {
                uint32_t ah[4], al[4];
                uint32_t off = (uint32_t)((a_m_base + mt * 16) * SPAD + k0 + a_kk) * 2;
                ldmx4(ah, aAh + off);
                ldmx4(al, aAl + off);
#pragma unroll
                for (int nt = 0; nt < 4; nt++) {
                    mma_f16(c[mt][nt], ah, bh[nt * 2], bh[nt * 2 + 1]);
                    mma_f16(c[mt][nt], al, bh[nt * 2], bh[nt * 2 + 1]);
                }
            }
        }
        __syncthreads();
    }

    const int r0 = lane >> 2, c0 = (lane & 3) * 2;
#pragma unroll
    for (int mt = 0; mt < 4; mt++) {
        int row = bm + wm * 64 + mt * 16 + r0;
#pragma unroll
        for (int nt = 0; nt < 4; nt++) {
            int col = bn + wn * 32 + nt * 8 + c0;
            float b0v = bias[col], b1v = bias[col + 1];
            float v0 = c[mt][nt][0] + b0v, v1 = c[mt][nt][1] + b1v;
            float v2 = c[mt][nt][2] + b0v, v3 = c[mt][nt][3] + b1v;
            if (relu) {
                v0 = fmaxf(v0, 0.f); v1 = fmaxf(v1, 0.f);
                v2 = fmaxf(v2, 0.f); v3 = fmaxf(v3, 0.f);
            }
            if (C) {
                *(float2*)(C + (size_t)row * N + col) = make_float2(v0, v1);
                *(float2*)(C + (size_t)(row + 8) * N + col) = make_float2(v2, v3);
            }
            if (Chi) {
                __half h0 = __float2half_rn(v0), h1 = __float2half_rn(v1);
                __half h2 = __float2half_rn(v2), h3 = __float2half_rn(v3);
                *(uint32_t*)(Chi + (size_t)row * N + col) = pkh2(h0, h1);
                *(uint32_t*)(Chi + (size_t)(row + 8) * N + col) = pkh2(h2, h3);
                *(uint32_t*)(Clo + (size_t)row * N + col) =
                    pkh2(__float2half_rn(v0 - __half2float(h0)),
                         __float2half_rn(v1 - __half2float(h1)));
                *(uint32_t*)(Clo + (size_t)(row + 8) * N + col) =
                    pkh2(__float2half_rn(v2 - __half2float(h2)),
                         __float2half_rn(v3 - __half2float(h3)));
            }
        }
    }
}

// ---------------- fused flash attention ----------------
// Scores: bf16x3 (Q,K hi/lo). PV: fp16 single P x fp16 single Vt.
#define QP 72
#define VP 136
#define OFF_QH 0
#define OFF_QL 18432
#define OFF_KH 36864
#define OFF_KL 55296
#define OFF_VH 73728
#define OFF_WB 91136
#define OFF_SR 108544
#define OFF_F  125952
#define OFF_RKH 126464
#define OFF_RKL 133376
#define FLASH_SMEM 140288

__global__ __launch_bounds__(256, 1) void flash_attn(const float* __restrict__ rel_v) {
    extern __shared__ char fsm[];
    float* sWb = (float*)(fsm + OFF_WB);    // [128][34]
    float* sSr = (float*)(fsm + OFF_SR);    // [128][34]
    float* sF  = (float*)(fsm + OFF_F);     // [128]

    const int tid = threadIdx.x;
    const int wid = tid >> 5, lane = tid & 31;
    const int bh = blockIdx.y, b = bh >> 4, h = bh & 15;
    const int bq = blockIdx.x * 128;

    const uint32_t aQh = smem_u32(fsm + OFF_QH), aQl = smem_u32(fsm + OFF_QL);
    const uint32_t aKh = smem_u32(fsm + OFF_KH), aKl = smem_u32(fsm + OFF_KL);
    const uint32_t aVh = smem_u32(fsm + OFF_VH);
    const uint32_t aRKh = smem_u32(fsm + OFF_RKH), aRKl = smem_u32(fsm + OFF_RKL);

#pragma unroll
    for (int i = 0; i < 4; i++) {
        int f = tid + i * 256;
        int row = f >> 3, seg = f & 7;
        uint32_t so = (uint32_t)(row * QP + seg * 8) * 2;
        size_t gq = (size_t)(b * LSEQ + bq + row) * DM + h * DK + seg * 8;
        cp_async16(aQh + so, g_Qhi + gq);
        cp_async16(aQl + so, g_Qlo + gq);
    }
    for (int f = tid; f < 384; f += 256) {
        int row = f >> 3, seg = f & 7;
        uint32_t so = (uint32_t)(row * QP + seg * 8) * 2;
        cp_async16(aRKh + so, g_RKhi + row * DK + seg * 8);
        cp_async16(aRKl + so, g_RKlo + row * DK + seg * 8);
    }
    for (int o = tid; o < 128 * 34; o += 256) sWb[o] = 0.f;
    cp_async_wait_all();
    __syncthreads();

    const int a_row = wid * 16 + (lane & 7) + 8 * ((lane >> 3) & 1);
    const int a_kk = 8 * (lane >> 4);
    const int b_row = (lane & 7) + 8 * (lane >> 4);
    const int b_kk = 8 * ((lane >> 3) & 1);
    const int r0 = lane >> 2, c0 = (lane & 3) * 2;
    const int qrow0 = wid * 16 + r0;
    const int q0 = bq + qrow0;

    // ---- sSr = Q . rel_k^T via MMA ----
    {
        float csr[6][4];
#pragma unroll
        for (int nt = 0; nt < 6; nt++)
#pragma unroll
            for (int j = 0; j < 4; j++) csr[nt][j] = 0.f;
#pragma unroll
        for (int ks = 0; ks < 4; ks++) {
            uint32_t ah[4], al[4];
            uint32_t aoff = (uint32_t)(a_row * QP + ks * 16 + a_kk) * 2;
            ldmx4(ah, aQh + aoff);
            ldmx4(al, aQl + aoff);
            uint32_t rbh[12], rbl[12];
#pragma unroll
            for (int p = 0; p < 3; p++) {
                uint32_t boff = (uint32_t)((b_row + p * 16) * QP + ks * 16 + b_kk) * 2;
                ldmx4(rbh + p * 4, aRKh + boff);
                ldmx4(rbl + p * 4, aRKl + boff);
            }
#pragma unroll
            for (int nt = 0; nt < 6; nt++) {
                mma_bf16(csr[nt], ah, rbh[nt * 2], rbh[nt * 2 + 1]);
                mma_bf16(csr[nt], ah, rbl[nt * 2], rbl[nt * 2 + 1]);
                mma_bf16(csr[nt], al, rbh[nt * 2], rbh[nt * 2 + 1]);
            }
        }
#pragma unroll
        for (int nt = 0; nt < 6; nt++) {
#pragma unroll
            for (int j = 0; j < 4; j++) {
                int col = nt * 8 + c0 + (j & 1);
                if (col < 34) {
                    int row = (j < 2) ? qrow0 : qrow0 + 8;
                    sSr[row * 34 + col] = csr[nt][j];
                }
            }
        }
        __syncwarp();
    }

    float m0 = -1e30f, m1 = -1e30f, l0 = 0.f, l1 = 0.f;
    float O[8][4];
#pragma unroll
    for (int nt = 0; nt < 8; nt++)
#pragma unroll
        for (int j = 0; j < 4; j++) O[nt][j] = 0.f;

    const __half* Vth = (const __half*)g_Vth;

    for (int kt = 0; kt < 8; kt++) {
        const int k0 = kt * 128;
#pragma unroll
        for (int i = 0; i < 4; i++) {
            int f = tid + i * 256;
            int row = f >> 3, seg = f & 7;
            uint32_t so = (uint32_t)(row * QP + seg * 8) * 2;
            size_t gk = (size_t)(b * LSEQ + k0 + row) * DM + h * DK + seg * 8;
            cp_async16(aKh + so, g_Khi + gk);
            cp_async16(aKl + so, g_Klo + gk);
        }
#pragma unroll
        for (int i = 0; i < 4; i++) {
            int f = tid + i * 256;
            int row = f >> 4, seg = f & 15;
            uint32_t so = (uint32_t)(row * VP + seg * 8) * 2;
            size_t gv = ((size_t)bh * DK + row) * LSEQ + k0 + seg * 8;
            cp_async16(aVh + so, Vth + gv);
        }
        cp_async_wait_all();
        __syncthreads();

        float c[16][4];
#pragma unroll
        for (int nt = 0; nt < 16; nt++)
#pragma unroll
            for (int j = 0; j < 4; j++) c[nt][j] = 0.f;

#pragma unroll
        for (int ks = 0; ks < 4; ks++) {
            uint32_t ah[4], al[4];
            uint32_t aoff = (uint32_t)(a_row * QP + ks * 16 + a_kk) * 2;
            ldmx4(ah, aQh + aoff);
            ldmx4(al, aQl + aoff);
#pragma unroll
            for (int hh = 0; hh < 2; hh++) {
                uint32_t bhf[16], blf[16];
#pragma unroll
                for (int p = 0; p < 4; p++) {
                    uint32_t boff = (uint32_t)((b_row + hh * 64 + p * 16) * QP + ks * 16 + b_kk) * 2;
                    ldmx4(bhf + p * 4, aKh + boff);
                    ldmx4(blf + p * 4, aKl + boff);
                }
#pragma unroll
                for (int nt = 0; nt < 8; nt++) {
                    float* cc = c[hh * 8 + nt];
                    mma_bf16(cc, ah, bhf[nt * 2], bhf[nt * 2 + 1]);
                    mma_bf16(cc, ah, blf[nt * 2], blf[nt * 2 + 1]);
                    mma_bf16(cc, al, bhf[nt * 2], bhf[nt * 2 + 1]);
                }
            }
        }

        float tm0 = -1e30f, tm1 = -1e30f;
#pragma unroll
        for (int nt = 0; nt < 16; nt++) {
            int kA = k0 + nt * 8 + c0;
#pragma unroll
            for (int j = 0; j < 4; j++) {
                int kk = kA + (j & 1);
                bool low = (j < 2);
                int q = low ? q0 : q0 + 8;
                int lrow = low ? qrow0 : qrow0 + 8;
                int d = kk - q; d = max(-16, min(16, d));
                float s = (c[nt][j] + sSr[lrow * 34 + d + 16]) * 0.125f;
                c[nt][j] = s;
                if (low) tm0 = fmaxf(tm0, s); else tm1 = fmaxf(tm1, s);
            }
        }
        tm0 = fmaxf(tm0, __shfl_xor_sync(0xffffffffu, tm0, 1));
        tm0 = fmaxf(tm0, __shfl_xor_sync(0xffffffffu, tm0, 2));
        tm1 = fmaxf(tm1, __shfl_xor_sync(0xffffffffu, tm1, 1));
        tm1 = fmaxf(tm1, __shfl_xor_sync(0xffffffffu, tm1, 2));
        float nm0 = fmaxf(m0, tm0), nm1 = fmaxf(m1, tm1);
        float f0 = __expf(m0 - nm0), f1 = __expf(m1 - nm1);
        m0 = nm0; m1 = nm1;
        if ((lane & 3) == 0) { sF[qrow0] = f0; sF[qrow0 + 8] = f1; }
        __syncwarp();
        for (int o = lane; o < 16 * 33; o += 32) {
            int rr = o / 33, cc2 = o % 33;
            sWb[(wid * 16 + rr) * 34 + cc2] *= sF[wid * 16 + rr];
        }
        __syncwarp();

        float sum0 = 0.f, sum1 = 0.f, lo0 = 0.f, lo1 = 0.f, hi0 = 0.f, hi1 = 0.f;
#pragma unroll
        for (int nt = 0; nt < 16; nt++) {
#pragma unroll
            for (int j = 0; j < 4; j++) {
                int kk = k0 + nt * 8 + c0 + (j & 1);
                bool low = (j < 2);
                float p = __expf(c[nt][j] - (low ? nm0 : nm1));
                c[nt][j] = p;
                int q = low ? q0 : q0 + 8;
                int d = kk - q;
                if (low) sum0 += p; else sum1 += p;
                if (d <= -16) { if (low) lo0 += p; else lo1 += p; }
                else if (d >= 16) { if (low) hi0 += p; else hi1 += p; }
                else sWb[(low ? qrow0 : qrow0 + 8) * 34 + d + 16] += p;
            }
        }
        sum0 += __shfl_xor_sync(0xffffffffu, sum0, 1);
        sum0 += __shfl_xor_sync(0xffffffffu, sum0, 2);
        sum1 += __shfl_xor_sync(0xffffffffu, sum1, 1);
        sum1 += __shfl_xor_sync(0xffffffffu, sum1, 2);
        lo0 += __shfl_xor_sync(0xffffffffu, lo0, 1);
        lo0 += __shfl_xor_sync(0xffffffffu, lo0, 2);
        lo1 += __shfl_xor_sync(0xffffffffu, lo1, 1);
        lo1 += __shfl_xor_sync(0xffffffffu, lo1, 2);
        hi0 += __shfl_xor_sync(0xffffffffu, hi0, 1);
        hi0 += __shfl_xor_sync(0xffffffffu, hi0, 2);
        hi1 += __shfl_xor_sync(0xffffffffu, hi1, 1);
        hi1 += __shfl_xor_sync(0xffffffffu, hi1, 2);
        l0 = l0 * f0 + sum0;
        l1 = l1 * f1 + sum1;
        if ((lane & 3) == 0) {
            sWb[qrow0 * 34 + 0] += lo0;  sWb[qrow0 * 34 + 32] += hi0;
            sWb[(qrow0 + 8) * 34 + 0] += lo1;  sWb[(qrow0 + 8) * 34 + 32] += hi1;
        }
#pragma unroll
        for (int nt = 0; nt < 8; nt++) {
            O[nt][0] *= f0; O[nt][1] *= f0; O[nt][2] *= f1; O[nt][3] *= f1;
        }

        // ---- PV: P rounded to fp16 single, Vt fp16 single, 1 MMA pass ----
#pragma unroll
        for (int j = 0; j < 8; j++) {
            uint32_t pa[4];
            pa[0] = pkh2(__float2half_rn(c[2 * j][0]), __float2half_rn(c[2 * j][1]));
            pa[1] = pkh2(__float2half_rn(c[2 * j][2]), __float2half_rn(c[2 * j][3]));
            pa[2] = pkh2(__float2half_rn(c[2 * j + 1][0]), __float2half_rn(c[2 * j + 1][1]));
            pa[3] = pkh2(__float2half_rn(c[2 * j + 1][2]), __float2half_rn(c[2 * j + 1][3]));
            uint32_t vh[16];
#pragma unroll
            for (int p = 0; p < 4; p++) {
                uint32_t voff = (uint32_t)((b_row + p * 16) * VP + j * 16 + b_kk) * 2;
                ldmx4(vh + p * 4, aVh + voff);
            }
#pragma unroll
            for (int nt = 0; nt < 8; nt++)
                mma_f16(O[nt], pa, vh[nt * 2], vh[nt * 2 + 1]);
        }
        __syncthreads();
    }

    // ---- epilogue: rank-33 rel_v update, normalize, store as fp16 hi/lo split ----
    float* rv = (float*)(fsm + OFF_KH);
    for (int o = tid; o < NREL * DK; o += 256) rv[o] = rel_v[o];
    __syncthreads();

#pragma unroll 1
    for (int r = 0; r < NREL; r++) {
        float wb0 = sWb[qrow0 * 34 + r];
        float wb1 = sWb[(qrow0 + 8) * 34 + r];
#pragma unroll
        for (int nt = 0; nt < 8; nt++) {
            int d = nt * 8 + c0;
            float rv0 = rv[r * DK + d], rv1 = rv[r * DK + d + 1];
            O[nt][0] += wb0 * rv0; O[nt][1] += wb0 * rv1;
            O[nt][2] += wb1 * rv0; O[nt][3] += wb1 * rv1;
        }
    }
    float inv0 = 1.f / l0, inv1 = 1.f / l1;
    __half* Xh = (__half*)g_Xhi;
    __half* Xl = (__half*)g_Xlo;
    size_t o0 = (size_t)(b * LSEQ + q0) * DM + h * DK;
    size_t o1 = (size_t)(b * LSEQ + q0 + 8) * DM + h * DK;
#pragma unroll
    for (int nt = 0; nt < 8; nt++) {
        int d = nt * 8 + c0;
        float v0 = O[nt][0] * inv0, v1 = O[nt][1] * inv0;
        float v2 = O[nt][2] * inv1, v3 = O[nt][3] * inv1;
        __half h0 = __float2half_rn(v0), h1 = __float2half_rn(v1);
        __half h2 = __float2half_rn(v2), h3 = __float2half_rn(v3);
        *(uint32_t*)(Xh + o0 + d) = pkh2(h0, h1);
        *(uint32_t*)(Xh + o1 + d) = pkh2(h2, h3);
        *(uint32_t*)(Xl + o0 + d) =
            pkh2(__float2half_rn(v0 - __half2float(h0)),
                 __float2half_rn(v1 - __half2float(h1)));
        *(uint32_t*)(Xl + o1 + d) =
            pkh2(__float2half_rn(v2 - __half2float(h2)),
                 __float2half_rn(v3 - __half2float(h3)));
    }
}

// ---------------- reductions ----------------
__device__ __forceinline__ float block_sum(float v, float* red) {
    int lane = threadIdx.x & 31, w = threadIdx.x >> 5;
#pragma unroll
    for (int o = 16; o; o >>= 1) v += __shfl_xor_sync(0xffffffffu, v, o);
    if (lane == 0) red[w] = v;
    __syncthreads();
    if (w == 0) {
        float t = (lane < 8) ? red[lane] : 0.f;
#pragma unroll
        for (int o = 4; o; o >>= 1) t += __shfl_xor_sync(0xffffffffu, t, o);
        if (lane == 0) red[0] = t;
    }
    __syncthreads();
    float r = red[0];
    __syncthreads();
    return r;
}

// ---------------- layernorm (optional fp16 hi/lo outputs) ----------------
__global__ void layernorm_k(const float* __restrict__ X, const float* __restrict__ Res,
                            const float* __restrict__ gam, const float* __restrict__ bet,
                            float* __restrict__ O,
                            __half* __restrict__ Ohi, __half* __restrict__ Olo) {
    int row = blockIdx.x, tid = threadIdx.x;
    __shared__ float red[32];
    float4 v = *(const float4*)(X + (size_t)row * DM + tid * 4);
    if (Res) {
        float4 rr = *(const float4*)(Res + (size_t)row * DM + tid * 4);
        v.x += rr.x; v.y += rr.y; v.z += rr.z; v.w += rr.w;
    }
    float s = block_sum(v.x + v.y + v.z + v.w, red);
    float s2 = block_sum(v.x * v.x + v.y * v.y + v.z * v.z + v.w * v.w, red);
    float mu = s * (1.f / DM);
    float var = s2 * (1.f / DM) - mu * mu;
    float rstd = rsqrtf(var + 1e-6f);
    float4 g4 = *(const float4*)(gam + tid * 4);
    float4 b4 = *(const float4*)(bet + tid * 4);
    float4 o;
    o.x = (v.x - mu) * rstd * g4.x + b4.x;
    o.y = (v.y - mu) * rstd * g4.y + b4.y;
    o.z = (v.z - mu) * rstd * g4.z + b4.z;
    o.w = (v.w - mu) * rstd * g4.w + b4.w;
    if (O) *(float4*)(O + (size_t)row * DM + tid * 4) = o;
    if (Ohi) {
        __half h0 = __float2half_rn(o.x), h1 = __float2half_rn(o.y);
        __half h2 = __float2half_rn(o.z), h3 = __float2half_rn(o.w);
        uint2 ph = make_uint2(pkh2(h0, h1), pkh2(h2, h3));
        uint2 pl = make_uint2(
            pkh2(__float2half_rn(o.x - __half2float(h0)),
                 __float2half_rn(o.y - __half2float(h1))),
            pkh2(__float2half_rn(o.z - __half2float(h2)),
                 __float2half_rn(o.w - __half2float(h3))));
        *(uint2*)(Ohi + (size_t)row * DM + tid * 4) = ph;
        *(uint2*)(Olo + (size_t)row * DM + tid * 4) = pl;
    }
}

// ---------------- launch ----------------
static void* sym_addr(const void* s) { void* p = nullptr; cudaGetSymbolAddress(&p, s); return p; }

extern "C" void kernel_launch(void* const* d_in, const int* in_sizes, int n_in,
                              void* d_out, int out_size) {
    const float* q    = (const float*)d_in[0];
    const float* k    = (const float*)d_in[1];
    const float* v    = (const float*)d_in[2];
    const float* wq   = (const float*)d_in[3];
    const float* bq   = (const float*)d_in[4];
    const float* wk   = (const float*)d_in[5];
    const float* bk   = (const float*)d_in[6];
    const float* wv   = (const float*)d_in[7];
    const float* bv   = (const float*)d_in[8];
    const float* wfc  = (const float*)d_in[9];
    const float* bfc  = (const float*)d_in[10];
    const float* w1   = (const float*)d_in[11];
    const float* b1   = (const float*)d_in[12];
    const float* w2   = (const float*)d_in[13];
    const float* b2   = (const float*)d_in[14];
    const float* ln_g = (const float*)d_in[15];
    const float* ln_b = (const float*)d_in[16];
    const float* relk = (const float*)d_in[17];
    const float* relv = (const float*)d_in[18];
    float* out = (float*)d_out;

    float* pV    = (float*)sym_addr(g_V);
    float* pTmp  = (float*)sym_addr(g_tmp);
    float* pLn1  = (float*)sym_addr(g_ln1);
    float* pT2   = (float*)sym_addr(g_t2);
    float* pBqkv = (float*)sym_addr(g_bqkv);
    __half* pAhi = (__half*)sym_addr(g_Ahi);
    __half* pAlo = (__half*)sym_addr(g_Alo);
    __half* pXhi = (__half*)sym_addr(g_Xhi);
    __half* pXlo = (__half*)sym_addr(g_Xlo);
    __half* pWh  = (__half*)sym_addr(g_Whi);
    __half* pVth = (__half*)sym_addr(g_Vth);

    cudaFuncSetAttribute(gemm_qkv_h, cudaFuncAttributeMaxDynamicSharedMemorySize, GEMM_H_SMEM);
    cudaFuncSetAttribute(gemm_fp16, cudaFuncAttributeMaxDynamicSharedMemorySize, GEMM_H_SMEM);
    cudaFuncSetAttribute(flash_attn, cudaFuncAttributeMaxDynamicSharedMemorySize, FLASH_SMEM);

    const int nD4 = ROWS * DM / 4 / 256;
    dim3 tBlk(32, 8);
    dim3 tGridD(DM / 32, DM / 32);
    dim3 tGridW1(DI / 32, DM / 32);
    dim3 tGridW2(DM / 32, DI / 32);
    dim3 gD(DM / 128, ROWS / 128);
    dim3 gI(DI / 128, ROWS / 128);
    dim3 gQKV(3 * DM / 128, ROWS / 128);

    // ---- merged QKV (fp16 2-pass): stacked weights, stacked inputs, concat bias ----
    bias_concat<<<12, 256>>>(bq, bk, bv);
    relk_split<<<12, 256>>>(relk);
    conv_T_h<<<tGridD, tBlk>>>(wq, pWh, DM, DM);
    conv_T_h<<<tGridD, tBlk>>>(wk, pWh + (size_t)DM * DM, DM, DM);
    conv_T_h<<<tGridD, tBlk>>>(wv, pWh + 2 * (size_t)DM * DM, DM, DM);
    conv_split_h<<<nD4, 256>>>(q, pAhi, pAlo);
    conv_split_h<<<nD4, 256>>>(k, pAhi + (size_t)ROWS * DM, pAlo + (size_t)ROWS * DM);
    conv_split_h<<<nD4, 256>>>(v, pAhi + 2 * (size_t)ROWS * DM, pAlo + 2 * (size_t)ROWS * DM);
    gemm_qkv_h<<<gQKV, 256, GEMM_H_SMEM>>>(pAhi, pAlo, pWh, pBqkv);

    // attention prep
    dim3 gvt(LSEQ / 32, DK / 32, BHN);
    vt_split_h<<<gvt, tBlk>>>(pV, pVth);

    // fused flash attention -> attn fp16 split into g_Xhi/g_Xlo
    dim3 gfa(LSEQ / 128, BHN);
    flash_attn<<<gfa, 256, FLASH_SMEM>>>(relv);

    // out-proj (fp16 2-pass) + LN1 (emits fp16 split for FFN1)
    conv_T_h<<<tGridD, tBlk>>>(wfc, pWh, DM, DM);
    gemm_fp16<<<gD, 256, GEMM_H_SMEM>>>(pXhi, pXlo, pWh, bfc, pTmp, nullptr, nullptr,
                                        ROWS, DM, DM, 0);
    layernorm_k<<<ROWS, 256>>>(pTmp, q, ln_g, ln_b, pLn1, pXhi, pXlo);

    // FFN (fp16 2-pass)
    conv_T_h<<<tGridW1, tBlk>>>(w1, pWh, DM, DI);
    gemm_fp16<<<gI, 256, GEMM_H_SMEM>>>(pXhi, pXlo, pWh, b1, nullptr,
                                        pAhi, pAlo, ROWS, DI, DM, 1);

    conv_T_h<<<tGridW2, tBlk>>>(w2, pWh, DI, DM);
    gemm_fp16<<<gD, 256, GEMM_H_SMEM>>>(pAhi, pAlo, pWh, b2, pT2, nullptr, nullptr,
                                        ROWS, DM, DI, 0);
    layernorm_k<<<ROWS, 256>>>(pT2, pLn1, ln_g, ln_b, out, nullptr, nullptr);
}

// round 12
// speedup vs baseline: 6.8459x; 1.4018x over previous
#include <cuda_runtime.h>
#include <cuda_bf16.h>
#include <cuda_fp16.h>
#include <cstdint>

#define LSEQ 1024
#define DM   1024
#define BATCH 8
#define NH   16
#define DK   64
#define BHN  (BATCH*NH)     // 128
#define NREL 33
#define DI   4096
#define ROWS (BATCH*LSEQ)   // 8192

// ---------------- scratch (static device arrays; no allocation) ----------------
__device__ float g_V[ROWS*DM];
__device__ float g_tmp[ROWS*DM];
__device__ float g_ln1[ROWS*DM];
__device__ float g_t2[ROWS*DM];
__device__ float g_bqkv[3*DM];
// fp16/bf16 buffers
__device__ __half g_Ah[(size_t)ROWS*DI];         // stacked QKV inputs / h1 (fp16)
__device__ __half g_Xh[ROWS*DM];                 // current activation (fp16)
__device__ __half g_Wh[(size_t)DM*DI];           // weights (fp16, stacked for QKV)
__device__ __nv_bfloat16 g_Qhi[ROWS*DM];
__device__ __nv_bfloat16 g_Qlo[ROWS*DM];
__device__ __nv_bfloat16 g_Khi[ROWS*DM];
__device__ __nv_bfloat16 g_Klo[ROWS*DM];
__device__ __half g_Vth[(size_t)BHN*DK*LSEQ];    // [bh][d][k] fp16
__device__ __nv_bfloat16 g_RKhi[48*DK];          // rel_k split, padded to 48 rows
__device__ __nv_bfloat16 g_RKlo[48*DK];

// ---------------- helpers ----------------
__device__ __forceinline__ uint32_t smem_u32(const void* p) {
    uint32_t a;
    asm("{ .reg .u64 t; cvta.to.shared.u64 t, %1; cvt.u32.u64 %0, t; }" : "=r"(a) : "l"(p));
    return a;
}
__device__ __forceinline__ void cp_async16(uint32_t saddr, const void* gaddr) {
    asm volatile("cp.async.cg.shared.global [%0], [%1], 16;" :: "r"(saddr), "l"(gaddr));
}
__device__ __forceinline__ void cp_commit() {
    asm volatile("cp.async.commit_group;" ::: "memory");
}
__device__ __forceinline__ void cp_wait1() {
    asm volatile("cp.async.wait_group 1;" ::: "memory");
}
__device__ __forceinline__ void cp_wait0() {
    asm volatile("cp.async.wait_group 0;" ::: "memory");
}
__device__ __forceinline__ void cp_async_wait_all() {
    asm volatile("cp.async.commit_group;\ncp.async.wait_group 0;" ::: "memory");
}
__device__ __forceinline__ void ldmx4(uint32_t* r, uint32_t addr) {
    asm volatile("ldmatrix.sync.aligned.m8n8.x4.shared.b16 {%0,%1,%2,%3}, [%4];"
        : "=r"(r[0]), "=r"(r[1]), "=r"(r[2]), "=r"(r[3]) : "r"(addr));
}
__device__ __forceinline__ void mma_bf16(float* c, const uint32_t* a, uint32_t b0, uint32_t b1) {
    asm volatile(
        "mma.sync.aligned.m16n8k16.row.col.f32.bf16.bf16.f32 "
        "{%0,%1,%2,%3}, {%4,%5,%6,%7}, {%8,%9}, {%0,%1,%2,%3};"
        : "+f"(c[0]), "+f"(c[1]), "+f"(c[2]), "+f"(c[3])
        : "r"(a[0]), "r"(a[1]), "r"(a[2]), "r"(a[3]), "r"(b0), "r"(b1));
}
__device__ __forceinline__ void mma_f16(float* c, const uint32_t* a, uint32_t b0, uint32_t b1) {
    asm volatile(
        "mma.sync.aligned.m16n8k16.row.col.f32.f16.f16.f32 "
        "{%0,%1,%2,%3}, {%4,%5,%6,%7}, {%8,%9}, {%0,%1,%2,%3};"
        : "+f"(c[0]), "+f"(c[1]), "+f"(c[2]), "+f"(c[3])
        : "r"(a[0]), "r"(a[1]), "r"(a[2]), "r"(a[3]), "r"(b0), "r"(b1));
}
__device__ __forceinline__ uint32_t pkbf2(__nv_bfloat16 lo, __nv_bfloat16 hi) {
    __nv_bfloat162 t(lo, hi);
    return *(uint32_t*)&t;
}
__device__ __forceinline__ uint32_t pkh2(__half lo, __half hi) {
    __half2 t(lo, hi);
    return *(uint32_t*)&t;
}

// ---------------- conversion kernels ----------------
// fp32 -> fp16 single
__global__ void conv_h(const float* __restrict__ X, __half* __restrict__ H) {
    int i = blockIdx.x * blockDim.x + threadIdx.x;
    float4 v = ((const float4*)X)[i];
    __half h[4] = {__float2half_rn(v.x), __float2half_rn(v.y),
                   __float2half_rn(v.z), __float2half_rn(v.w)};
    *(uint2*)(H + (size_t)i * 4) = *(uint2*)h;
}

// W[K,N] -> fp16 single T [N,K]
__global__ void conv_T_h(const float* __restrict__ W, __half* __restrict__ hT, int K, int N) {
    __shared__ float t[32][33];
    int n0 = blockIdx.x * 32, k0 = blockIdx.y * 32;
    int tx = threadIdx.x, ty = threadIdx.y;
    for (int i = ty; i < 32; i += 8)
        t[i][tx] = W[(size_t)(k0 + i) * N + n0 + tx];
    __syncthreads();
    for (int r = ty; r < 32; r += 8)
        hT[(size_t)(n0 + r) * K + k0 + tx] = __float2half_rn(t[tx][r]);
}

// V [b*L+k][h*64+d] -> Vt [bh][d][k] fp16 single
__global__ void vt_split_h(const float* __restrict__ V, __half* __restrict__ hT) {
    __shared__ float t[32][33];
    int bh = blockIdx.z, b = bh >> 4, h = bh & 15;
    int k0 = blockIdx.x * 32, d0 = blockIdx.y * 32;
    int tx = threadIdx.x, ty = threadIdx.y;
    for (int i = ty; i < 32; i += 8)
        t[i][tx] = V[(size_t)(b * LSEQ + k0 + i) * DM + h * DK + d0 + tx];
    __syncthreads();
    for (int r = ty; r < 32; r += 8)
        hT[((size_t)bh * DK + d0 + r) * LSEQ + k0 + tx] = __float2half_rn(t[tx][r]);
}

// rel_k [33,64] -> padded [48,64] bf16 hi/lo
__global__ void relk_split(const float* __restrict__ rel_k) {
    int i = blockIdx.x * 256 + threadIdx.x;   // 0..3071
    int r = i >> 6;
    float x = (r < NREL) ? rel_k[i] : 0.f;
    __nv_bfloat16 h = __float2bfloat16(x);
    g_RKhi[i] = h;
    g_RKlo[i] = __float2bfloat16(x - __bfloat162float(h));
}

__global__ void bias_concat(const float* __restrict__ b0, const float* __restrict__ b1,
                            const float* __restrict__ b2) {
    int i = blockIdx.x * 256 + threadIdx.x;   // 0..3071
    g_bqkv[i] = (i < DM) ? b0[i] : ((i < 2 * DM) ? b1[i - DM] : b2[i - 2 * DM]);
}

#define SPAD 40
#define GSTAGE_S 20480          // 2 arrays x 10240
#define GEMM_S_SMEM (2 * GSTAGE_S)

// ---------------- fp16 single-pass QKV GEMM (stacked segments) ----------------
// Epilogue: seg0->Qhi/lo(bf16), seg1->Khi/lo(bf16), seg2->fp32 g_V.
__global__ __launch_bounds__(256, 2) void gemm_qkv_h(
    const __half* __restrict__ Ah, const __half* __restrict__ Bh,
    const float* __restrict__ bias)
{
    extern __shared__ char gsm[];
    const uint32_t base = smem_u32(gsm);

    const int tid = threadIdx.x;
    const int wid = tid >> 5, lane = tid & 31;
    const int wm = wid >> 2, wn = wid & 3;
    const int bm = blockIdx.y * 128, bn = blockIdx.x * 128;

    const int seg = bn >> 10;
    const int bnl = bn & (DM - 1);
    Ah += (size_t)seg * ROWS * DM;
    Bh += (size_t)seg * DM * DM;

    float c[4][4][4];
#pragma unroll
    for (int mt = 0; mt < 4; mt++)
#pragma unroll
        for (int nt = 0; nt < 4; nt++)
#pragma unroll
            for (int r = 0; r < 4; r++) c[mt][nt][r] = 0.f;

    const int a_m_base = wm * 64 + (lane & 7) + 8 * ((lane >> 3) & 1);
    const int a_kk = 8 * (lane >> 4);
    const int b_n_base = wn * 32 + (lane & 7) + 8 * (lane >> 4);
    const int b_kk = 8 * ((lane >> 3) & 1);

    const int ktiles = DM >> 5;

    auto load_tile = [&](int t, int s) {
        const int kbase = t * 32;
        const uint32_t sb = base + s * GSTAGE_S;
#pragma unroll
        for (int i = 0; i < 2; i++) {
            int f = tid + i * 256;
            int row = f >> 2, seg2 = f & 3;
            uint32_t so = (uint32_t)(row * SPAD + seg2 * 8) * 2;
            cp_async16(sb + so, Ah + (size_t)(bm + row) * DM + kbase + seg2 * 8);
            cp_async16(sb + 10240 + so, Bh + (size_t)(bnl + row) * DM + kbase + seg2 * 8);
        }
        cp_commit();
    };

    load_tile(0, 0);
    for (int t = 0; t < ktiles; t++) {
        if (t + 1 < ktiles) {
            load_tile(t + 1, (t + 1) & 1);
            cp_wait1();
        } else {
            cp_wait0();
        }
        __syncthreads();

        const uint32_t sb = base + (t & 1) * GSTAGE_S;
        const uint32_t aA = sb, aB = sb + 10240;
#pragma unroll
        for (int kh = 0; kh < 2; kh++) {
            const int k0 = kh * 16;
            uint32_t bh[8];
#pragma unroll
            for (int p = 0; p < 2; p++) {
                uint32_t off = (uint32_t)((b_n_base + p * 16) * SPAD + k0 + b_kk) * 2;
                ldmx4(bh + p * 4, aB + off);
            }
#pragma unroll
            for (int mt = 0; mt < 4; mt++) {
                uint32_t ah[4];
                uint32_t off = (uint32_t)((a_m_base + mt * 16) * SPAD + k0 + a_kk) * 2;
                ldmx4(ah, aA + off);
#pragma unroll
                for (int nt = 0; nt < 4; nt++)
                    mma_f16(c[mt][nt], ah, bh[nt * 2], bh[nt * 2 + 1]);
            }
        }
        __syncthreads();
    }

    const int r0 = lane >> 2, c0 = (lane & 3) * 2;
#pragma unroll
    for (int mt = 0; mt < 4; mt++) {
        int row = bm + wm * 64 + mt * 16 + r0;
#pragma unroll
        for (int nt = 0; nt < 4; nt++) {
            int col = bn + wn * 32 + nt * 8 + c0;
            float b0v = bias[col], b1v = bias[col + 1];
            float v0 = c[mt][nt][0] + b0v, v1 = c[mt][nt][1] + b1v;
            float v2 = c[mt][nt][2] + b0v, v3 = c[mt][nt][3] + b1v;
            int coll = bnl + wn * 32 + nt * 8 + c0;
            if (seg == 2) {
                *(float2*)(g_V + (size_t)row * DM + coll) = make_float2(v0, v1);
                *(float2*)(g_V + (size_t)(row + 8) * DM + coll) = make_float2(v2, v3);
            } else {
                __nv_bfloat16* dh = (seg == 0) ? g_Qhi : g_Khi;
                __nv_bfloat16* dl = (seg == 0) ? g_Qlo : g_Klo;
                __nv_bfloat16 h0 = __float2bfloat16(v0), h1 = __float2bfloat16(v1);
                __nv_bfloat16 h2 = __float2bfloat16(v2), h3 = __float2bfloat16(v3);
                *(uint32_t*)(dh + (size_t)row * DM + coll) = pkbf2(h0, h1);
                *(uint32_t*)(dh + (size_t)(row + 8) * DM + coll) = pkbf2(h2, h3);
                *(uint32_t*)(dl + (size_t)row * DM + coll) =
                    pkbf2(__float2bfloat16(v0 - __bfloat162float(h0)),
                          __float2bfloat16(v1 - __bfloat162float(h1)));
                *(uint32_t*)(dl + (size_t)(row + 8) * DM + coll) =
                    pkbf2(__float2bfloat16(v2 - __bfloat162float(h2)),
                          __float2bfloat16(v3 - __bfloat162float(h3)));
            }
        }
    }
}

// ---------------- fp16 single-pass GEMM ----------------
__global__ __launch_bounds__(256, 2) void gemm_fp16(
    const __half* __restrict__ Ah, const __half* __restrict__ Bh,
    const float* __restrict__ bias, float* __restrict__ C,
    __half* __restrict__ Chi, int M, int N, int K, int relu)
{
    extern __shared__ char gsm[];
    const uint32_t base = smem_u32(gsm);

    const int tid = threadIdx.x;
    const int wid = tid >> 5, lane = tid & 31;
    const int wm = wid >> 2, wn = wid & 3;
    const int bm = blockIdx.y * 128, bn = blockIdx.x * 128;

    float c[4][4][4];
#pragma unroll
    for (int mt = 0; mt < 4; mt++)
#pragma unroll
        for (int nt = 0; nt < 4; nt++)
#pragma unroll
            for (int r = 0; r < 4; r++) c[mt][nt][r] = 0.f;

    const int a_m_base = wm * 64 + (lane & 7) + 8 * ((lane >> 3) & 1);
    const int a_kk = 8 * (lane >> 4);
    const int b_n_base = wn * 32 + (lane & 7) + 8 * (lane >> 4);
    const int b_kk = 8 * ((lane >> 3) & 1);

    const int ktiles = K >> 5;

    auto load_tile = [&](int t, int s) {
        const int kbase = t * 32;
        const uint32_t sb = base + s * GSTAGE_S;
#pragma unroll
        for (int i = 0; i < 2; i++) {
            int f = tid + i * 256;
            int row = f >> 2, seg2 = f & 3;
            uint32_t so = (uint32_t)(row * SPAD + seg2 * 8) * 2;
            cp_async16(sb + so, Ah + (size_t)(bm + row) * K + kbase + seg2 * 8);
            cp_async16(sb + 10240 + so, Bh + (size_t)(bn + row) * K + kbase + seg2 * 8);
        }
        cp_commit();
    };

    load_tile(0, 0);
    for (int t = 0; t < ktiles; t++) {
        if (t + 1 < ktiles) {
            load_tile(t + 1, (t + 1) & 1);
            cp_wait1();
        } else {
            cp_wait0();
        }
        __syncthreads();

        const uint32_t sb = base + (t & 1) * GSTAGE_S;
        const uint32_t aA = sb, aB = sb + 10240;
#pragma unroll
        for (int kh = 0; kh < 2; kh++) {
            const int k0 = kh * 16;
            uint32_t bh[8];
#pragma unroll
            for (int p = 0; p < 2; p++) {
                uint32_t off = (uint32_t)((b_n_base + p * 16) * SPAD + k0 + b_kk) * 2;
                ldmx4(bh + p * 4, aB + off);
            }
#pragma unroll
            for (int mt = 0; mt < 4; mt++) {
                uint32_t ah[4];
                uint32_t off = (uint32_t)((a_m_base + mt * 16) * SPAD + k0 + a_kk) * 2;
                ldmx4(ah, aA + off);
#pragma unroll
                for (int nt = 0; nt < 4; nt++)
                    mma_f16(c[mt][nt], ah, bh[nt * 2], bh[nt * 2 + 1]);
            }
        }
        __syncthreads();
    }

    const int r0 = lane >> 2, c0 = (lane & 3) * 2;
#pragma unroll
    for (int mt = 0; mt < 4; mt++) {
        int row = bm + wm * 64 + mt * 16 + r0;
#pragma unroll
        for (int nt = 0; nt < 4; nt++) {
            int col = bn + wn * 32 + nt * 8 + c0;
            float b0v = bias[col], b1v = bias[col + 1];
            float v0 = c[mt][nt][0] + b0v, v1 = c[mt][nt][1] + b1v;
            float v2 = c[mt][nt][2] + b0v, v3 = c[mt][nt][3] + b1v;
            if (relu) {
                v0 = fmaxf(v0, 0.f); v1 = fmaxf(v1, 0.f);
                v2 = fmaxf(v2, 0.f); v3 = fmaxf(v3, 0.f);
            }
            if (C) {
                *(float2*)(C + (size_t)row * N + col) = make_float2(v0, v1);
                *(float2*)(C + (size_t)(row + 8) * N + col) = make_float2(v2, v3);
            }
            if (Chi) {
                *(uint32_t*)(Chi + (size_t)row * N + col) =
                    pkh2(__float2half_rn(v0), __float2half_rn(v1));
                *(uint32_t*)(Chi + (size_t)(row + 8) * N + col) =
                    pkh2(__float2half_rn(v2), __float2half_rn(v3));
            }
        }
    }
}

// ---------------- fused flash attention ----------------
// Scores: bf16x3 (Q,K hi/lo). PV: fp16 single P x fp16 single Vt.
#define QP 72
#define VP 136
#define OFF_QH 0
#define OFF_QL 18432
#define OFF_KH 36864
#define OFF_KL 55296
#define OFF_VH 73728
#define OFF_WB 91136
#define OFF_SR 108544
#define OFF_F  125952
#define OFF_RKH 126464
#define OFF_RKL 133376
#define FLASH_SMEM 140288

__global__ __launch_bounds__(256, 1) void flash_attn(const float* __restrict__ rel_v) {
    extern __shared__ char fsm[];
    float* sWb = (float*)(fsm + OFF_WB);    // [128][34]
    float* sSr = (float*)(fsm + OFF_SR);    // [128][34]
    float* sF  = (float*)(fsm + OFF_F);     // [128]

    const int tid = threadIdx.x;
    const int wid = tid >> 5, lane = tid & 31;
    const int bh = blockIdx.y, b = bh >> 4, h = bh & 15;
    const int bq = blockIdx.x * 128;

    const uint32_t aQh = smem_u32(fsm + OFF_QH), aQl = smem_u32(fsm + OFF_QL);
    const uint32_t aKh = smem_u32(fsm + OFF_KH), aKl = smem_u32(fsm + OFF_KL);
    const uint32_t aVh = smem_u32(fsm + OFF_VH);
    const uint32_t aRKh = smem_u32(fsm + OFF_RKH), aRKl = smem_u32(fsm + OFF_RKL);

#pragma unroll
    for (int i = 0; i < 4; i++) {
        int f = tid + i * 256;
        int row = f >> 3, seg = f & 7;
        uint32_t so = (uint32_t)(row * QP + seg * 8) * 2;
        size_t gq = (size_t)(b * LSEQ + bq + row) * DM + h * DK + seg * 8;
        cp_async16(aQh + so, g_Qhi + gq);
        cp_async16(aQl + so, g_Qlo + gq);
    }
    for (int f = tid; f < 384; f += 256) {
        int row = f >> 3, seg = f & 7;
        uint32_t so = (uint32_t)(row * QP + seg * 8) * 2;
        cp_async16(aRKh + so, g_RKhi + row * DK + seg * 8);
        cp_async16(aRKl + so, g_RKlo + row * DK + seg * 8);
    }
    for (int o = tid; o < 128 * 34; o += 256) sWb[o] = 0.f;
    cp_async_wait_all();
    __syncthreads();

    const int a_row = wid * 16 + (lane & 7) + 8 * ((lane >> 3) & 1);
    const int a_kk = 8 * (lane >> 4);
    const int b_row = (lane & 7) + 8 * (lane >> 4);
    const int b_kk = 8 * ((lane >> 3) & 1);
    const int r0 = lane >> 2, c0 = (lane & 3) * 2;
    const int qrow0 = wid * 16 + r0;
    const int q0 = bq + qrow0;

    // ---- sSr = Q . rel_k^T via MMA ----
    {
        float csr[6][4];
#pragma unroll
        for (int nt = 0; nt < 6; nt++)
#pragma unroll
            for (int j = 0; j < 4; j++) csr[nt][j] = 0.f;
#pragma unroll
        for (int ks = 0; ks < 4; ks++) {
            uint32_t ah[4], al[4];
            uint32_t aoff = (uint32_t)(a_row * QP + ks * 16 + a_kk) * 2;
            ldmx4(ah, aQh + aoff);
            ldmx4(al, aQl + aoff);
            uint32_t rbh[12], rbl[12];
#pragma unroll
            for (int p = 0; p < 3; p++) {
                uint32_t boff = (uint32_t)((b_row + p * 16) * QP + ks * 16 + b_kk) * 2;
                ldmx4(rbh + p * 4, aRKh + boff);
                ldmx4(rbl + p * 4, aRKl + boff);
            }
#pragma unroll
            for (int nt = 0; nt < 6; nt++) {
                mma_bf16(csr[nt], ah, rbh[nt * 2], rbh[nt * 2 + 1]);
                mma_bf16(csr[nt], ah, rbl[nt * 2], rbl[nt * 2 + 1]);
                mma_bf16(csr[nt], al, rbh[nt * 2], rbh[nt * 2 + 1]);
            }
        }
#pragma unroll
        for (int nt = 0; nt < 6; nt++) {
#pragma unroll
            for (int j = 0; j < 4; j++) {
                int col = nt * 8 + c0 + (j & 1);
                if (col < 34) {
                    int row = (j < 2) ? qrow0 : qrow0 + 8;
                    sSr[row * 34 + col] = csr[nt][j];
                }
            }
        }
        __syncwarp();
    }

    float m0 = -1e30f, m1 = -1e30f, l0 = 0.f, l1 = 0.f;
    float O[8][4];
#pragma unroll
    for (int nt = 0; nt < 8; nt++)
#pragma unroll
        for (int j = 0; j < 4; j++) O[nt][j] = 0.f;

    for (int kt = 0; kt < 8; kt++) {
        const int k0 = kt * 128;
#pragma unroll
        for (int i = 0; i < 4; i++) {
            int f = tid + i * 256;
            int row = f >> 3, seg = f & 7;
            uint32_t so = (uint32_t)(row * QP + seg * 8) * 2;
            size_t gk = (size_t)(b * LSEQ + k0 + row) * DM + h * DK + seg * 8;
            cp_async16(aKh + so, g_Khi + gk);
            cp_async16(aKl + so, g_Klo + gk);
        }
#pragma unroll
        for (int i = 0; i < 4; i++) {
            int f = tid + i * 256;
            int row = f >> 4, seg = f & 15;
            uint32_t so = (uint32_t)(row * VP + seg * 8) * 2;
            size_t gv = ((size_t)bh * DK + row) * LSEQ + k0 + seg * 8;
            cp_async16(aVh + so, g_Vth + gv);
        }
        cp_async_wait_all();
        __syncthreads();

        float c[16][4];
#pragma unroll
        for (int nt = 0; nt < 16; nt++)
#pragma unroll
            for (int j = 0; j < 4; j++) c[nt][j] = 0.f;

#pragma unroll
        for (int ks = 0; ks < 4; ks++) {
            uint32_t ah[4], al[4];
            uint32_t aoff = (uint32_t)(a_row * QP + ks * 16 + a_kk) * 2;
            ldmx4(ah, aQh + aoff);
            ldmx4(al, aQl + aoff);
#pragma unroll
            for (int hh = 0; hh < 2; hh++) {
                uint32_t bhf[16], blf[16];
#pragma unroll
                for (int p = 0; p < 4; p++) {
                    uint32_t boff = (uint32_t)((b_row + hh * 64 + p * 16) * QP + ks * 16 + b_kk) * 2;
                    ldmx4(bhf + p * 4, aKh + boff);
                    ldmx4(blf + p * 4, aKl + boff);
                }
#pragma unroll
                for (int nt = 0; nt < 8; nt++) {
                    float* cc = c[hh * 8 + nt];
                    mma_bf16(cc, ah, bhf[nt * 2], bhf[nt * 2 + 1]);
                    mma_bf16(cc, ah, blf[nt * 2], blf[nt * 2 + 1]);
                    mma_bf16(cc, al, bhf[nt * 2], bhf[nt * 2 + 1]);
                }
            }
        }

        float tm0 = -1e30f, tm1 = -1e30f;
#pragma unroll
        for (int nt = 0; nt < 16; nt++) {
            int kA = k0 + nt * 8 + c0;
#pragma unroll
            for (int j = 0; j < 4; j++) {
                int kk = kA + (j & 1);
                bool low = (j < 2);
                int q = low ? q0 : q0 + 8;
                int lrow = low ? qrow0 : qrow0 + 8;
                int d = kk - q; d = max(-16, min(16, d));
                float s = (c[nt][j] + sSr[lrow * 34 + d + 16]) * 0.125f;
                c[nt][j] = s;
                if (low) tm0 = fmaxf(tm0, s); else tm1 = fmaxf(tm1, s);
            }
        }
        tm0 = fmaxf(tm0, __shfl_xor_sync(0xffffffffu, tm0, 1));
        tm0 = fmaxf(tm0, __shfl_xor_sync(0xffffffffu, tm0, 2));
        tm1 = fmaxf(tm1, __shfl_xor_sync(0xffffffffu, tm1, 1));
        tm1 = fmaxf(tm1, __shfl_xor_sync(0xffffffffu, tm1, 2));
        float nm0 = fmaxf(m0, tm0), nm1 = fmaxf(m1, tm1);
        float f0 = __expf(m0 - nm0), f1 = __expf(m1 - nm1);
        m0 = nm0; m1 = nm1;
        if ((lane & 3) == 0) { sF[qrow0] = f0; sF[qrow0 + 8] = f1; }
        __syncwarp();
        for (int o = lane; o < 16 * 33; o += 32) {
            int rr = o / 33, cc2 = o % 33;
            sWb[(wid * 16 + rr) * 34 + cc2] *= sF[wid * 16 + rr];
        }
        __syncwarp();

        float sum0 = 0.f, sum1 = 0.f, lo0 = 0.f, lo1 = 0.f, hi0 = 0.f, hi1 = 0.f;
#pragma unroll
        for (int nt = 0; nt < 16; nt++) {
#pragma unroll
            for (int j = 0; j < 4; j++) {
                int kk = k0 + nt * 8 + c0 + (j & 1);
                bool low = (j < 2);
                float p = __expf(c[nt][j] - (low ? nm0 : nm1));
                c[nt][j] = p;
                int q = low ? q0 : q0 + 8;
                int d = kk - q;
                if (low) sum0 += p; else sum1 += p;
                if (d <= -16) { if (low) lo0 += p; else lo1 += p; }
                else if (d >= 16) { if (low) hi0 += p; else hi1 += p; }
                else sWb[(low ? qrow0 : qrow0 + 8) * 34 + d + 16] += p;
            }
        }
        sum0 += __shfl_xor_sync(0xffffffffu, sum0, 1);
        sum0 += __shfl_xor_sync(0xffffffffu, sum0, 2);
        sum1 += __shfl_xor_sync(0xffffffffu, sum1, 1);
        sum1 += __shfl_xor_sync(0xffffffffu, sum1, 2);
        lo0 += __shfl_xor_sync(0xffffffffu, lo0, 1);
        lo0 += __shfl_xor_sync(0xffffffffu, lo0, 2);
        lo1 += __shfl_xor_sync(0xffffffffu, lo1, 1);
        lo1 += __shfl_xor_sync(0xffffffffu, lo1, 2);
        hi0 += __shfl_xor_sync(0xffffffffu, hi0, 1);
        hi0 += __shfl_xor_sync(0xffffffffu, hi0, 2);
        hi1 += __shfl_xor_sync(0xffffffffu, hi1, 1);
        hi1 += __shfl_xor_sync(0xffffffffu, hi1, 2);
        l0 = l0 * f0 + sum0;
        l1 = l1 * f1 + sum1;
        if ((lane & 3) == 0) {
            sWb[qrow0 * 34 + 0] += lo0;  sWb[qrow0 * 34 + 32] += hi0;
            sWb[(qrow0 + 8) * 34 + 0] += lo1;  sWb[(qrow0 + 8) * 34 + 32] += hi1;
        }
#pragma unroll
        for (int nt = 0; nt < 8; nt++) {
            O[nt][0] *= f0; O[nt][1] *= f0; O[nt][2] *= f1; O[nt][3] *= f1;
        }

        // ---- PV: P fp16 single x Vt fp16 single ----
#pragma unroll
        for (int j = 0; j < 8; j++) {
            uint32_t pa[4];
            pa[0] = pkh2(__float2half_rn(c[2 * j][0]), __float2half_rn(c[2 * j][1]));
            pa[1] = pkh2(__float2half_rn(c[2 * j][2]), __float2half_rn(c[2 * j][3]));
            pa[2] = pkh2(__float2half_rn(c[2 * j + 1][0]), __float2half_rn(c[2 * j + 1][1]));
            pa[3] = pkh2(__float2half_rn(c[2 * j + 1][2]), __float2half_rn(c[2 * j + 1][3]));
            uint32_t vh[16];
#pragma unroll
            for (int p = 0; p < 4; p++) {
                uint32_t voff = (uint32_t)((b_row + p * 16) * VP + j * 16 + b_kk) * 2;
                ldmx4(vh + p * 4, aVh + voff);
            }
#pragma unroll
            for (int nt = 0; nt < 8; nt++)
                mma_f16(O[nt], pa, vh[nt * 2], vh[nt * 2 + 1]);
        }
        __syncthreads();
    }

    // ---- epilogue: rank-33 rel_v update, normalize, store fp16 single ----
    float* rv = (float*)(fsm + OFF_KH);
    for (int o = tid; o < NREL * DK; o += 256) rv[o] = rel_v[o];
    __syncthreads();

#pragma unroll 1
    for (int r = 0; r < NREL; r++) {
        float wb0 = sWb[qrow0 * 34 + r];
        float wb1 = sWb[(qrow0 + 8) * 34 + r];
#pragma unroll
        for (int nt = 0; nt < 8; nt++) {
            int d = nt * 8 + c0;
            float rv0 = rv[r * DK + d], rv1 = rv[r * DK + d + 1];
            O[nt][0] += wb0 * rv0; O[nt][1] += wb0 * rv1;
            O[nt][2] += wb1 * rv0; O[nt][3] += wb1 * rv1;
        }
    }
    float inv0 = 1.f / l0, inv1 = 1.f / l1;
    size_t o0 = (size_t)(b * LSEQ + q0) * DM + h * DK;
    size_t o1 = (size_t)(b * LSEQ + q0 + 8) * DM + h * DK;
#pragma unroll
    for (int nt = 0; nt < 8; nt++) {
        int d = nt * 8 + c0;
        *(uint32_t*)(g_Xh + o0 + d) =
            pkh2(__float2half_rn(O[nt][0] * inv0), __float2half_rn(O[nt][1] * inv0));
        *(uint32_t*)(g_Xh + o1 + d) =
            pkh2(__float2half_rn(O[nt][2] * inv1), __float2half_rn(O[nt][3] * inv1));
    }
}

// ---------------- reductions ----------------
__device__ __forceinline__ float block_sum(float v, float* red) {
    int lane = threadIdx.x & 31, w = threadIdx.x >> 5;
#pragma unroll
    for (int o = 16; o; o >>= 1) v += __shfl_xor_sync(0xffffffffu, v, o);
    if (lane == 0) red[w] = v;
    __syncthreads();
    if (w == 0) {
        float t = (lane < 8) ? red[lane] : 0.f;
#pragma unroll
        for (int o = 4; o; o >>= 1) t += __shfl_xor_sync(0xffffffffu, t, o);
        if (lane == 0) red[0] = t;
    }
    __syncthreads();
    float r = red[0];
    __syncthreads();
    return r;
}

// ---------------- layernorm (optional fp16 single output) ----------------
__global__ void layernorm_k(const float* __restrict__ X, const float* __restrict__ Res,
                            const float* __restrict__ gam, const float* __restrict__ bet,
                            float* __restrict__ O, __half* __restrict__ Oh) {
    int row = blockIdx.x, tid = threadIdx.x;
    __shared__ float red[32];
    float4 v = *(const float4*)(X + (size_t)row * DM + tid * 4);
    if (Res) {
        float4 rr = *(const float4*)(Res + (size_t)row * DM + tid * 4);
        v.x += rr.x; v.y += rr.y; v.z += rr.z; v.w += rr.w;
    }
    float s = block_sum(v.x + v.y + v.z + v.w, red);
    float s2 = block_sum(v.x * v.x + v.y * v.y + v.z * v.z + v.w * v.w, red);
    float mu = s * (1.f / DM);
    float var = s2 * (1.f / DM) - mu * mu;
    float rstd = rsqrtf(var + 1e-6f);
    float4 g4 = *(const float4*)(gam + tid * 4);
    float4 b4 = *(const float4*)(bet + tid * 4);
    float4 o;
    o.x = (v.x - mu) * rstd * g4.x + b4.x;
    o.y = (v.y - mu) * rstd * g4.y + b4.y;
    o.z = (v.z - mu) * rstd * g4.z + b4.z;
    o.w = (v.w - mu) * rstd * g4.w + b4.w;
    if (O) *(float4*)(O + (size_t)row * DM + tid * 4) = o;
    if (Oh) {
        uint2 ph = make_uint2(pkh2(__float2half_rn(o.x), __float2half_rn(o.y)),
                              pkh2(__float2half_rn(o.z), __float2half_rn(o.w)));
        *(uint2*)(Oh + (size_t)row * DM + tid * 4) = ph;
    }
}

// ---------------- launch ----------------
static void* sym_addr(const void* s) { void* p = nullptr; cudaGetSymbolAddress(&p, s); return p; }

extern "C" void kernel_launch(void* const* d_in, const int* in_sizes, int n_in,
                              void* d_out, int out_size) {
    const float* q    = (const float*)d_in[0];
    const float* k    = (const float*)d_in[1];
    const float* v    = (const float*)d_in[2];
    const float* wq   = (const float*)d_in[3];
    const float* bq   = (const float*)d_in[4];
    const float* wk   = (const float*)d_in[5];
    const float* bk   = (const float*)d_in[6];
    const float* wv   = (const float*)d_in[7];
    const float* bv   = (const float*)d_in[8];
    const float* wfc  = (const float*)d_in[9];
    const float* bfc  = (const float*)d_in[10];
    const float* w1   = (const float*)d_in[11];
    const float* b1   = (const float*)d_in[12];
    const float* w2   = (const float*)d_in[13];
    const float* b2   = (const float*)d_in[14];
    const float* ln_g = (const float*)d_in[15];
    const float* ln_b = (const float*)d_in[16];
    const float* relk = (const float*)d_in[17];
    const float* relv = (const float*)d_in[18];
    float* out = (float*)d_out;

    float* pV    = (float*)sym_addr(g_V);
    float* pTmp  = (float*)sym_addr(g_tmp);
    float* pLn1  = (float*)sym_addr(g_ln1);
    float* pT2   = (float*)sym_addr(g_t2);
    float* pBqkv = (float*)sym_addr(g_bqkv);
    __half* pAh  = (__half*)sym_addr(g_Ah);
    __half* pXh  = (__half*)sym_addr(g_Xh);
    __half* pWh  = (__half*)sym_addr(g_Wh);
    __half* pVth = (__half*)sym_addr(g_Vth);

    cudaFuncSetAttribute(gemm_qkv_h, cudaFuncAttributeMaxDynamicSharedMemorySize, GEMM_S_SMEM);
    cudaFuncSetAttribute(gemm_fp16, cudaFuncAttributeMaxDynamicSharedMemorySize, GEMM_S_SMEM);
    cudaFuncSetAttribute(flash_attn, cudaFuncAttributeMaxDynamicSharedMemorySize, FLASH_SMEM);

    const int nD4 = ROWS * DM / 4 / 256;
    dim3 tBlk(32, 8);
    dim3 tGridD(DM / 32, DM / 32);
    dim3 tGridW1(DI / 32, DM / 32);
    dim3 tGridW2(DM / 32, DI / 32);
    dim3 gD(DM / 128, ROWS / 128);
    dim3 gI(DI / 128, ROWS / 128);
    dim3 gQKV(3 * DM / 128, ROWS / 128);

    // ---- merged QKV (fp16 single-pass): stacked weights, stacked inputs ----
    bias_concat<<<12, 256>>>(bq, bk, bv);
    relk_split<<<12, 256>>>(relk);
    conv_T_h<<<tGridD, tBlk>>>(wq, pWh, DM, DM);
    conv_T_h<<<tGridD, tBlk>>>(wk, pWh + (size_t)DM * DM, DM, DM);
    conv_T_h<<<tGridD, tBlk>>>(wv, pWh + 2 * (size_t)DM * DM, DM, DM);
    conv_h<<<nD4, 256>>>(q, pAh);
    conv_h<<<nD4, 256>>>(k, pAh + (size_t)ROWS * DM);
    conv_h<<<nD4, 256>>>(v, pAh + 2 * (size_t)ROWS * DM);
    gemm_qkv_h<<<gQKV, 256, GEMM_S_SMEM>>>(pAh, pWh, pBqkv);

    // attention prep
    dim3 gvt(LSEQ / 32, DK / 32, BHN);
    vt_split_h<<<gvt, tBlk>>>(pV, pVth);

    // fused flash attention -> attn fp16 into g_Xh
    dim3 gfa(LSEQ / 128, BHN);
    flash_attn<<<gfa, 256, FLASH_SMEM>>>(relv);

    // out-proj + LN1 (emits fp16 for FFN1)
    conv_T_h<<<tGridD, tBlk>>>(wfc, pWh, DM, DM);
    gemm_fp16<<<gD, 256, GEMM_S_SMEM>>>(pXh, pWh, bfc, pTmp, nullptr, ROWS, DM, DM, 0);
    layernorm_k<<<ROWS, 256>>>(pTmp, q, ln_g, ln_b, pLn1, pXh);

    // FFN
    conv_T_h<<<tGridW1, tBlk>>>(w1, pWh, DM, DI);
    gemm_fp16<<<gI, 256, GEMM_S_SMEM>>>(pXh, pWh, b1, nullptr, pAh, ROWS, DI, DM, 1);

    conv_T_h<<<tGridW2, tBlk>>>(w2, pWh, DI, DM);
    gemm_fp16<<<gD, 256, GEMM_S_SMEM>>>(pAh, pWh, b2, pT2, nullptr, ROWS, DM, DI, 0);
    layernorm_k<<<ROWS, 256>>>(pT2, pLn1, ln_g, ln_b, out, nullptr);
}

// round 14
// speedup vs baseline: 7.9637x; 1.1633x over previous
#include <cuda_runtime.h>
#include <cuda_bf16.h>
#include <cuda_fp16.h>
#include <cstdint>

#define LSEQ 1024
#define DM   1024
#define BATCH 8
#define NH   16
#define DK   64
#define BHN  (BATCH*NH)     // 128
#define NREL 33
#define DI   4096
#define ROWS (BATCH*LSEQ)   // 8192

// ---------------- scratch (static device arrays; no allocation) ----------------
__device__ float g_V[ROWS*DM];
__device__ float g_tmp[ROWS*DM];
__device__ float g_ln1[ROWS*DM];
__device__ float g_t2[ROWS*DM];
__device__ float g_bqkv[3*DM];
// fp16 buffers
__device__ __half g_Ah[(size_t)ROWS*DI];         // stacked QKV inputs / h1 (fp16)
__device__ __half g_Xh[ROWS*DM];                 // current activation (fp16)
__device__ __half g_Wh[(size_t)DM*DI];           // weights (fp16, stacked for QKV)
__device__ __half g_Qh[ROWS*DM];
__device__ __half g_Kh[ROWS*DM];
__device__ __half g_Vth[(size_t)BHN*DK*LSEQ];    // [bh][d][k] fp16
__device__ __half g_RKh[48*DK];                  // rel_k fp16, padded to 48 rows

// ---------------- helpers ----------------
__device__ __forceinline__ uint32_t smem_u32(const void* p) {
    uint32_t a;
    asm("{ .reg .u64 t; cvta.to.shared.u64 t, %1; cvt.u32.u64 %0, t; }" : "=r"(a) : "l"(p));
    return a;
}
__device__ __forceinline__ void cp_async16(uint32_t saddr, const void* gaddr) {
    asm volatile("cp.async.cg.shared.global [%0], [%1], 16;" :: "r"(saddr), "l"(gaddr));
}
__device__ __forceinline__ void cp_commit() {
    asm volatile("cp.async.commit_group;" ::: "memory");
}
__device__ __forceinline__ void cp_wait1() {
    asm volatile("cp.async.wait_group 1;" ::: "memory");
}
__device__ __forceinline__ void cp_wait0() {
    asm volatile("cp.async.wait_group 0;" ::: "memory");
}
__device__ __forceinline__ void cp_async_wait_all() {
    asm volatile("cp.async.commit_group;\ncp.async.wait_group 0;" ::: "memory");
}
__device__ __forceinline__ void ldmx4(uint32_t* r, uint32_t addr) {
    asm volatile("ldmatrix.sync.aligned.m8n8.x4.shared.b16 {%0,%1,%2,%3}, [%4];"
        : "=r"(r[0]), "=r"(r[1]), "=r"(r[2]), "=r"(r[3]) : "r"(addr));
}
__device__ __forceinline__ void mma_f16(float* c, const uint32_t* a, uint32_t b0, uint32_t b1) {
    asm volatile(
        "mma.sync.aligned.m16n8k16.row.col.f32.f16.f16.f32 "
        "{%0,%1,%2,%3}, {%4,%5,%6,%7}, {%8,%9}, {%0,%1,%2,%3};"
        : "+f"(c[0]), "+f"(c[1]), "+f"(c[2]), "+f"(c[3])
        : "r"(a[0]), "r"(a[1]), "r"(a[2]), "r"(a[3]), "r"(b0), "r"(b1));
}
__device__ __forceinline__ uint32_t pkh2(__half lo, __half hi) {
    __half2 t(lo, hi);
    return *(uint32_t*)&t;
}

// ---------------- conversion kernels ----------------
__global__ void conv_h(const float* __restrict__ X, __half* __restrict__ H) {
    int i = blockIdx.x * blockDim.x + threadIdx.x;
    float4 v = ((const float4*)X)[i];
    __half h[4] = {__float2half_rn(v.x), __float2half_rn(v.y),
                   __float2half_rn(v.z), __float2half_rn(v.w)};
    *(uint2*)(H + (size_t)i * 4) = *(uint2*)h;
}

// W[K,N] -> fp16 single T [N,K]
__global__ void conv_T_h(const float* __restrict__ W, __half* __restrict__ hT, int K, int N) {
    __shared__ float t[32][33];
    int n0 = blockIdx.x * 32, k0 = blockIdx.y * 32;
    int tx = threadIdx.x, ty = threadIdx.y;
    for (int i = ty; i < 32; i += 8)
        t[i][tx] = W[(size_t)(k0 + i) * N + n0 + tx];
    __syncthreads();
    for (int r = ty; r < 32; r += 8)
        hT[(size_t)(n0 + r) * K + k0 + tx] = __float2half_rn(t[tx][r]);
}

// V [b*L+k][h*64+d] -> Vt [bh][d][k] fp16
__global__ void vt_split_h(const float* __restrict__ V, __half* __restrict__ hT) {
    __shared__ float t[32][33];
    int bh = blockIdx.z, b = bh >> 4, h = bh & 15;
    int k0 = blockIdx.x * 32, d0 = blockIdx.y * 32;
    int tx = threadIdx.x, ty = threadIdx.y;
    for (int i = ty; i < 32; i += 8)
        t[i][tx] = V[(size_t)(b * LSEQ + k0 + i) * DM + h * DK + d0 + tx];
    __syncthreads();
    for (int r = ty; r < 32; r += 8)
        hT[((size_t)bh * DK + d0 + r) * LSEQ + k0 + tx] = __float2half_rn(t[tx][r]);
}

// rel_k [33,64] -> padded [48,64] fp16
__global__ void relk_h(const float* __restrict__ rel_k) {
    int i = blockIdx.x * 256 + threadIdx.x;   // 0..3071
    int r = i >> 6;
    float x = (r < NREL) ? rel_k[i] : 0.f;
    g_RKh[i] = __float2half_rn(x);
}

__global__ void bias_concat(const float* __restrict__ b0, const float* __restrict__ b1,
                            const float* __restrict__ b2) {
    int i = blockIdx.x * 256 + threadIdx.x;   // 0..3071
    g_bqkv[i] = (i < DM) ? b0[i] : ((i < 2 * DM) ? b1[i - DM] : b2[i - 2 * DM]);
}

#define SPAD 40
#define GSTAGE_S 20480          // 2 arrays x 10240
#define GEMM_S_SMEM (2 * GSTAGE_S)

// ---------------- fp16 single-pass QKV GEMM (stacked segments) ----------------
// Epilogue: seg0->g_Qh fp16, seg1->g_Kh fp16, seg2->fp32 g_V.
__global__ __launch_bounds__(256, 2) void gemm_qkv_h(
    const __half* __restrict__ Ah, const __half* __restrict__ Bh,
    const float* __restrict__ bias)
{
    extern __shared__ char gsm[];
    const uint32_t base = smem_u32(gsm);

    const int tid = threadIdx.x;
    const int wid = tid >> 5, lane = tid & 31;
    const int wm = wid >> 2, wn = wid & 3;
    const int bm = blockIdx.y * 128, bn = blockIdx.x * 128;

    const int seg = bn >> 10;
    const int bnl = bn & (DM - 1);
    Ah += (size_t)seg * ROWS * DM;
    Bh += (size_t)seg * DM * DM;

    float c[4][4][4];
#pragma unroll
    for (int mt = 0; mt < 4; mt++)
#pragma unroll
        for (int nt = 0; nt < 4; nt++)
#pragma unroll
            for (int r = 0; r < 4; r++) c[mt][nt][r] = 0.f;

    const int a_m_base = wm * 64 + (lane & 7) + 8 * ((lane >> 3) & 1);
    const int a_kk = 8 * (lane >> 4);
    const int b_n_base = wn * 32 + (lane & 7) + 8 * (lane >> 4);
    const int b_kk = 8 * ((lane >> 3) & 1);

    const int ktiles = DM >> 5;

    auto load_tile = [&](int t, int s) {
        const int kbase = t * 32;
        const uint32_t sb = base + s * GSTAGE_S;
#pragma unroll
        for (int i = 0; i < 2; i++) {
            int f = tid + i * 256;
            int row = f >> 2, seg2 = f & 3;
            uint32_t so = (uint32_t)(row * SPAD + seg2 * 8) * 2;
            cp_async16(sb + so, Ah + (size_t)(bm + row) * DM + kbase + seg2 * 8);
            cp_async16(sb + 10240 + so, Bh + (size_t)(bnl + row) * DM + kbase + seg2 * 8);
        }
        cp_commit();
    };

    load_tile(0, 0);
    for (int t = 0; t < ktiles; t++) {
        if (t + 1 < ktiles) {
            load_tile(t + 1, (t + 1) & 1);
            cp_wait1();
        } else {
            cp_wait0();
        }
        __syncthreads();

        const uint32_t sb = base + (t & 1) * GSTAGE_S;
        const uint32_t aA = sb, aB = sb + 10240;
#pragma unroll
        for (int kh = 0; kh < 2; kh++) {
            const int k0 = kh * 16;
            uint32_t bh[8];
#pragma unroll
            for (int p = 0; p < 2; p++) {
                uint32_t off = (uint32_t)((b_n_base + p * 16) * SPAD + k0 + b_kk) * 2;
                ldmx4(bh + p * 4, aB + off);
            }
#pragma unroll
            for (int mt = 0; mt < 4; mt++) {
                uint32_t ah[4];
                uint32_t off = (uint32_t)((a_m_base + mt * 16) * SPAD + k0 + a_kk) * 2;
                ldmx4(ah, aA + off);
#pragma unroll
                for (int nt = 0; nt < 4; nt++)
                    mma_f16(c[mt][nt], ah, bh[nt * 2], bh[nt * 2 + 1]);
            }
        }
        __syncthreads();
    }

    const int r0 = lane >> 2, c0 = (lane & 3) * 2;
#pragma unroll
    for (int mt = 0; mt < 4; mt++) {
        int row = bm + wm * 64 + mt * 16 + r0;
#pragma unroll
        for (int nt = 0; nt < 4; nt++) {
            int col = bn + wn * 32 + nt * 8 + c0;
            float b0v = bias[col], b1v = bias[col + 1];
            float v0 = c[mt][nt][0] + b0v, v1 = c[mt][nt][1] + b1v;
            float v2 = c[mt][nt][2] + b0v, v3 = c[mt][nt][3] + b1v;
            int coll = bnl + wn * 32 + nt * 8 + c0;
            if (seg == 2) {
                *(float2*)(g_V + (size_t)row * DM + coll) = make_float2(v0, v1);
                *(float2*)(g_V + (size_t)(row + 8) * DM + coll) = make_float2(v2, v3);
            } else {
                __half* dh = (seg == 0) ? g_Qh : g_Kh;
                *(uint32_t*)(dh + (size_t)row * DM + coll) =
                    pkh2(__float2half_rn(v0), __float2half_rn(v1));
                *(uint32_t*)(dh + (size_t)(row + 8) * DM + coll) =
                    pkh2(__float2half_rn(v2), __float2half_rn(v3));
            }
        }
    }
}

// ---------------- fp16 single-pass GEMM ----------------
__global__ __launch_bounds__(256, 2) void gemm_fp16(
    const __half* __restrict__ Ah, const __half* __restrict__ Bh,
    const float* __restrict__ bias, float* __restrict__ C,
    __half* __restrict__ Chi, int M, int N, int K, int relu)
{
    extern __shared__ char gsm[];
    const uint32_t base = smem_u32(gsm);

    const int tid = threadIdx.x;
    const int wid = tid >> 5, lane = tid & 31;
    const int wm = wid >> 2, wn = wid & 3;
    const int bm = blockIdx.y * 128, bn = blockIdx.x * 128;

    float c[4][4][4];
#pragma unroll
    for (int mt = 0; mt < 4; mt++)
#pragma unroll
        for (int nt = 0; nt < 4; nt++)
#pragma unroll
            for (int r = 0; r < 4; r++) c[mt][nt][r] = 0.f;

    const int a_m_base = wm * 64 + (lane & 7) + 8 * ((lane >> 3) & 1);
    const int a_kk = 8 * (lane >> 4);
    const int b_n_base = wn * 32 + (lane & 7) + 8 * (lane >> 4);
    const int b_kk = 8 * ((lane >> 3) & 1);

    const int ktiles = K >> 5;

    auto load_tile = [&](int t, int s) {
        const int kbase = t * 32;
        const uint32_t sb = base + s * GSTAGE_S;
#pragma unroll
        for (int i = 0; i < 2; i++) {
            int f = tid + i * 256;
            int row = f >> 2, seg2 = f & 3;
            uint32_t so = (uint32_t)(row * SPAD + seg2 * 8) * 2;
            cp_async16(sb + so, Ah + (size_t)(bm + row) * K + kbase + seg2 * 8);
            cp_async16(sb + 10240 + so, Bh + (size_t)(bn + row) * K + kbase + seg2 * 8);
        }
        cp_commit();
    };

    load_tile(0, 0);
    for (int t = 0; t < ktiles; t++) {
        if (t + 1 < ktiles) {
            load_tile(t + 1, (t + 1) & 1);
            cp_wait1();
        } else {
            cp_wait0();
        }
        __syncthreads();

        const uint32_t sb = base + (t & 1) * GSTAGE_S;
        const uint32_t aA = sb, aB = sb + 10240;
#pragma unroll
        for (int kh = 0; kh < 2; kh++) {
            const int k0 = kh * 16;
            uint32_t bh[8];
#pragma unroll
            for (int p = 0; p < 2; p++) {
                uint32_t off = (uint32_t)((b_n_base + p * 16) * SPAD + k0 + b_kk) * 2;
                ldmx4(bh + p * 4, aB + off);
            }
#pragma unroll
            for (int mt = 0; mt < 4; mt++) {
                uint32_t ah[4];
                uint32_t off = (uint32_t)((a_m_base + mt * 16) * SPAD + k0 + a_kk) * 2;
                ldmx4(ah, aA + off);
#pragma unroll
                for (int nt = 0; nt < 4; nt++)
                    mma_f16(c[mt][nt], ah, bh[nt * 2], bh[nt * 2 + 1]);
            }
        }
        __syncthreads();
    }

    const int r0 = lane >> 2, c0 = (lane & 3) * 2;
#pragma unroll
    for (int mt = 0; mt < 4; mt++) {
        int row = bm + wm * 64 + mt * 16 + r0;
#pragma unroll
        for (int nt = 0; nt < 4; nt++) {
            int col = bn + wn * 32 + nt * 8 + c0;
            float b0v = bias[col], b1v = bias[col + 1];
            float v0 = c[mt][nt][0] + b0v, v1 = c[mt][nt][1] + b1v;
            float v2 = c[mt][nt][2] + b0v, v3 = c[mt][nt][3] + b1v;
            if (relu) {
                v0 = fmaxf(v0, 0.f); v1 = fmaxf(v1, 0.f);
                v2 = fmaxf(v2, 0.f); v3 = fmaxf(v3, 0.f);
            }
            if (C) {
                *(float2*)(C + (size_t)row * N + col) = make_float2(v0, v1);
                *(float2*)(C + (size_t)(row + 8) * N + col) = make_float2(v2, v3);
            }
            if (Chi) {
                *(uint32_t*)(Chi + (size_t)row * N + col) =
                    pkh2(__float2half_rn(v0), __float2half_rn(v1));
                *(uint32_t*)(Chi + (size_t)(row + 8) * N + col) =
                    pkh2(__float2half_rn(v2), __float2half_rn(v3));
            }
        }
    }
}

// ---------------- fused flash attention (all fp16 single MMA) ----------------
#define QP 72
#define VP 136
#define OFF_QH 0
#define OFF_KH 18432
#define OFF_VH 36864
#define OFF_WB 54272
#define OFF_SR 71680
#define OFF_F  89088
#define OFF_RKH 89600
#define FLASH_SMEM 96512

__global__ __launch_bounds__(256, 2) void flash_attn(const float* __restrict__ rel_v) {
    extern __shared__ char fsm[];
    float* sWb = (float*)(fsm + OFF_WB);    // [128][34]
    float* sSr = (float*)(fsm + OFF_SR);    // [128][34]
    float* sF  = (float*)(fsm + OFF_F);     // [128]

    const int tid = threadIdx.x;
    const int wid = tid >> 5, lane = tid & 31;
    const int bh = blockIdx.y, b = bh >> 4, h = bh & 15;
    const int bq = blockIdx.x * 128;

    const uint32_t aQ = smem_u32(fsm + OFF_QH);
    const uint32_t aK = smem_u32(fsm + OFF_KH);
    const uint32_t aV = smem_u32(fsm + OFF_VH);
    const uint32_t aRK = smem_u32(fsm + OFF_RKH);

#pragma unroll
    for (int i = 0; i < 4; i++) {
        int f = tid + i * 256;
        int row = f >> 3, seg = f & 7;
        uint32_t so = (uint32_t)(row * QP + seg * 8) * 2;
        cp_async16(aQ + so, g_Qh + (size_t)(b * LSEQ + bq + row) * DM + h * DK + seg * 8);
    }
    for (int f = tid; f < 384; f += 256) {
        int row = f >> 3, seg = f & 7;
        uint32_t so = (uint32_t)(row * QP + seg * 8) * 2;
        cp_async16(aRK + so, g_RKh + row * DK + seg * 8);
    }
    for (int o = tid; o < 128 * 34; o += 256) sWb[o] = 0.f;
    cp_async_wait_all();
    __syncthreads();

    const int a_row = wid * 16 + (lane & 7) + 8 * ((lane >> 3) & 1);
    const int a_kk = 8 * (lane >> 4);
    const int b_row = (lane & 7) + 8 * (lane >> 4);
    const int b_kk = 8 * ((lane >> 3) & 1);
    const int r0 = lane >> 2, c0 = (lane & 3) * 2;
    const int qrow0 = wid * 16 + r0;
    const int q0 = bq + qrow0;

    // ---- sSr = Q . rel_k^T (fp16 single pass) ----
    {
        float csr[6][4];
#pragma unroll
        for (int nt = 0; nt < 6; nt++)
#pragma unroll
            for (int j = 0; j < 4; j++) csr[nt][j] = 0.f;
#pragma unroll
        for (int ks = 0; ks < 4; ks++) {
            uint32_t ah[4];
            ldmx4(ah, aQ + (uint32_t)(a_row * QP + ks * 16 + a_kk) * 2);
            uint32_t rb[12];
#pragma unroll
            for (int p = 0; p < 3; p++)
                ldmx4(rb + p * 4, aRK + (uint32_t)((b_row + p * 16) * QP + ks * 16 + b_kk) * 2);
#pragma unroll
            for (int nt = 0; nt < 6; nt++)
                mma_f16(csr[nt], ah, rb[nt * 2], rb[nt * 2 + 1]);
        }
#pragma unroll
        for (int nt = 0; nt < 6; nt++) {
#pragma unroll
            for (int j = 0; j < 4; j++) {
                int col = nt * 8 + c0 + (j & 1);
                if (col < 34) {
                    int row = (j < 2) ? qrow0 : qrow0 + 8;
                    sSr[row * 34 + col] = csr[nt][j];
                }
            }
        }
        __syncwarp();
    }

    float m0 = -1e30f, m1 = -1e30f, l0 = 0.f, l1 = 0.f;
    float O[8][4];
#pragma unroll
    for (int nt = 0; nt < 8; nt++)
#pragma unroll
        for (int j = 0; j < 4; j++) O[nt][j] = 0.f;

    for (int kt = 0; kt < 8; kt++) {
        const int k0 = kt * 128;
#pragma unroll
        for (int i = 0; i < 4; i++) {
            int f = tid + i * 256;
            int row = f >> 3, seg = f & 7;
            uint32_t so = (uint32_t)(row * QP + seg * 8) * 2;
            cp_async16(aK + so, g_Kh + (size_t)(b * LSEQ + k0 + row) * DM + h * DK + seg * 8);
        }
#pragma unroll
        for (int i = 0; i < 4; i++) {
            int f = tid + i * 256;
            int row = f >> 4, seg = f & 15;
            uint32_t so = (uint32_t)(row * VP + seg * 8) * 2;
            cp_async16(aV + so, g_Vth + ((size_t)bh * DK + row) * LSEQ + k0 + seg * 8);
        }
        cp_async_wait_all();
        __syncthreads();

        float c[16][4];
#pragma unroll
        for (int nt = 0; nt < 16; nt++)
#pragma unroll
            for (int j = 0; j < 4; j++) c[nt][j] = 0.f;

#pragma unroll
        for (int ks = 0; ks < 4; ks++) {
            uint32_t ah[4];
            ldmx4(ah, aQ + (uint32_t)(a_row * QP + ks * 16 + a_kk) * 2);
#pragma unroll
            for (int hh = 0; hh < 2; hh++) {
                uint32_t bhf[16];
#pragma unroll
                for (int p = 0; p < 4; p++)
                    ldmx4(bhf + p * 4,
                          aK + (uint32_t)((b_row + hh * 64 + p * 16) * QP + ks * 16 + b_kk) * 2);
#pragma unroll
                for (int nt = 0; nt < 8; nt++)
                    mma_f16(c[hh * 8 + nt], ah, bhf[nt * 2], bhf[nt * 2 + 1]);
            }
        }

        float tm0 = -1e30f, tm1 = -1e30f;
#pragma unroll
        for (int nt = 0; nt < 16; nt++) {
            int kA = k0 + nt * 8 + c0;
#pragma unroll
            for (int j = 0; j < 4; j++) {
                int kk = kA + (j & 1);
                bool low = (j < 2);
                int q = low ? q0 : q0 + 8;
                int lrow = low ? qrow0 : qrow0 + 8;
                int d = kk - q; d = max(-16, min(16, d));
                float s = (c[nt][j] + sSr[lrow * 34 + d + 16]) * 0.125f;
                c[nt][j] = s;
                if (low) tm0 = fmaxf(tm0, s); else tm1 = fmaxf(tm1, s);
            }
        }
        tm0 = fmaxf(tm0, __shfl_xor_sync(0xffffffffu, tm0, 1));
        tm0 = fmaxf(tm0, __shfl_xor_sync(0xffffffffu, tm0, 2));
        tm1 = fmaxf(tm1, __shfl_xor_sync(0xffffffffu, tm1, 1));
        tm1 = fmaxf(tm1, __shfl_xor_sync(0xffffffffu, tm1, 2));
        float nm0 = fmaxf(m0, tm0), nm1 = fmaxf(m1, tm1);
        float f0 = __expf(m0 - nm0), f1 = __expf(m1 - nm1);
        m0 = nm0; m1 = nm1;
        if ((lane & 3) == 0) { sF[qrow0] = f0; sF[qrow0 + 8] = f1; }
        __syncwarp();
        for (int o = lane; o < 16 * 33; o += 32) {
            int rr = o / 33, cc2 = o % 33;
            sWb[(wid * 16 + rr) * 34 + cc2] *= sF[wid * 16 + rr];
        }
        __syncwarp();

        float sum0 = 0.f, sum1 = 0.f, lo0 = 0.f, lo1 = 0.f, hi0 = 0.f, hi1 = 0.f;
#pragma unroll
        for (int nt = 0; nt < 16; nt++) {
#pragma unroll
            for (int j = 0; j < 4; j++) {
                int kk = k0 + nt * 8 + c0 + (j & 1);
                bool low = (j < 2);
                float p = __expf(c[nt][j] - (low ? nm0 : nm1));
                c[nt][j] = p;
                int q = low ? q0 : q0 + 8;
                int d = kk - q;
                if (low) sum0 += p; else sum1 += p;
                if (d <= -16) { if (low) lo0 += p; else lo1 += p; }
                else if (d >= 16) { if (low) hi0 += p; else hi1 += p; }
                else sWb[(low ? qrow0 : qrow0 + 8) * 34 + d + 16] += p;
            }
        }
        sum0 += __shfl_xor_sync(0xffffffffu, sum0, 1);
        sum0 += __shfl_xor_sync(0xffffffffu, sum0, 2);
        sum1 += __shfl_xor_sync(0xffffffffu, sum1, 1);
        sum1 += __shfl_xor_sync(0xffffffffu, sum1, 2);
        lo0 += __shfl_xor_sync(0xffffffffu, lo0, 1);
        lo0 += __shfl_xor_sync(0xffffffffu, lo0, 2);
        lo1 += __shfl_xor_sync(0xffffffffu, lo1, 1);
        lo1 += __shfl_xor_sync(0xffffffffu, lo1, 2);
        hi0 += __shfl_xor_sync(0xffffffffu, hi0, 1);
        hi0 += __shfl_xor_sync(0xffffffffu, hi0, 2);
        hi1 += __shfl_xor_sync(0xffffffffu, hi1, 1);
        hi1 += __shfl_xor_sync(0xffffffffu, hi1, 2);
        l0 = l0 * f0 + sum0;
        l1 = l1 * f1 + sum1;
        if ((lane & 3) == 0) {
            sWb[qrow0 * 34 + 0] += lo0;  sWb[qrow0 * 34 + 32] += hi0;
            sWb[(qrow0 + 8) * 34 + 0] += lo1;  sWb[(qrow0 + 8) * 34 + 32] += hi1;
        }
#pragma unroll
        for (int nt = 0; nt < 8; nt++) {
            O[nt][0] *= f0; O[nt][1] *= f0; O[nt][2] *= f1; O[nt][3] *= f1;
        }

        // ---- PV: P fp16 single x Vt fp16 single ----
#pragma unroll
        for (int j = 0; j < 8; j++) {
            uint32_t pa[4];
            pa[0] = pkh2(__float2half_rn(c[2 * j][0]), __float2half_rn(c[2 * j][1]));
            pa[1] = pkh2(__float2half_rn(c[2 * j][2]), __float2half_rn(c[2 * j][3]));
            pa[2] = pkh2(__float2half_rn(c[2 * j + 1][0]), __float2half_rn(c[2 * j + 1][1]));
            pa[3] = pkh2(__float2half_rn(c[2 * j + 1][2]), __float2half_rn(c[2 * j + 1][3]));
            uint32_t vh[16];
#pragma unroll
            for (int p = 0; p < 4; p++)
                ldmx4(vh + p * 4, aV + (uint32_t)((b_row + p * 16) * VP + j * 16 + b_kk) * 2);
#pragma unroll
            for (int nt = 0; nt < 8; nt++)
                mma_f16(O[nt], pa, vh[nt * 2], vh[nt * 2 + 1]);
        }
        __syncthreads();
    }

    // ---- epilogue: rank-33 rel_v update, normalize, store fp16 single ----
    float* rv = (float*)(fsm + OFF_KH);
    for (int o = tid; o < NREL * DK; o += 256) rv[o] = rel_v[o];
    __syncthreads();

#pragma unroll 1
    for (int r = 0; r < NREL; r++) {
        float wb0 = sWb[qrow0 * 34 + r];
        float wb1 = sWb[(qrow0 + 8) * 34 + r];
#pragma unroll
        for (int nt = 0; nt < 8; nt++) {
            int d = nt * 8 + c0;
            float rv0 = rv[r * DK + d], rv1 = rv[r * DK + d + 1];
            O[nt][0] += wb0 * rv0; O[nt][1] += wb0 * rv1;
            O[nt][2] += wb1 * rv0; O[nt][3] += wb1 * rv1;
        }
    }
    float inv0 = 1.f / l0, inv1 = 1.f / l1;
    size_t o0 = (size_t)(b * LSEQ + q0) * DM + h * DK;
    size_t o1 = (size_t)(b * LSEQ + q0 + 8) * DM + h * DK;
#pragma unroll
    for (int nt = 0; nt < 8; nt++) {
        int d = nt * 8 + c0;
        *(uint32_t*)(g_Xh + o0 + d) =
            pkh2(__float2half_rn(O[nt][0] * inv0), __float2half_rn(O[nt][1] * inv0));
        *(uint32_t*)(g_Xh + o1 + d) =
            pkh2(__float2half_rn(O[nt][2] * inv1), __float2half_rn(O[nt][3] * inv1));
    }
}

// ---------------- reductions ----------------
__device__ __forceinline__ float block_sum(float v, float* red) {
    int lane = threadIdx.x & 31, w = threadIdx.x >> 5;
#pragma unroll
    for (int o = 16; o; o >>= 1) v += __shfl_xor_sync(0xffffffffu, v, o);
    if (lane == 0) red[w] = v;
    __syncthreads();
    if (w == 0) {
        float t = (lane < 8) ? red[lane] : 0.f;
#pragma unroll
        for (int o = 4; o; o >>= 1) t += __shfl_xor_sync(0xffffffffu, t, o);
        if (lane == 0) red[0] = t;
    }
    __syncthreads();
    float r = red[0];
    __syncthreads();
    return r;
}

// ---------------- layernorm (optional fp16 single output) ----------------
__global__ void layernorm_k(const float* __restrict__ X, const float* __restrict__ Res,
                            const float* __restrict__ gam, const float* __restrict__ bet,
                            float* __restrict__ O, __half* __restrict__ Oh) {
    int row = blockIdx.x, tid = threadIdx.x;
    __shared__ float red[32];
    float4 v = *(const float4*)(X + (size_t)row * DM + tid * 4);
    if (Res) {
        float4 rr = *(const float4*)(Res + (size_t)row * DM + tid * 4);
        v.x += rr.x; v.y += rr.y; v.z += rr.z; v.w += rr.w;
    }
    float s = block_sum(v.x + v.y + v.z + v.w, red);
    float s2 = block_sum(v.x * v.x + v.y * v.y + v.z * v.z + v.w * v.w, red);
    float mu = s * (1.f / DM);
    float var = s2 * (1.f / DM) - mu * mu;
    float rstd = rsqrtf(var + 1e-6f);
    float4 g4 = *(const float4*)(gam + tid * 4);
    float4 b4 = *(const float4*)(bet + tid * 4);
    float4 o;
    o.x = (v.x - mu) * rstd * g4.x + b4.x;
    o.y = (v.y - mu) * rstd * g4.y + b4.y;
    o.z = (v.z - mu) * rstd * g4.z + b4.z;
    o.w = (v.w - mu) * rstd * g4.w + b4.w;
    if (O) *(float4*)(O + (size_t)row * DM + tid * 4) = o;
    if (Oh) {
        uint2 ph = make_uint2(pkh2(__float2half_rn(o.x), __float2half_rn(o.y)),
                              pkh2(__float2half_rn(o.z), __float2half_rn(o.w)));
        *(uint2*)(Oh + (size_t)row * DM + tid * 4) = ph;
    }
}

// ---------------- launch ----------------
static void* sym_addr(const void* s) { void* p = nullptr; cudaGetSymbolAddress(&p, s); return p; }

extern "C" void kernel_launch(void* const* d_in, const int* in_sizes, int n_in,
                              void* d_out, int out_size) {
    const float* q    = (const float*)d_in[0];
    const float* k    = (const float*)d_in[1];
    const float* v    = (const float*)d_in[2];
    const float* wq   = (const float*)d_in[3];
    const float* bq   = (const float*)d_in[4];
    const float* wk   = (const float*)d_in[5];
    const float* bk   = (const float*)d_in[6];
    const float* wv   = (const float*)d_in[7];
    const float* bv   = (const float*)d_in[8];
    const float* wfc  = (const float*)d_in[9];
    const float* bfc  = (const float*)d_in[10];
    const float* w1   = (const float*)d_in[11];
    const float* b1   = (const float*)d_in[12];
    const float* w2   = (const float*)d_in[13];
    const float* b2   = (const float*)d_in[14];
    const float* ln_g = (const float*)d_in[15];
    const float* ln_b = (const float*)d_in[16];
    const float* relk = (const float*)d_in[17];
    const float* relv = (const float*)d_in[18];
    float* out = (float*)d_out;

    float* pV    = (float*)sym_addr(g_V);
    float* pTmp  = (float*)sym_addr(g_tmp);
    float* pLn1  = (float*)sym_addr(g_ln1);
    float* pT2   = (float*)sym_addr(g_t2);
    float* pBqkv = (float*)sym_addr(g_bqkv);
    __half* pAh  = (__half*)sym_addr(g_Ah);
    __half* pXh  = (__half*)sym_addr(g_Xh);
    __half* pWh  = (__half*)sym_addr(g_Wh);
    __half* pVth = (__half*)sym_addr(g_Vth);

    cudaFuncSetAttribute(gemm_qkv_h, cudaFuncAttributeMaxDynamicSharedMemorySize, GEMM_S_SMEM);
    cudaFuncSetAttribute(gemm_fp16, cudaFuncAttributeMaxDynamicSharedMemorySize, GEMM_S_SMEM);
    cudaFuncSetAttribute(flash_attn, cudaFuncAttributeMaxDynamicSharedMemorySize, FLASH_SMEM);

    const int nD4 = ROWS * DM / 4 / 256;
    dim3 tBlk(32, 8);
    dim3 tGridD(DM / 32, DM / 32);
    dim3 tGridW1(DI / 32, DM / 32);
    dim3 tGridW2(DM / 32, DI / 32);
    dim3 gD(DM / 128, ROWS / 128);
    dim3 gI(DI / 128, ROWS / 128);
    dim3 gQKV(3 * DM / 128, ROWS / 128);

    // ---- merged QKV (fp16 single-pass): stacked weights, stacked inputs ----
    bias_concat<<<12, 256>>>(bq, bk, bv);
    relk_h<<<12, 256>>>(relk);
    conv_T_h<<<tGridD, tBlk>>>(wq, pWh, DM, DM);
    conv_T_h<<<tGridD, tBlk>>>(wk, pWh + (size_t)DM * DM, DM, DM);
    conv_T_h<<<tGridD, tBlk>>>(wv, pWh + 2 * (size_t)DM * DM, DM, DM);
    conv_h<<<nD4, 256>>>(q, pAh);
    conv_h<<<nD4, 256>>>(k, pAh + (size_t)ROWS * DM);
    conv_h<<<nD4, 256>>>(v, pAh + 2 * (size_t)ROWS * DM);
    gemm_qkv_h<<<gQKV, 256, GEMM_S_SMEM>>>(pAh, pWh, pBqkv);

    // attention prep
    dim3 gvt(LSEQ / 32, DK / 32, BHN);
    vt_split_h<<<gvt, tBlk>>>(pV, pVth);

    // fused flash attention -> attn fp16 into g_Xh
    dim3 gfa(LSEQ / 128, BHN);
    flash_attn<<<gfa, 256, FLASH_SMEM>>>(relv);

    // out-proj + LN1 (emits fp16 for FFN1)
    conv_T_h<<<tGridD, tBlk>>>(wfc, pWh, DM, DM);
    gemm_fp16<<<gD, 256, GEMM_S_SMEM>>>(pXh, pWh, bfc, pTmp, nullptr, ROWS, DM, DM, 0);
    layernorm_k<<<ROWS, 256>>>(pTmp, q, ln_g, ln_b, pLn1, pXh);

    // FFN
    conv_T_h<<<tGridW1, tBlk>>>(w1, pWh, DM, DI);
    gemm_fp16<<<gI, 256, GEMM_S_SMEM>>>(pXh, pWh, b1, nullptr, pAh, ROWS, DI, DM, 1);

    conv_T_h<<<tGridW2, tBlk>>>(w2, pWh, DI, DM);
    gemm_fp16<<<gD, 256, GEMM_S_SMEM>>>(pAh, pWh, b2, pT2, nullptr, ROWS, DM, DI, 0);
    layernorm_k<<<ROWS, 256>>>(pT2, pLn1, ln_g, ln_b, out, nullptr);
}

// round 15
// speedup vs baseline: 8.1809x; 1.0273x over previous
#include <cuda_runtime.h>
#include <cuda_bf16.h>
#include <cuda_fp16.h>
#include <cstdint>

#define LSEQ 1024
#define DM   1024
#define BATCH 8
#define NH   16
#define DK   64
#define BHN  (BATCH*NH)     // 128
#define NREL 33
#define DI   4096
#define ROWS (BATCH*LSEQ)   // 8192

// ---------------- scratch (static device arrays; no allocation) ----------------
__device__ float g_tmp[ROWS*DM];
__device__ float g_ln1[ROWS*DM];
__device__ float g_t2[ROWS*DM];
__device__ float g_bqkv[3*DM];
// fp16 buffers
__device__ __half g_Ah[(size_t)ROWS*DI];         // stacked QKV inputs / h1 (fp16)
__device__ __half g_Xh[ROWS*DM];                 // current activation (fp16)
__device__ __half g_Wh[(size_t)DM*DI];           // weights (fp16, stacked for QKV)
__device__ __half g_Qh[ROWS*DM];
__device__ __half g_Kh[ROWS*DM];
__device__ __half g_Vth[(size_t)BHN*DK*LSEQ];    // [bh][d][k] fp16
__device__ __half g_RKh[48*DK];                  // rel_k fp16, padded to 48 rows

// ---------------- helpers ----------------
__device__ __forceinline__ uint32_t smem_u32(const void* p) {
    uint32_t a;
    asm("{ .reg .u64 t; cvta.to.shared.u64 t, %1; cvt.u32.u64 %0, t; }" : "=r"(a) : "l"(p));
    return a;
}
__device__ __forceinline__ void cp_async16(uint32_t saddr, const void* gaddr) {
    asm volatile("cp.async.cg.shared.global [%0], [%1], 16;" :: "r"(saddr), "l"(gaddr));
}
__device__ __forceinline__ void cp_commit() {
    asm volatile("cp.async.commit_group;" ::: "memory");
}
__device__ __forceinline__ void cp_wait1() {
    asm volatile("cp.async.wait_group 1;" ::: "memory");
}
__device__ __forceinline__ void cp_wait0() {
    asm volatile("cp.async.wait_group 0;" ::: "memory");
}
__device__ __forceinline__ void cp_async_wait_all() {
    asm volatile("cp.async.commit_group;\ncp.async.wait_group 0;" ::: "memory");
}
__device__ __forceinline__ void ldmx4(uint32_t* r, uint32_t addr) {
    asm volatile("ldmatrix.sync.aligned.m8n8.x4.shared.b16 {%0,%1,%2,%3}, [%4];"
        : "=r"(r[0]), "=r"(r[1]), "=r"(r[2]), "=r"(r[3]) : "r"(addr));
}
__device__ __forceinline__ void mma_f16(float* c, const uint32_t* a, uint32_t b0, uint32_t b1) {
    asm volatile(
        "mma.sync.aligned.m16n8k16.row.col.f32.f16.f16.f32 "
        "{%0,%1,%2,%3}, {%4,%5,%6,%7}, {%8,%9}, {%0,%1,%2,%3};"
        : "+f"(c[0]), "+f"(c[1]), "+f"(c[2]), "+f"(c[3])
        : "r"(a[0]), "r"(a[1]), "r"(a[2]), "r"(a[3]), "r"(b0), "r"(b1));
}
__device__ __forceinline__ uint32_t pkh2(__half lo, __half hi) {
    __half2 t(lo, hi);
    return *(uint32_t*)&t;
}

// ---------------- conversion kernels ----------------
// q/k/v fp32 -> stacked fp16 (one launch, grid.y = which tensor)
__global__ void conv3_h(const float* __restrict__ q, const float* __restrict__ k,
                        const float* __restrict__ v, __half* __restrict__ H) {
    int z = blockIdx.y;
    const float* X = (z == 0) ? q : ((z == 1) ? k : v);
    int i = blockIdx.x * blockDim.x + threadIdx.x;
    float4 val = ((const float4*)X)[i];
    __half h[4] = {__float2half_rn(val.x), __float2half_rn(val.y),
                   __float2half_rn(val.z), __float2half_rn(val.w)};
    *(uint2*)(H + (size_t)z * ROWS * DM + (size_t)i * 4) = *(uint2*)h;
}

// single fp32 activation -> fp16
__global__ void conv_h(const float* __restrict__ X, __half* __restrict__ H) {
    int i = blockIdx.x * blockDim.x + threadIdx.x;
    float4 v = ((const float4*)X)[i];
    __half h[4] = {__float2half_rn(v.x), __float2half_rn(v.y),
                   __float2half_rn(v.z), __float2half_rn(v.w)};
    *(uint2*)(H + (size_t)i * 4) = *(uint2*)h;
}

// W[K,N] -> fp16 single T [N,K]
__global__ void conv_T_h(const float* __restrict__ W, __half* __restrict__ hT, int K, int N) {
    __shared__ float t[32][33];
    int n0 = blockIdx.x * 32, k0 = blockIdx.y * 32;
    int tx = threadIdx.x, ty = threadIdx.y;
    for (int i = ty; i < 32; i += 8)
        t[i][tx] = W[(size_t)(k0 + i) * N + n0 + tx];
    __syncthreads();
    for (int r = ty; r < 32; r += 8)
        hT[(size_t)(n0 + r) * K + k0 + tx] = __float2half_rn(t[tx][r]);
}

// wq/wk/wv -> stacked fp16 T (one launch, grid.z selects)
__global__ void convT3_h(const float* __restrict__ wq, const float* __restrict__ wk,
                         const float* __restrict__ wv, __half* __restrict__ hT) {
    __shared__ float t[32][33];
    int z = blockIdx.z;
    const float* W = (z == 0) ? wq : ((z == 1) ? wk : wv);
    __half* dst = hT + (size_t)z * DM * DM;
    int n0 = blockIdx.x * 32, k0 = blockIdx.y * 32;
    int tx = threadIdx.x, ty = threadIdx.y;
    for (int i = ty; i < 32; i += 8)
        t[i][tx] = W[(size_t)(k0 + i) * DM + n0 + tx];
    __syncthreads();
    for (int r = ty; r < 32; r += 8)
        dst[(size_t)(n0 + r) * DM + k0 + tx] = __float2half_rn(t[tx][r]);
}

// rel_k [33,64] -> padded [48,64] fp16
__global__ void relk_h(const float* __restrict__ rel_k) {
    int i = blockIdx.x * 256 + threadIdx.x;   // 0..3071
    int r = i >> 6;
    float x = (r < NREL) ? rel_k[i] : 0.f;
    g_RKh[i] = __float2half_rn(x);
}

__global__ void bias_concat(const float* __restrict__ b0, const float* __restrict__ b1,
                            const float* __restrict__ b2) {
    int i = blockIdx.x * 256 + threadIdx.x;   // 0..3071
    g_bqkv[i] = (i < DM) ? b0[i] : ((i < 2 * DM) ? b1[i - DM] : b2[i - 2 * DM]);
}

#define SPAD 40
#define GSTAGE_S 20480          // 2 arrays x 10240
#define GEMM_S_SMEM (2 * GSTAGE_S)

// ---------------- fp16 single-pass QKV GEMM (stacked segments) ----------------
// Epilogue: seg0->g_Qh fp16, seg1->g_Kh fp16, seg2->transposed fp16 g_Vth.
__global__ __launch_bounds__(256, 2) void gemm_qkv_h(
    const __half* __restrict__ Ah, const __half* __restrict__ Bh,
    const float* __restrict__ bias)
{
    extern __shared__ char gsm[];
    const uint32_t base = smem_u32(gsm);

    const int tid = threadIdx.x;
    const int wid = tid >> 5, lane = tid & 31;
    const int wm = wid >> 2, wn = wid & 3;
    const int bm = blockIdx.y * 128, bn = blockIdx.x * 128;

    const int seg = bn >> 10;
    const int bnl = bn & (DM - 1);
    Ah += (size_t)seg * ROWS * DM;
    Bh += (size_t)seg * DM * DM;

    float c[4][4][4];
#pragma unroll
    for (int mt = 0; mt < 4; mt++)
#pragma unroll
        for (int nt = 0; nt < 4; nt++)
#pragma unroll
            for (int r = 0; r < 4; r++) c[mt][nt][r] = 0.f;

    const int a_m_base = wm * 64 + (lane & 7) + 8 * ((lane >> 3) & 1);
    const int a_kk = 8 * (lane >> 4);
    const int b_n_base = wn * 32 + (lane & 7) + 8 * (lane >> 4);
    const int b_kk = 8 * ((lane >> 3) & 1);

    const int ktiles = DM >> 5;

    auto load_tile = [&](int t, int s) {
        const int kbase = t * 32;
        const uint32_t sb = base + s * GSTAGE_S;
#pragma unroll
        for (int i = 0; i < 2; i++) {
            int f = tid + i * 256;
            int row = f >> 2, seg2 = f & 3;
            uint32_t so = (uint32_t)(row * SPAD + seg2 * 8) * 2;
            cp_async16(sb + so, Ah + (size_t)(bm + row) * DM + kbase + seg2 * 8);
            cp_async16(sb + 10240 + so, Bh + (size_t)(bnl + row) * DM + kbase + seg2 * 8);
        }
        cp_commit();
    };

    load_tile(0, 0);
    for (int t = 0; t < ktiles; t++) {
        if (t + 1 < ktiles) {
            load_tile(t + 1, (t + 1) & 1);
            cp_wait1();
        } else {
            cp_wait0();
        }
        __syncthreads();

        const uint32_t sb = base + (t & 1) * GSTAGE_S;
        const uint32_t aA = sb, aB = sb + 10240;
#pragma unroll
        for (int kh = 0; kh < 2; kh++) {
            const int k0 = kh * 16;
            uint32_t bh[8];
#pragma unroll
            for (int p = 0; p < 2; p++) {
                uint32_t off = (uint32_t)((b_n_base + p * 16) * SPAD + k0 + b_kk) * 2;
                ldmx4(bh + p * 4, aB + off);
            }
#pragma unroll
            for (int mt = 0; mt < 4; mt++) {
                uint32_t ah[4];
                uint32_t off = (uint32_t)((a_m_base + mt * 16) * SPAD + k0 + a_kk) * 2;
                ldmx4(ah, aA + off);
#pragma unroll
                for (int nt = 0; nt < 4; nt++)
                    mma_f16(c[mt][nt], ah, bh[nt * 2], bh[nt * 2 + 1]);
            }
        }
        __syncthreads();
    }

    const int r0 = lane >> 2, c0 = (lane & 3) * 2;
    if (seg == 2) {
        // ---- stage transposed fp16 V tile in smem, then coalesced Vt writes ----
        __half* T = (__half*)gsm;           // [128 cols][136 rows] fp16, row stride 272B (16B-mult)
#pragma unroll
        for (int mt = 0; mt < 4; mt++) {
            int rl = wm * 64 + mt * 16 + r0;
#pragma unroll
            for (int nt = 0; nt < 4; nt++) {
                int cl = wn * 32 + nt * 8 + c0;
                int col = bnl + cl;
                float b0v = bias[bn + cl], b1v = bias[bn + cl + 1];
                (void)col;
                T[cl * 136 + rl]           = __float2half_rn(c[mt][nt][0] + b0v);
                T[(cl + 1) * 136 + rl]     = __float2half_rn(c[mt][nt][1] + b1v);
                T[cl * 136 + rl + 8]       = __float2half_rn(c[mt][nt][2] + b0v);
                T[(cl + 1) * 136 + rl + 8] = __float2half_rn(c[mt][nt][3] + b1v);
            }
        }
        __syncthreads();
        const int bb = bm >> 10;            // batch index (128 | 1024, so bm within one b)
        const int kq = bm & 1023;           // k offset within sequence
        for (int f = tid; f < 128 * 16; f += 256) {
            int cl = f >> 4, s8 = f & 15;   // col-local, 8-fp16 segment
            int gc = bnl + cl;
            int hh = gc >> 6, dd = gc & 63;
            size_t o = ((size_t)(bb * NH + hh) * DK + dd) * LSEQ + kq + s8 * 8;
            *(uint4*)(g_Vth + o) = *(const uint4*)&T[cl * 136 + s8 * 8];
        }
    } else {
        __half* dh = (seg == 0) ? g_Qh : g_Kh;
#pragma unroll
        for (int mt = 0; mt < 4; mt++) {
            int row = bm + wm * 64 + mt * 16 + r0;
#pragma unroll
            for (int nt = 0; nt < 4; nt++) {
                int col = bn + wn * 32 + nt * 8 + c0;
                float b0v = bias[col], b1v = bias[col + 1];
                int coll = bnl + wn * 32 + nt * 8 + c0;
                *(uint32_t*)(dh + (size_t)row * DM + coll) =
                    pkh2(__float2half_rn(c[mt][nt][0] + b0v), __float2half_rn(c[mt][nt][1] + b1v));
                *(uint32_t*)(dh + (size_t)(row + 8) * DM + coll) =
                    pkh2(__float2half_rn(c[mt][nt][2] + b0v), __float2half_rn(c[mt][nt][3] + b1v));
            }
        }
    }
}

// ---------------- fp16 single-pass GEMM ----------------
__global__ __launch_bounds__(256, 2) void gemm_fp16(
    const __half* __restrict__ Ah, const __half* __restrict__ Bh,
    const float* __restrict__ bias, float* __restrict__ C,
    __half* __restrict__ Chi, int M, int N, int K, int relu)
{
    extern __shared__ char gsm[];
    const uint32_t base = smem_u32(gsm);

    const int tid = threadIdx.x;
    const int wid = tid >> 5, lane = tid & 31;
    const int wm = wid >> 2, wn = wid & 3;
    const int bm = blockIdx.y * 128, bn = blockIdx.x * 128;

    float c[4][4][4];
#pragma unroll
    for (int mt = 0; mt < 4; mt++)
#pragma unroll
        for (int nt = 0; nt < 4; nt++)
#pragma unroll
            for (int r = 0; r < 4; r++) c[mt][nt][r] = 0.f;

    const int a_m_base = wm * 64 + (lane & 7) + 8 * ((lane >> 3) & 1);
    const int a_kk = 8 * (lane >> 4);
    const int b_n_base = wn * 32 + (lane & 7) + 8 * (lane >> 4);
    const int b_kk = 8 * ((lane >> 3) & 1);

    const int ktiles = K >> 5;

    auto load_tile = [&](int t, int s) {
        const int kbase = t * 32;
        const uint32_t sb = base + s * GSTAGE_S;
#pragma unroll
        for (int i = 0; i < 2; i++) {
            int f = tid + i * 256;
            int row = f >> 2, seg2 = f & 3;
            uint32_t so = (uint32_t)(row * SPAD + seg2 * 8) * 2;
            cp_async16(sb + so, Ah + (size_t)(bm + row) * K + kbase + seg2 * 8);
            cp_async16(sb + 10240 + so, Bh + (size_t)(bn + row) * K + kbase + seg2 * 8);
        }
        cp_commit();
    };

    load_tile(0, 0);
    for (int t = 0; t < ktiles; t++) {
        if (t + 1 < ktiles) {
            load_tile(t + 1, (t + 1) & 1);
            cp_wait1();
        } else {
            cp_wait0();
        }
        __syncthreads();

        const uint32_t sb = base + (t & 1) * GSTAGE_S;
        const uint32_t aA = sb, aB = sb + 10240;
#pragma unroll
        for (int kh = 0; kh < 2; kh++) {
            const int k0 = kh * 16;
            uint32_t bh[8];
#pragma unroll
            for (int p = 0; p < 2; p++) {
                uint32_t off = (uint32_t)((b_n_base + p * 16) * SPAD + k0 + b_kk) * 2;
                ldmx4(bh + p * 4, aB + off);
            }
#pragma unroll
            for (int mt = 0; mt < 4; mt++) {
                uint32_t ah[4];
                uint32_t off = (uint32_t)((a_m_base + mt * 16) * SPAD + k0 + a_kk) * 2;
                ldmx4(ah, aA + off);
#pragma unroll
                for (int nt = 0; nt < 4; nt++)
                    mma_f16(c[mt][nt], ah, bh[nt * 2], bh[nt * 2 + 1]);
            }
        }
        __syncthreads();
    }

    const int r0 = lane >> 2, c0 = (lane & 3) * 2;
#pragma unroll
    for (int mt = 0; mt < 4; mt++) {
        int row = bm + wm * 64 + mt * 16 + r0;
#pragma unroll
        for (int nt = 0; nt < 4; nt++) {
            int col = bn + wn * 32 + nt * 8 + c0;
            float b0v = bias[col], b1v = bias[col + 1];
            float v0 = c[mt][nt][0] + b0v, v1 = c[mt][nt][1] + b1v;
            float v2 = c[mt][nt][2] + b0v, v3 = c[mt][nt][3] + b1v;
            if (relu) {
                v0 = fmaxf(v0, 0.f); v1 = fmaxf(v1, 0.f);
                v2 = fmaxf(v2, 0.f); v3 = fmaxf(v3, 0.f);
            }
            if (C) {
                *(float2*)(C + (size_t)row * N + col) = make_float2(v0, v1);
                *(float2*)(C + (size_t)(row + 8) * N + col) = make_float2(v2, v3);
            }
            if (Chi) {
                *(uint32_t*)(Chi + (size_t)row * N + col) =
                    pkh2(__float2half_rn(v0), __float2half_rn(v1));
                *(uint32_t*)(Chi + (size_t)(row + 8) * N + col) =
                    pkh2(__float2half_rn(v2), __float2half_rn(v3));
            }
        }
    }
}

// ---------------- fused flash attention (all fp16 single MMA) ----------------
#define QP 72
#define VP 136
#define OFF_QH 0
#define OFF_KH 18432
#define OFF_VH 36864
#define OFF_WB 54272
#define OFF_SR 71680
#define OFF_F  89088
#define OFF_RKH 89600
#define FLASH_SMEM 96512

__global__ __launch_bounds__(256, 2) void flash_attn(const float* __restrict__ rel_v) {
    extern __shared__ char fsm[];
    float* sWb = (float*)(fsm + OFF_WB);    // [128][34]
    float* sSr = (float*)(fsm + OFF_SR);    // [128][34]
    float* sF  = (float*)(fsm + OFF_F);     // [128]

    const int tid = threadIdx.x;
    const int wid = tid >> 5, lane = tid & 31;
    const int bh = blockIdx.y, b = bh >> 4, h = bh & 15;
    const int bq = blockIdx.x * 128;

    const uint32_t aQ = smem_u32(fsm + OFF_QH);
    const uint32_t aK = smem_u32(fsm + OFF_KH);
    const uint32_t aV = smem_u32(fsm + OFF_VH);
    const uint32_t aRK = smem_u32(fsm + OFF_RKH);

#pragma unroll
    for (int i = 0; i < 4; i++) {
        int f = tid + i * 256;
        int row = f >> 3, seg = f & 7;
        uint32_t so = (uint32_t)(row * QP + seg * 8) * 2;
        cp_async16(aQ + so, g_Qh + (size_t)(b * LSEQ + bq + row) * DM + h * DK + seg * 8);
    }
    for (int f = tid; f < 384; f += 256) {
        int row = f >> 3, seg = f & 7;
        uint32_t so = (uint32_t)(row * QP + seg * 8) * 2;
        cp_async16(aRK + so, g_RKh + row * DK + seg * 8);
    }
    for (int o = tid; o < 128 * 34; o += 256) sWb[o] = 0.f;
    cp_async_wait_all();
    __syncthreads();

    const int a_row = wid * 16 + (lane & 7) + 8 * ((lane >> 3) & 1);
    const int a_kk = 8 * (lane >> 4);
    const int b_row = (lane & 7) + 8 * (lane >> 4);
    const int b_kk = 8 * ((lane >> 3) & 1);
    const int r0 = lane >> 2, c0 = (lane & 3) * 2;
    const int qrow0 = wid * 16 + r0;
    const int q0 = bq + qrow0;

    // ---- sSr = Q . rel_k^T (fp16 single pass) ----
    {
        float csr[6][4];
#pragma unroll
        for (int nt = 0; nt < 6; nt++)
#pragma unroll
            for (int j = 0; j < 4; j++) csr[nt][j] = 0.f;
#pragma unroll
        for (int ks = 0; ks < 4; ks++) {
            uint32_t ah[4];
            ldmx4(ah, aQ + (uint32_t)(a_row * QP + ks * 16 + a_kk) * 2);
            uint32_t rb[12];
#pragma unroll
            for (int p = 0; p < 3; p++)
                ldmx4(rb + p * 4, aRK + (uint32_t)((b_row + p * 16) * QP + ks * 16 + b_kk) * 2);
#pragma unroll
            for (int nt = 0; nt < 6; nt++)
                mma_f16(csr[nt], ah, rb[nt * 2], rb[nt * 2 + 1]);
        }
#pragma unroll
        for (int nt = 0; nt < 6; nt++) {
#pragma unroll
            for (int j = 0; j < 4; j++) {
                int col = nt * 8 + c0 + (j & 1);
                if (col < 34) {
                    int row = (j < 2) ? qrow0 : qrow0 + 8;
                    sSr[row * 34 + col] = csr[nt][j];
                }
            }
        }
        __syncwarp();
    }

    float m0 = -1e30f, m1 = -1e30f, l0 = 0.f, l1 = 0.f;
    float O[8][4];
#pragma unroll
    for (int nt = 0; nt < 8; nt++)
#pragma unroll
        for (int j = 0; j < 4; j++) O[nt][j] = 0.f;

    for (int kt = 0; kt < 8; kt++) {
        const int k0 = kt * 128;
#pragma unroll
        for (int i = 0; i < 4; i++) {
            int f = tid + i * 256;
            int row = f >> 3, seg = f & 7;
            uint32_t so = (uint32_t)(row * QP + seg * 8) * 2;
            cp_async16(aK + so, g_Kh + (size_t)(b * LSEQ + k0 + row) * DM + h * DK + seg * 8);
        }
#pragma unroll
        for (int i = 0; i < 4; i++) {
            int f = tid + i * 256;
            int row = f >> 4, seg = f & 15;
            uint32_t so = (uint32_t)(row * VP + seg * 8) * 2;
            cp_async16(aV + so, g_Vth + ((size_t)bh * DK + row) * LSEQ + k0 + seg * 8);
        }
        cp_async_wait_all();
        __syncthreads();

        float c[16][4];
#pragma unroll
        for (int nt = 0; nt < 16; nt++)
#pragma unroll
            for (int j = 0; j < 4; j++) c[nt][j] = 0.f;

#pragma unroll
        for (int ks = 0; ks < 4; ks++) {
            uint32_t ah[4];
            ldmx4(ah, aQ + (uint32_t)(a_row * QP + ks * 16 + a_kk) * 2);
#pragma unroll
            for (int hh = 0; hh < 2; hh++) {
                uint32_t bhf[16];
#pragma unroll
                for (int p = 0; p < 4; p++)
                    ldmx4(bhf + p * 4,
                          aK + (uint32_t)((b_row + hh * 64 + p * 16) * QP + ks * 16 + b_kk) * 2);
#pragma unroll
                for (int nt = 0; nt < 8; nt++)
                    mma_f16(c[hh * 8 + nt], ah, bhf[nt * 2], bhf[nt * 2 + 1]);
            }
        }

        float tm0 = -1e30f, tm1 = -1e30f;
#pragma unroll
        for (int nt = 0; nt < 16; nt++) {
            int kA = k0 + nt * 8 + c0;
#pragma unroll
            for (int j = 0; j < 4; j++) {
                int kk = kA + (j & 1);
                bool low = (j < 2);
                int q = low ? q0 : q0 + 8;
                int lrow = low ? qrow0 : qrow0 + 8;
                int d = kk - q; d = max(-16, min(16, d));
                float s = (c[nt][j] + sSr[lrow * 34 + d + 16]) * 0.125f;
                c[nt][j] = s;
                if (low) tm0 = fmaxf(tm0, s); else tm1 = fmaxf(tm1, s);
            }
        }
        tm0 = fmaxf(tm0, __shfl_xor_sync(0xffffffffu, tm0, 1));
        tm0 = fmaxf(tm0, __shfl_xor_sync(0xffffffffu, tm0, 2));
        tm1 = fmaxf(tm1, __shfl_xor_sync(0xffffffffu, tm1, 1));
        tm1 = fmaxf(tm1, __shfl_xor_sync(0xffffffffu, tm1, 2));
        float nm0 = fmaxf(m0, tm0), nm1 = fmaxf(m1, tm1);
        float f0 = __expf(m0 - nm0), f1 = __expf(m1 - nm1);
        m0 = nm0; m1 = nm1;
        if ((lane & 3) == 0) { sF[qrow0] = f0; sF[qrow0 + 8] = f1; }
        __syncwarp();
        for (int o = lane; o < 16 * 33; o += 32) {
            int rr = o / 33, cc2 = o % 33;
            sWb[(wid * 16 + rr) * 34 + cc2] *= sF[wid * 16 + rr];
        }
        __syncwarp();

        float sum0 = 0.f, sum1 = 0.f, lo0 = 0.f, lo1 = 0.f, hi0 = 0.f, hi1 = 0.f;
#pragma unroll
        for (int nt = 0; nt < 16; nt++) {
#pragma unroll
            for (int j = 0; j < 4; j++) {
                int kk = k0 + nt * 8 + c0 + (j & 1);
                bool low = (j < 2);
                float p = __expf(c[nt][j] - (low ? nm0 : nm1));
                c[nt][j] = p;
                int q = low ? q0 : q0 + 8;
                int d = kk - q;
                if (low) sum0 += p; else sum1 += p;
                if (d <= -16) { if (low) lo0 += p; else lo1 += p; }
                else if (d >= 16) { if (low) hi0 += p; else hi1 += p; }
                else sWb[(low ? qrow0 : qrow0 + 8) * 34 + d + 16] += p;
            }
        }
        sum0 += __shfl_xor_sync(0xffffffffu, sum0, 1);
        sum0 += __shfl_xor_sync(0xffffffffu, sum0, 2);
        sum1 += __shfl_xor_sync(0xffffffffu, sum1, 1);
        sum1 += __shfl_xor_sync(0xffffffffu, sum1, 2);
        lo0 += __shfl_xor_sync(0xffffffffu, lo0, 1);
        lo0 += __shfl_xor_sync(0xffffffffu, lo0, 2);
        lo1 += __shfl_xor_sync(0xffffffffu, lo1, 1);
        lo1 += __shfl_xor_sync(0xffffffffu, lo1, 2);
        hi0 += __shfl_xor_sync(0xffffffffu, hi0, 1);
        hi0 += __shfl_xor_sync(0xffffffffu, hi0, 2);
        hi1 += __shfl_xor_sync(0xffffffffu, hi1, 1);
        hi1 += __shfl_xor_sync(0xffffffffu, hi1, 2);
        l0 = l0 * f0 + sum0;
        l1 = l1 * f1 + sum1;
        if ((lane & 3) == 0) {
            sWb[qrow0 * 34 + 0] += lo0;  sWb[qrow0 * 34 + 32] += hi0;
            sWb[(qrow0 + 8) * 34 + 0] += lo1;  sWb[(qrow0 + 8) * 34 + 32] += hi1;
        }
#pragma unroll
        for (int nt = 0; nt < 8; nt++) {
            O[nt][0] *= f0; O[nt][1] *= f0; O[nt][2] *= f1; O[nt][3] *= f1;
        }

        // ---- PV: P fp16 single x Vt fp16 single ----
#pragma unroll
        for (int j = 0; j < 8; j++) {
            uint32_t pa[4];
            pa[0] = pkh2(__float2half_rn(c[2 * j][0]), __float2half_rn(c[2 * j][1]));
            pa[1] = pkh2(__float2half_rn(c[2 * j][2]), __float2half_rn(c[2 * j][3]));
            pa[2] = pkh2(__float2half_rn(c[2 * j + 1][0]), __float2half_rn(c[2 * j + 1][1]));
            pa[3] = pkh2(__float2half_rn(c[2 * j + 1][2]), __float2half_rn(c[2 * j + 1][3]));
            uint32_t vh[16];
#pragma unroll
            for (int p = 0; p < 4; p++)
                ldmx4(vh + p * 4, aV + (uint32_t)((b_row + p * 16) * VP + j * 16 + b_kk) * 2);
#pragma unroll
            for (int nt = 0; nt < 8; nt++)
                mma_f16(O[nt], pa, vh[nt * 2], vh[nt * 2 + 1]);
        }
        __syncthreads();
    }

    // ---- epilogue: rank-33 rel_v update, normalize, store fp16 single ----
    float* rv = (float*)(fsm + OFF_KH);
    for (int o = tid; o < NREL * DK; o += 256) rv[o] = rel_v[o];
    __syncthreads();

#pragma unroll 1
    for (int r = 0; r < NREL; r++) {
        float wb0 = sWb[qrow0 * 34 + r];
        float wb1 = sWb[(qrow0 + 8) * 34 + r];
#pragma unroll
        for (int nt = 0; nt < 8; nt++) {
            int d = nt * 8 + c0;
            float rv0 = rv[r * DK + d], rv1 = rv[r * DK + d + 1];
            O[nt][0] += wb0 * rv0; O[nt][1] += wb0 * rv1;
            O[nt][2] += wb1 * rv0; O[nt][3] += wb1 * rv1;
        }
    }
    float inv0 = 1.f / l0, inv1 = 1.f / l1;
    size_t o0 = (size_t)(b * LSEQ + q0) * DM + h * DK;
    size_t o1 = (size_t)(b * LSEQ + q0 + 8) * DM + h * DK;
#pragma unroll
    for (int nt = 0; nt < 8; nt++) {
        int d = nt * 8 + c0;
        *(uint32_t*)(g_Xh + o0 + d) =
            pkh2(__float2half_rn(O[nt][0] * inv0), __float2half_rn(O[nt][1] * inv0));
        *(uint32_t*)(g_Xh + o1 + d) =
            pkh2(__float2half_rn(O[nt][2] * inv1), __float2half_rn(O[nt][3] * inv1));
    }
}

// ---------------- reductions ----------------
__device__ __forceinline__ float block_sum(float v, float* red) {
    int lane = threadIdx.x & 31, w = threadIdx.x >> 5;
#pragma unroll
    for (int o = 16; o; o >>= 1) v += __shfl_xor_sync(0xffffffffu, v, o);
    if (lane == 0) red[w] = v;
    __syncthreads();
    if (w == 0) {
        float t = (lane < 8) ? red[lane] : 0.f;
#pragma unroll
        for (int o = 4; o; o >>= 1) t += __shfl_xor_sync(0xffffffffu, t, o);
        if (lane == 0) red[0] = t;
    }
    __syncthreads();
    float r = red[0];
    __syncthreads();
    return r;
}

// ---------------- layernorm (optional fp16 single output) ----------------
__global__ void layernorm_k(const float* __restrict__ X, const float* __restrict__ Res,
                            const float* __restrict__ gam, const float* __restrict__ bet,
                            float* __restrict__ O, __half* __restrict__ Oh) {
    int row = blockIdx.x, tid = threadIdx.x;
    __shared__ float red[32];
    float4 v = *(const float4*)(X + (size_t)row * DM + tid * 4);
    if (Res) {
        float4 rr = *(const float4*)(Res + (size_t)row * DM + tid * 4);
        v.x += rr.x; v.y += rr.y; v.z += rr.z; v.w += rr.w;
    }
    float s = block_sum(v.x + v.y + v.z + v.w, red);
    float s2 = block_sum(v.x * v.x + v.y * v.y + v.z * v.z + v.w * v.w, red);
    float mu = s * (1.f / DM);
    float var = s2 * (1.f / DM) - mu * mu;
    float rstd = rsqrtf(var + 1e-6f);
    float4 g4 = *(const float4*)(gam + tid * 4);
    float4 b4 = *(const float4*)(bet + tid * 4);
    float4 o;
    o.x = (v.x - mu) * rstd * g4.x + b4.x;
    o.y = (v.y - mu) * rstd * g4.y + b4.y;
    o.z = (v.z - mu) * rstd * g4.z + b4.z;
    o.w = (v.w - mu) * rstd * g4.w + b4.w;
    if (O) *(float4*)(O + (size_t)row * DM + tid * 4) = o;
    if (Oh) {
        uint2 ph = make_uint2(pkh2(__float2half_rn(o.x), __float2half_rn(o.y)),
                              pkh2(__float2half_rn(o.z), __float2half_rn(o.w)));
        *(uint2*)(Oh + (size_t)row * DM + tid * 4) = ph;
    }
}

// ---------------- launch ----------------
static void* sym_addr(const void* s) { void* p = nullptr; cudaGetSymbolAddress(&p, s); return p; }

extern "C" void kernel_launch(void* const* d_in, const int* in_sizes, int n_in,
                              void* d_out, int out_size) {
    const float* q    = (const float*)d_in[0];
    const float* k    = (const float*)d_in[1];
    const float* v    = (const float*)d_in[2];
    const float* wq   = (const float*)d_in[3];
    const float* bq   = (const float*)d_in[4];
    const float* wk   = (const float*)d_in[5];
    const float* bk   = (const float*)d_in[6];
    const float* wv   = (const float*)d_in[7];
    const float* bv   = (const float*)d_in[8];
    const float* wfc  = (const float*)d_in[9];
    const float* bfc  = (const float*)d_in[10];
    const float* w1   = (const float*)d_in[11];
    const float* b1   = (const float*)d_in[12];
    const float* w2   = (const float*)d_in[13];
    const float* b2   = (const float*)d_in[14];
    const float* ln_g = (const float*)d_in[15];
    const float* ln_b = (const float*)d_in[16];
    const float* relk = (const float*)d_in[17];
    const float* relv = (const float*)d_in[18];
    float* out = (float*)d_out;

    float* pTmp  = (float*)sym_addr(g_tmp);
    float* pLn1  = (float*)sym_addr(g_ln1);
    float* pT2   = (float*)sym_addr(g_t2);
    float* pBqkv = (float*)sym_addr(g_bqkv);
    __half* pAh  = (__half*)sym_addr(g_Ah);
    __half* pXh  = (__half*)sym_addr(g_Xh);
    __half* pWh  = (__half*)sym_addr(g_Wh);

    cudaFuncSetAttribute(gemm_qkv_h, cudaFuncAttributeMaxDynamicSharedMemorySize, GEMM_S_SMEM);
    cudaFuncSetAttribute(gemm_fp16, cudaFuncAttributeMaxDynamicSharedMemorySize, GEMM_S_SMEM);
    cudaFuncSetAttribute(flash_attn, cudaFuncAttributeMaxDynamicSharedMemorySize, FLASH_SMEM);

    const int nD4 = ROWS * DM / 4 / 256;
    dim3 tBlk(32, 8);
    dim3 tGridQKV(DM / 32, DM / 32, 3);
    dim3 tGridD(DM / 32, DM / 32);
    dim3 tGridW1(DI / 32, DM / 32);
    dim3 tGridW2(DM / 32, DI / 32);
    dim3 gD(DM / 128, ROWS / 128);
    dim3 gI(DI / 128, ROWS / 128);
    dim3 gQKV(3 * DM / 128, ROWS / 128);
    dim3 gC3(nD4, 3);

    // ---- merged QKV (fp16 single-pass): stacked weights + inputs, fused V-transpose ----
    bias_concat<<<12, 256>>>(bq, bk, bv);
    relk_h<<<12, 256>>>(relk);
    convT3_h<<<tGridQKV, tBlk>>>(wq, wk, wv, pWh);
    conv3_h<<<gC3, 256>>>(q, k, v, pAh);
    gemm_qkv_h<<<gQKV, 256, GEMM_S_SMEM>>>(pAh, pWh, pBqkv);

    // fused flash attention -> attn fp16 into g_Xh
    dim3 gfa(LSEQ / 128, BHN);
    flash_attn<<<gfa, 256, FLASH_SMEM>>>(relv);

    // out-proj + LN1 (emits fp16 for FFN1)
    conv_T_h<<<tGridD, tBlk>>>(wfc, pWh, DM, DM);
    gemm_fp16<<<gD, 256, GEMM_S_SMEM>>>(pXh, pWh, bfc, pTmp, nullptr, ROWS, DM, DM, 0);
    layernorm_k<<<ROWS, 256>>>(pTmp, q, ln_g, ln_b, pLn1, pXh);

    // FFN
    conv_T_h<<<tGridW1, tBlk>>>(w1, pWh, DM, DI);
    gemm_fp16<<<gI, 256, GEMM_S_SMEM>>>(pXh, pWh, b1, nullptr, pAh, ROWS, DI, DM, 1);

    conv_T_h<<<tGridW2, tBlk>>>(w2, pWh, DI, DM);
    gemm_fp16<<<gD, 256, GEMM_S_SMEM>>>(pAh, pWh, b2, pT2, nullptr, ROWS, DM, DI, 0);
    layernorm_k<<<ROWS, 256>>>(pT2, pLn1, ln_g, ln_b, out, nullptr);
}